// round 5
// baseline (speedup 1.0000x reference)
#include <cuda_runtime.h>
#include <cuda_bf16.h>
#include <cstdint>
#include <cstddef>

// ---------------- problem constants ----------------
#define BATCH   4
#define SEQ     2048
#define DIM     768
#define HEADS   12
#define HEAD_D  64
#define HIDDEN  3072
#define MTOK    (BATCH * SEQ)        // 8192 tokens
#define QKV_N   (3 * DIM)            // 2304
#define SCALE_ATT 0.125f             // 64^-0.5
#define LN_EPS  1e-5f

// ---------------- scratch (alloc-free: __device__ globals) ----------------
__device__ float g_h   [(size_t)MTOK * DIM];     // LN output (reused for LN1 and LN2)
__device__ float g_qkv [(size_t)MTOK * QKV_N];   // QKV GEMM output
__device__ float g_attn[(size_t)MTOK * DIM];     // attention output [B,N,C]
__device__ float g_x1  [(size_t)MTOK * DIM];     // residual after attn branch
__device__ float g_u   [(size_t)MTOK * HIDDEN];  // FC1/poly-GELU output

// =====================================================================
// LayerNorm: one block per token row (768 elems, 256 threads x 3)
// =====================================================================
__global__ __launch_bounds__(256) void ln_kernel(
    const float* __restrict__ x, const float* __restrict__ gamma,
    const float* __restrict__ beta, float* __restrict__ out)
{
    const int row = blockIdx.x;
    const int tid = threadIdx.x;
    const float* xr = x + (size_t)row * DIM;

    float v0 = xr[tid], v1 = xr[tid + 256], v2 = xr[tid + 512];
    float s = v0 + v1 + v2;
    float q = v0 * v0 + v1 * v1 + v2 * v2;

    __shared__ float ws[8], wq[8];
    #pragma unroll
    for (int o = 16; o; o >>= 1) {
        s += __shfl_xor_sync(0xffffffffu, s, o);
        q += __shfl_xor_sync(0xffffffffu, q, o);
    }
    if ((tid & 31) == 0) { ws[tid >> 5] = s; wq[tid >> 5] = q; }
    __syncthreads();
    float ts = 0.f, tq = 0.f;
    #pragma unroll
    for (int i = 0; i < 8; i++) { ts += ws[i]; tq += wq[i]; }

    const float mean = ts * (1.0f / DIM);
    const float var  = tq * (1.0f / DIM) - mean * mean;
    const float rstd = rsqrtf(var + LN_EPS);

    float* orow = out + (size_t)row * DIM;
    orow[tid]       = (v0 - mean) * rstd * gamma[tid]       + beta[tid];
    orow[tid + 256] = (v1 - mean) * rstd * gamma[tid + 256] + beta[tid + 256];
    orow[tid + 512] = (v2 - mean) * rstd * gamma[tid + 512] + beta[tid + 512];
}

// =====================================================================
// SGEMM: C[M,N] = A[M,K] @ W[K,N] + bias (+ residual) (opt poly-GELU)
// 128x128 tile, BK=8, 256 threads, 8x8 per thread.
// M,N multiples of 128; K multiple of 8 (true for all calls here).
// =====================================================================
template<bool RES, bool GELU>
__global__ __launch_bounds__(256) void sgemm_kernel(
    const float* __restrict__ A, const float* __restrict__ W,
    const float* __restrict__ bias, const float* __restrict__ res,
    float* __restrict__ C, int M, int N, int K,
    const float* __restrict__ pga, const float* __restrict__ pgb,
    const float* __restrict__ pgc)
{
    __shared__ float As[8][132];   // [k][m], padded to dodge store conflicts
    __shared__ float Ws[8][128];   // [k][n]

    const int tid = threadIdx.x;
    const int m0 = blockIdx.y * 128, n0 = blockIdx.x * 128;

    const int aRow = tid >> 1;            // 0..127
    const int aCol = (tid & 1) * 4;       // 0 or 4
    const int wRow = tid >> 5;            // 0..7
    const int wCol = (tid & 31) * 4;      // 0..124
    const int r0 = (tid >> 4) << 3;       // thread tile row
    const int c0 = (tid & 15) << 3;       // thread tile col

    const float* Aptr = A + (size_t)(m0 + aRow) * K + aCol;
    const float* Wptr = W + (size_t)wRow * N + n0 + wCol;

    float acc[8][8] = {};

    for (int kt = 0; kt < K; kt += 8) {
        float4 av = *(const float4*)(Aptr + kt);
        float4 wv = *(const float4*)(Wptr + (size_t)kt * N);
        __syncthreads();
        As[aCol + 0][aRow] = av.x;
        As[aCol + 1][aRow] = av.y;
        As[aCol + 2][aRow] = av.z;
        As[aCol + 3][aRow] = av.w;
        *(float4*)&Ws[wRow][wCol] = wv;
        __syncthreads();

        #pragma unroll
        for (int k = 0; k < 8; k++) {
            float a[8], w[8];
            *(float4*)(a)     = *(const float4*)&As[k][r0];
            *(float4*)(a + 4) = *(const float4*)&As[k][r0 + 4];
            *(float4*)(w)     = *(const float4*)&Ws[k][c0];
            *(float4*)(w + 4) = *(const float4*)&Ws[k][c0 + 4];
            #pragma unroll
            for (int i = 0; i < 8; i++)
                #pragma unroll
                for (int j = 0; j < 8; j++)
                    acc[i][j] = fmaf(a[i], w[j], acc[i][j]);
        }
    }

    float ga = 0.f, gb = 0.f, gc = 0.f;
    if (GELU) { ga = *pga; gb = *pgb; gc = *pgc; }

    #pragma unroll
    for (int i = 0; i < 8; i++) {
        const size_t row = (size_t)(m0 + r0 + i);
        #pragma unroll
        for (int j = 0; j < 8; j += 4) {
            float4 v;
            float* vp = &v.x;
            #pragma unroll
            for (int s = 0; s < 4; s++) {
                float val = acc[i][j + s] + bias[n0 + c0 + j + s];
                if (GELU) val = fmaf(fmaf(ga, val, gb), val, gc);
                vp[s] = val;
            }
            if (RES) {
                float4 rv = *(const float4*)(res + row * N + n0 + c0 + j);
                v.x += rv.x; v.y += rv.y; v.z += rv.z; v.w += rv.w;
            }
            *(float4*)(C + row * N + n0 + c0 + j) = v;
        }
    }
}

// =====================================================================
// Fused attention: per (b,h), 64-query blocks stream 64-key/value tiles.
// p = max(a*s^2 + b*s + c, 1e-6)  [s = (q.k)*SCALE]
// O = (sum_m p_m v_m) / (sum_m p_m + 1e-8)   -- single pass, no softmax.
// Thread layout: 16x16, each thread 4x4 of S / 4x4 of O.
// smem: Qts[64][68] ([d][i]); KPs[64][68] (K^T [d][j], then P^T [m][i]);
//       Vs[64][64] ([m][d]).  Total 51200 B dynamic.
// =====================================================================
#define ATTN_SMEM_BYTES (2 * 64 * 68 * 4 + 64 * 64 * 4)

__global__ __launch_bounds__(256) void attn_kernel(
    const float* __restrict__ qkv, float* __restrict__ out,
    const float* __restrict__ pa_, const float* __restrict__ pb_,
    const float* __restrict__ pc_)
{
    extern __shared__ float sm[];
    float (*Qts)[68] = (float(*)[68])(sm);
    float (*KPs)[68] = (float(*)[68])(sm + 64 * 68);
    float (*Vs)[64]  = (float(*)[64])(sm + 2 * 64 * 68);

    const int tid = threadIdx.x;
    const int tx = tid & 15, ty = tid >> 4;
    const int bh = blockIdx.y;
    const int b = bh / HEADS, h = bh % HEADS;
    const int q0 = blockIdx.x * 64;

    const size_t tokbase = (size_t)b * SEQ;
    const float* qbase = qkv + tokbase * QKV_N + h * HEAD_D;
    const float* kbase = qbase + DIM;
    const float* vbase = qbase + 2 * DIM;

    const float pa = *pa_, pb = *pb_, pc = *pc_;

    // Load Q tile transposed: Qts[d][i]
    #pragma unroll
    for (int it = 0; it < 4; it++) {
        const int g = tid + it * 256;     // 0..1023
        const int r = g >> 4;             // 0..63
        const int d0 = (g & 15) << 2;
        float4 qv = *(const float4*)(qbase + (size_t)(q0 + r) * QKV_N + d0);
        Qts[d0 + 0][r] = qv.x; Qts[d0 + 1][r] = qv.y;
        Qts[d0 + 2][r] = qv.z; Qts[d0 + 3][r] = qv.w;
    }

    float o[4][4] = {};
    float rsum[4] = {};

    for (int kv0 = 0; kv0 < SEQ; kv0 += 64) {
        __syncthreads();   // prior PV reads of KPs/Vs complete
        #pragma unroll
        for (int it = 0; it < 4; it++) {
            const int g = tid + it * 256;
            const int r = g >> 4;
            const int d0 = (g & 15) << 2;
            const size_t trow = (size_t)(kv0 + r) * QKV_N;
            float4 kv = *(const float4*)(kbase + trow + d0);
            KPs[d0 + 0][r] = kv.x; KPs[d0 + 1][r] = kv.y;
            KPs[d0 + 2][r] = kv.z; KPs[d0 + 3][r] = kv.w;
            *(float4*)&Vs[r][d0] = *(const float4*)(vbase + trow + d0);
        }
        __syncthreads();

        // S = Q K^T (per-thread 4x4)
        float s[4][4] = {};
        #pragma unroll 8
        for (int d = 0; d < 64; d++) {
            float qa[4], ka[4];
            *(float4*)qa = *(const float4*)&Qts[d][ty << 2];
            *(float4*)ka = *(const float4*)&KPs[d][tx << 2];
            #pragma unroll
            for (int ii = 0; ii < 4; ii++)
                #pragma unroll
                for (int jj = 0; jj < 4; jj++)
                    s[ii][jj] = fmaf(qa[ii], ka[jj], s[ii][jj]);
        }

        // polynomial activation + clamp, accumulate row sums
        float p[4][4];
        #pragma unroll
        for (int ii = 0; ii < 4; ii++)
            #pragma unroll
            for (int jj = 0; jj < 4; jj++) {
                const float sv = s[ii][jj] * SCALE_ATT;
                float pv = fmaf(fmaf(pa, sv, pb), sv, pc);
                pv = fmaxf(pv, 1e-6f);
                p[ii][jj] = pv;
                rsum[ii] += pv;
            }

        __syncthreads();   // all K^T reads done before P^T overwrites KPs
        #pragma unroll
        for (int jj = 0; jj < 4; jj++) {
            float4 col = make_float4(p[0][jj], p[1][jj], p[2][jj], p[3][jj]);
            *(float4*)&KPs[(tx << 2) + jj][ty << 2] = col;   // P^T [m][i]
        }
        __syncthreads();

        // O += P V (per-thread 4x4)
        #pragma unroll 8
        for (int m = 0; m < 64; m++) {
            float pr[4], vr[4];
            *(float4*)pr = *(const float4*)&KPs[m][ty << 2];
            *(float4*)vr = *(const float4*)&Vs[m][tx << 2];
            #pragma unroll
            for (int ii = 0; ii < 4; ii++)
                #pragma unroll
                for (int jj = 0; jj < 4; jj++)
                    o[ii][jj] = fmaf(pr[ii], vr[jj], o[ii][jj]);
        }
    }

    // reduce rsum across tx (16 lanes within each warp half)
    #pragma unroll
    for (int off = 1; off < 16; off <<= 1)
        #pragma unroll
        for (int ii = 0; ii < 4; ii++)
            rsum[ii] += __shfl_xor_sync(0xffffffffu, rsum[ii], off);

    // normalize + write O into [B,N,C] (c = h*64 + d)
    #pragma unroll
    for (int ii = 0; ii < 4; ii++) {
        const int n = q0 + (ty << 2) + ii;
        const float inv = 1.0f / (rsum[ii] + 1e-8f);
        float4 ov = make_float4(o[ii][0] * inv, o[ii][1] * inv,
                                o[ii][2] * inv, o[ii][3] * inv);
        *(float4*)(out + (tokbase + n) * DIM + h * HEAD_D + (tx << 2)) = ov;
    }
}

// =====================================================================
// Launch
// =====================================================================
extern "C" void kernel_launch(void* const* d_in, const int* in_sizes, int n_in,
                              void* d_out, int out_size)
{
    const float* x      = (const float*)d_in[0];
    const float* ln1_g  = (const float*)d_in[1];
    const float* ln1_b  = (const float*)d_in[2];
    const float* ln2_g  = (const float*)d_in[3];
    const float* ln2_b  = (const float*)d_in[4];
    const float* qkv_w  = (const float*)d_in[5];
    const float* qkv_b  = (const float*)d_in[6];
    const float* proj_w = (const float*)d_in[7];
    const float* proj_b = (const float*)d_in[8];
    const float* fc1_w  = (const float*)d_in[9];
    const float* fc1_b  = (const float*)d_in[10];
    const float* fc2_w  = (const float*)d_in[11];
    const float* fc2_b  = (const float*)d_in[12];
    const float* attn_a = (const float*)d_in[13];
    const float* attn_b = (const float*)d_in[14];
    const float* attn_c = (const float*)d_in[15];
    const float* gelu_a = (const float*)d_in[16];
    const float* gelu_b = (const float*)d_in[17];
    const float* gelu_c = (const float*)d_in[18];

    float *h, *qkvbuf, *attnbuf, *x1, *u;
    cudaGetSymbolAddress((void**)&h,       g_h);
    cudaGetSymbolAddress((void**)&qkvbuf,  g_qkv);
    cudaGetSymbolAddress((void**)&attnbuf, g_attn);
    cudaGetSymbolAddress((void**)&x1,      g_x1);
    cudaGetSymbolAddress((void**)&u,       g_u);

    cudaFuncSetAttribute(attn_kernel,
                         cudaFuncAttributeMaxDynamicSharedMemorySize,
                         ATTN_SMEM_BYTES);

    // 1) LN1
    ln_kernel<<<MTOK, 256>>>(x, ln1_g, ln1_b, h);

    // 2) QKV GEMM: [8192,768] @ [768,2304]
    sgemm_kernel<false, false><<<dim3(QKV_N / 128, MTOK / 128), 256>>>(
        h, qkv_w, qkv_b, nullptr, qkvbuf, MTOK, QKV_N, DIM,
        nullptr, nullptr, nullptr);

    // 3) fused attention (poly-normed), writes [B,N,C]
    attn_kernel<<<dim3(SEQ / 64, BATCH * HEADS), 256, ATTN_SMEM_BYTES>>>(
        qkvbuf, attnbuf, attn_a, attn_b, attn_c);

    // 4) proj GEMM + residual: x1 = x + attn @ proj_w + b
    sgemm_kernel<true, false><<<dim3(DIM / 128, MTOK / 128), 256>>>(
        attnbuf, proj_w, proj_b, x, x1, MTOK, DIM, DIM,
        nullptr, nullptr, nullptr);

    // 5) LN2
    ln_kernel<<<MTOK, 256>>>(x1, ln2_g, ln2_b, h);

    // 6) FC1 + poly-GELU: [8192,768] @ [768,3072]
    sgemm_kernel<false, true><<<dim3(HIDDEN / 128, MTOK / 128), 256>>>(
        h, fc1_w, fc1_b, nullptr, u, MTOK, HIDDEN, DIM,
        gelu_a, gelu_b, gelu_c);

    // 7) FC2 + residual: out = x1 + u @ fc2_w + b
    sgemm_kernel<true, false><<<dim3(DIM / 128, MTOK / 128), 256>>>(
        u, fc2_w, fc2_b, x1, (float*)d_out, MTOK, DIM, HIDDEN,
        nullptr, nullptr, nullptr);
}

// round 7
// speedup vs baseline: 1.6586x; 1.6586x over previous
#include <cuda_runtime.h>
#include <cuda_bf16.h>
#include <cstdint>
#include <cstddef>

// ---------------- problem constants ----------------
#define BATCH   4
#define SEQ     2048
#define DIM     768
#define HEADS   12
#define HEAD_D  64
#define HIDDEN  3072
#define MTOK    (BATCH * SEQ)        // 8192 tokens
#define QKV_N   (3 * DIM)            // 2304
#define SCALE_ATT 0.125f             // 64^-0.5
#define LN_EPS  1e-5f

// ---------------- scratch (alloc-free: __device__ globals) ----------------
__device__ float g_qkv [(size_t)MTOK * QKV_N];   // QKV GEMM output (fp32)
__device__ float g_x1  [(size_t)MTOK * DIM];     // residual after attn branch

__device__ __align__(16) __nv_bfloat16 g_h_hi [(size_t)MTOK * DIM];
__device__ __align__(16) __nv_bfloat16 g_h_lo [(size_t)MTOK * DIM];
__device__ __align__(16) __nv_bfloat16 g_at_hi[(size_t)MTOK * DIM];
__device__ __align__(16) __nv_bfloat16 g_at_lo[(size_t)MTOK * DIM];
__device__ __align__(16) __nv_bfloat16 g_u_hi [(size_t)MTOK * HIDDEN];
__device__ __align__(16) __nv_bfloat16 g_u_lo [(size_t)MTOK * HIDDEN];

// transposed + hi/lo-split weights: stored [N, K] bf16
__device__ __align__(16) __nv_bfloat16 g_wqkv_h[(size_t)QKV_N * DIM];
__device__ __align__(16) __nv_bfloat16 g_wqkv_l[(size_t)QKV_N * DIM];
__device__ __align__(16) __nv_bfloat16 g_wprj_h[(size_t)DIM * DIM];
__device__ __align__(16) __nv_bfloat16 g_wprj_l[(size_t)DIM * DIM];
__device__ __align__(16) __nv_bfloat16 g_wfc1_h[(size_t)HIDDEN * DIM];
__device__ __align__(16) __nv_bfloat16 g_wfc1_l[(size_t)HIDDEN * DIM];
__device__ __align__(16) __nv_bfloat16 g_wfc2_h[(size_t)DIM * HIDDEN];
__device__ __align__(16) __nv_bfloat16 g_wfc2_l[(size_t)DIM * HIDDEN];

// =====================================================================
// PTX helpers (sm_80-class: mma.sync / ldmatrix / cp.async — OK on sm_103)
// =====================================================================
__device__ __forceinline__ uint32_t smem_u32(const void* p) {
    uint32_t a;
    asm("{ .reg .u64 t; cvta.to.shared.u64 t, %1; cvt.u32.u64 %0, t; }"
        : "=r"(a) : "l"(p));
    return a;
}

#define LDSM_X4(r, addr)                                                        \
    asm volatile("ldmatrix.sync.aligned.m8n8.x4.shared.b16 {%0,%1,%2,%3}, [%4];"\
        : "=r"((r)[0]), "=r"((r)[1]), "=r"((r)[2]), "=r"((r)[3]) : "r"(addr))

#define MMA_BF16(d, a, b0, b1)                                                  \
    asm volatile("mma.sync.aligned.m16n8k16.row.col.f32.bf16.bf16.f32 "         \
        "{%0,%1,%2,%3}, {%4,%5,%6,%7}, {%8,%9}, {%0,%1,%2,%3};"                 \
        : "+f"((d)[0]), "+f"((d)[1]), "+f"((d)[2]), "+f"((d)[3])                \
        : "r"((a)[0]), "r"((a)[1]), "r"((a)[2]), "r"((a)[3]), "r"(b0), "r"(b1))

__device__ __forceinline__ void cp16(uint32_t dst, const void* src) {
    asm volatile("cp.async.cg.shared.global [%0], [%1], 16;"
                 :: "r"(dst), "l"(src) : "memory");
}
#define CP_COMMIT() asm volatile("cp.async.commit_group;" ::: "memory")
#define CP_WAIT1()  asm volatile("cp.async.wait_group 1;" ::: "memory")

__device__ __forceinline__ void split_bf16(float v, __nv_bfloat16& hi, __nv_bfloat16& lo) {
    hi = __float2bfloat16(v);
    lo = __float2bfloat16(v - __bfloat162float(hi));
}

// =====================================================================
// Weight convert: W[K,N] fp32 -> Wt_hi/Wt_lo[N,K] bf16 (tiled transpose)
// =====================================================================
__global__ __launch_bounds__(256) void wconv_kernel(
    const float* __restrict__ W, __nv_bfloat16* __restrict__ Th,
    __nv_bfloat16* __restrict__ Tl, int K, int N)
{
    __shared__ float t[32][33];
    const int n0 = blockIdx.x * 32, k0 = blockIdx.y * 32;
    const int tx = threadIdx.x, ty = threadIdx.y;
    #pragma unroll
    for (int j = 0; j < 4; j++)
        t[ty + 8 * j][tx] = W[(size_t)(k0 + ty + 8 * j) * N + n0 + tx];
    __syncthreads();
    #pragma unroll
    for (int j = 0; j < 4; j++) {
        const float v = t[tx][ty + 8 * j];
        __nv_bfloat16 hi, lo; split_bf16(v, hi, lo);
        const size_t idx = (size_t)(n0 + ty + 8 * j) * K + k0 + tx;
        Th[idx] = hi; Tl[idx] = lo;
    }
}

// =====================================================================
// LayerNorm -> bf16 hi/lo
// =====================================================================
__global__ __launch_bounds__(256) void ln_kernel(
    const float* __restrict__ x, const float* __restrict__ gamma,
    const float* __restrict__ beta,
    __nv_bfloat16* __restrict__ ohi, __nv_bfloat16* __restrict__ olo)
{
    const int row = blockIdx.x;
    const int tid = threadIdx.x;
    const float* xr = x + (size_t)row * DIM;

    float v0 = xr[tid], v1 = xr[tid + 256], v2 = xr[tid + 512];
    float s = v0 + v1 + v2;
    float q = v0 * v0 + v1 * v1 + v2 * v2;

    __shared__ float ws[8], wq[8];
    #pragma unroll
    for (int o = 16; o; o >>= 1) {
        s += __shfl_xor_sync(0xffffffffu, s, o);
        q += __shfl_xor_sync(0xffffffffu, q, o);
    }
    if ((tid & 31) == 0) { ws[tid >> 5] = s; wq[tid >> 5] = q; }
    __syncthreads();
    float ts = 0.f, tq = 0.f;
    #pragma unroll
    for (int i = 0; i < 8; i++) { ts += ws[i]; tq += wq[i]; }

    const float mean = ts * (1.0f / DIM);
    const float var  = tq * (1.0f / DIM) - mean * mean;
    const float rstd = rsqrtf(var + LN_EPS);

    const size_t rb = (size_t)row * DIM;
    #pragma unroll
    for (int j = 0; j < 3; j++) {
        const int c = tid + j * 256;
        const float v = (j == 0 ? v0 : (j == 1 ? v1 : v2));
        const float y = (v - mean) * rstd * gamma[c] + beta[c];
        __nv_bfloat16 hi, lo; split_bf16(y, hi, lo);
        ohi[rb + c] = hi; olo[rb + c] = lo;
    }
}

// =====================================================================
// Tensor-core split-bf16 GEMM via mma.sync.m16n8k16:
//   C[M,N] = (Ah+Al)[M,K] @ (Bh+Bl)[N,K]^T
//   3 MMAs per fragment pair: Ah*Bh + Al*Bh + Ah*Bl  (error ~2^-16)
// Block 128x128x32, 8 warps (warp tile 32x64), 3-stage cp.async pipeline.
// smem per stage 32KB: A rows [128][128B] = hi(64B)|lo(64B), swizzled
//   chunk' = chunk ^ (row & 7); same for B. Total 96KB.
// MODE 0: out = D + bias (fp32)
// MODE 1: out = D + bias + res (fp32)
// MODE 2: u = D + bias; poly-GELU(u) -> bf16 hi/lo
// =====================================================================
#define STAGE_BYTES 32768
#define GEMM_SMEM_BYTES (3 * STAGE_BYTES)

template<int MODE>
__global__ __launch_bounds__(256) void tc_gemm(
    const __nv_bfloat16* __restrict__ Ah, const __nv_bfloat16* __restrict__ Al,
    const __nv_bfloat16* __restrict__ Bh, const __nv_bfloat16* __restrict__ Bl,
    const float* __restrict__ bias, const float* __restrict__ res,
    float* __restrict__ outf,
    __nv_bfloat16* __restrict__ ohi, __nv_bfloat16* __restrict__ olo,
    int N, int K,
    const float* __restrict__ pga, const float* __restrict__ pgb,
    const float* __restrict__ pgc)
{
    extern __shared__ char sm[];
    const uint32_t sbase = smem_u32(sm);
    const int tid = threadIdx.x;
    const int lane = tid & 31, wid = tid >> 5;
    const int wm = wid & 3, wn = wid >> 2;      // 4 x 2 warp grid
    const int m0 = blockIdx.y * 128, n0 = blockIdx.x * 128;
    const int nt = K >> 5;                       // K/32 stages

    // ---- global->smem chunk mapping (8 x 16B per thread per stage) ----
    const __nv_bfloat16* agsrc[4]; uint32_t asoff[4];
    const __nv_bfloat16* bgsrc[4]; uint32_t bsoff[4];
    #pragma unroll
    for (int i = 0; i < 4; i++) {
        const int id = tid + i * 256;
        const int row = id >> 3, c = id & 7;
        const int half = c >> 2, kc = c & 3;
        agsrc[i] = (half ? Al : Ah) + (size_t)(m0 + row) * K + kc * 8;
        asoff[i] = row * 128 + ((c ^ (row & 7)) << 4);
        bgsrc[i] = (half ? Bl : Bh) + (size_t)(n0 + row) * K + kc * 8;
        bsoff[i] = 16384 + row * 128 + ((c ^ (row & 7)) << 4);
    }

    #define LOAD_STAGE(kt, slot) do {                                          \
        const uint32_t sb_ = sbase + (uint32_t)(slot) * STAGE_BYTES;            \
        const size_t ko_ = (size_t)(kt) * 32;                                   \
        _Pragma("unroll")                                                       \
        for (int i_ = 0; i_ < 4; i_++) {                                        \
            cp16(sb_ + asoff[i_], agsrc[i_] + ko_);                             \
            cp16(sb_ + bsoff[i_], bgsrc[i_] + ko_);                             \
        }                                                                       \
    } while (0)

    LOAD_STAGE(0, 0); CP_COMMIT();
    LOAD_STAGE(1, 1); CP_COMMIT();

    // ---- ldmatrix smem offsets (within a stage) ----
    uint32_t a_off[2][2][2];   // [mi][ks][half]
    #pragma unroll
    for (int mi = 0; mi < 2; mi++) {
        const int row = wm * 32 + mi * 16 + (lane & 15);
        const int kbit = (lane >> 4) & 1;
        #pragma unroll
        for (int ks = 0; ks < 2; ks++) {
            const int chi = ks * 2 + kbit;
            a_off[mi][ks][0] = row * 128 + (((chi    ) ^ (row & 7)) << 4);
            a_off[mi][ks][1] = row * 128 + (((chi + 4) ^ (row & 7)) << 4);
        }
    }
    uint32_t b_off[4][2][2];   // [nj][ks][half]
    #pragma unroll
    for (int nj = 0; nj < 4; nj++) {
        const int nrow = wn * 64 + nj * 16 + (lane & 7) + ((lane >> 4) << 3);
        const int kbit = (lane >> 3) & 1;
        #pragma unroll
        for (int ks = 0; ks < 2; ks++) {
            const int chi = ks * 2 + kbit;
            b_off[nj][ks][0] = 16384 + nrow * 128 + (((chi    ) ^ (nrow & 7)) << 4);
            b_off[nj][ks][1] = 16384 + nrow * 128 + (((chi + 4) ^ (nrow & 7)) << 4);
        }
    }

    float acc[2][8][4] = {};

    for (int kt = 0; kt < nt; kt++) {
        CP_WAIT1();
        __syncthreads();
        const uint32_t sb = sbase + (uint32_t)(kt % 3) * STAGE_BYTES;

        #pragma unroll
        for (int ks = 0; ks < 2; ks++) {
            uint32_t ah[2][4], al[2][4];
            LDSM_X4(ah[0], sb + a_off[0][ks][0]);
            LDSM_X4(al[0], sb + a_off[0][ks][1]);
            LDSM_X4(ah[1], sb + a_off[1][ks][0]);
            LDSM_X4(al[1], sb + a_off[1][ks][1]);
            #pragma unroll
            for (int nj = 0; nj < 4; nj++) {
                uint32_t bh[4], bl[4];
                LDSM_X4(bh, sb + b_off[nj][ks][0]);
                LDSM_X4(bl, sb + b_off[nj][ks][1]);
                #pragma unroll
                for (int mi = 0; mi < 2; mi++) {
                    MMA_BF16(acc[mi][nj * 2    ], ah[mi], bh[0], bh[1]);
                    MMA_BF16(acc[mi][nj * 2    ], al[mi], bh[0], bh[1]);
                    MMA_BF16(acc[mi][nj * 2    ], ah[mi], bl[0], bl[1]);
                    MMA_BF16(acc[mi][nj * 2 + 1], ah[mi], bh[2], bh[3]);
                    MMA_BF16(acc[mi][nj * 2 + 1], al[mi], bh[2], bh[3]);
                    MMA_BF16(acc[mi][nj * 2 + 1], ah[mi], bl[2], bl[3]);
                }
            }
        }
        __syncthreads();
        if (kt + 2 < nt) LOAD_STAGE(kt + 2, (kt + 2) % 3);
        CP_COMMIT();
    }

    // ---------------- epilogue (register accumulators) ----------------
    float gaV = 0.f, gbV = 0.f, gcV = 0.f;
    if (MODE == 2) { gaV = *pga; gbV = *pgb; gcV = *pgc; }

    #pragma unroll
    for (int mi = 0; mi < 2; mi++) {
        const int ma = m0 + wm * 32 + mi * 16 + (lane >> 2);
        #pragma unroll
        for (int t = 0; t < 8; t++) {
            const int n = n0 + wn * 64 + t * 8 + ((lane & 3) << 1);
            const float b0 = bias[n], b1 = bias[n + 1];
            #pragma unroll
            for (int half = 0; half < 2; half++) {
                const int m = ma + half * 8;
                float v0 = acc[mi][t][half * 2]     + b0;
                float v1 = acc[mi][t][half * 2 + 1] + b1;
                const size_t idx = (size_t)m * N + n;
                if (MODE == 2) {
                    v0 = fmaf(fmaf(gaV, v0, gbV), v0, gcV);
                    v1 = fmaf(fmaf(gaV, v1, gbV), v1, gcV);
                    __nv_bfloat16 h0, l0, h1, l1;
                    split_bf16(v0, h0, l0); split_bf16(v1, h1, l1);
                    *(__nv_bfloat162*)(ohi + idx) = __nv_bfloat162(h0, h1);
                    *(__nv_bfloat162*)(olo + idx) = __nv_bfloat162(l0, l1);
                } else {
                    if (MODE == 1) {
                        const float2 rv = *(const float2*)(res + idx);
                        v0 += rv.x; v1 += rv.y;
                    }
                    *(float2*)(outf + idx) = make_float2(v0, v1);
                }
            }
        }
    }
    #undef LOAD_STAGE
}

// =====================================================================
// Fused attention (fp32 SIMT), output -> bf16 hi/lo for proj GEMM
// p = max(a*s^2+b*s+c, 1e-6); O = (sum p v) / (sum p + 1e-8)
// =====================================================================
#define ATTN_SMEM_BYTES (2 * 64 * 68 * 4 + 64 * 64 * 4)

__global__ __launch_bounds__(256) void attn_kernel(
    const float* __restrict__ qkv,
    __nv_bfloat16* __restrict__ ohi, __nv_bfloat16* __restrict__ olo,
    const float* __restrict__ pa_, const float* __restrict__ pb_,
    const float* __restrict__ pc_)
{
    extern __shared__ float smf[];
    float (*Qts)[68] = (float(*)[68])(smf);
    float (*KPs)[68] = (float(*)[68])(smf + 64 * 68);
    float (*Vs)[64]  = (float(*)[64])(smf + 2 * 64 * 68);

    const int tid = threadIdx.x;
    const int tx = tid & 15, ty = tid >> 4;
    const int bh = blockIdx.y;
    const int b = bh / HEADS, h = bh % HEADS;
    const int q0 = blockIdx.x * 64;

    const size_t tokbase = (size_t)b * SEQ;
    const float* qbase = qkv + tokbase * QKV_N + h * HEAD_D;
    const float* kbase = qbase + DIM;
    const float* vbase = qbase + 2 * DIM;

    const float pa = *pa_, pb = *pb_, pc = *pc_;

    #pragma unroll
    for (int it = 0; it < 4; it++) {
        const int g = tid + it * 256;
        const int r = g >> 4;
        const int d0 = (g & 15) << 2;
        float4 qv = *(const float4*)(qbase + (size_t)(q0 + r) * QKV_N + d0);
        Qts[d0 + 0][r] = qv.x; Qts[d0 + 1][r] = qv.y;
        Qts[d0 + 2][r] = qv.z; Qts[d0 + 3][r] = qv.w;
    }

    float o[4][4] = {};
    float rsum[4] = {};

    for (int kv0 = 0; kv0 < SEQ; kv0 += 64) {
        __syncthreads();
        #pragma unroll
        for (int it = 0; it < 4; it++) {
            const int g = tid + it * 256;
            const int r = g >> 4;
            const int d0 = (g & 15) << 2;
            const size_t trow = (size_t)(kv0 + r) * QKV_N;
            float4 kv = *(const float4*)(kbase + trow + d0);
            KPs[d0 + 0][r] = kv.x; KPs[d0 + 1][r] = kv.y;
            KPs[d0 + 2][r] = kv.z; KPs[d0 + 3][r] = kv.w;
            *(float4*)&Vs[r][d0] = *(const float4*)(vbase + trow + d0);
        }
        __syncthreads();

        float s[4][4] = {};
        #pragma unroll 8
        for (int d = 0; d < 64; d++) {
            float qa[4], ka[4];
            *(float4*)qa = *(const float4*)&Qts[d][ty << 2];
            *(float4*)ka = *(const float4*)&KPs[d][tx << 2];
            #pragma unroll
            for (int ii = 0; ii < 4; ii++)
                #pragma unroll
                for (int jj = 0; jj < 4; jj++)
                    s[ii][jj] = fmaf(qa[ii], ka[jj], s[ii][jj]);
        }

        float p[4][4];
        #pragma unroll
        for (int ii = 0; ii < 4; ii++)
            #pragma unroll
            for (int jj = 0; jj < 4; jj++) {
                const float sv = s[ii][jj] * SCALE_ATT;
                float pv = fmaf(fmaf(pa, sv, pb), sv, pc);
                pv = fmaxf(pv, 1e-6f);
                p[ii][jj] = pv;
                rsum[ii] += pv;
            }

        __syncthreads();
        #pragma unroll
        for (int jj = 0; jj < 4; jj++) {
            float4 col = make_float4(p[0][jj], p[1][jj], p[2][jj], p[3][jj]);
            *(float4*)&KPs[(tx << 2) + jj][ty << 2] = col;
        }
        __syncthreads();

        #pragma unroll 8
        for (int mm = 0; mm < 64; mm++) {
            float pr[4], vr[4];
            *(float4*)pr = *(const float4*)&KPs[mm][ty << 2];
            *(float4*)vr = *(const float4*)&Vs[mm][tx << 2];
            #pragma unroll
            for (int ii = 0; ii < 4; ii++)
                #pragma unroll
                for (int jj = 0; jj < 4; jj++)
                    o[ii][jj] = fmaf(pr[ii], vr[jj], o[ii][jj]);
        }
    }

    #pragma unroll
    for (int off = 1; off < 16; off <<= 1)
        #pragma unroll
        for (int ii = 0; ii < 4; ii++)
            rsum[ii] += __shfl_xor_sync(0xffffffffu, rsum[ii], off);

    #pragma unroll
    for (int ii = 0; ii < 4; ii++) {
        const int n = q0 + (ty << 2) + ii;
        const float inv = 1.0f / (rsum[ii] + 1e-8f);
        const size_t base = (tokbase + n) * DIM + h * HEAD_D + (tx << 2);
        #pragma unroll
        for (int jj = 0; jj < 4; jj += 2) {
            const float v0 = o[ii][jj] * inv, v1 = o[ii][jj + 1] * inv;
            __nv_bfloat16 h0, l0, h1, l1;
            split_bf16(v0, h0, l0); split_bf16(v1, h1, l1);
            *(__nv_bfloat162*)(ohi + base + jj) = __nv_bfloat162(h0, h1);
            *(__nv_bfloat162*)(olo + base + jj) = __nv_bfloat162(l0, l1);
        }
    }
}

// =====================================================================
// Launch
// =====================================================================
extern "C" void kernel_launch(void* const* d_in, const int* in_sizes, int n_in,
                              void* d_out, int out_size)
{
    const float* x      = (const float*)d_in[0];
    const float* ln1_g  = (const float*)d_in[1];
    const float* ln1_b  = (const float*)d_in[2];
    const float* ln2_g  = (const float*)d_in[3];
    const float* ln2_b  = (const float*)d_in[4];
    const float* qkv_w  = (const float*)d_in[5];
    const float* qkv_b  = (const float*)d_in[6];
    const float* proj_w = (const float*)d_in[7];
    const float* proj_b = (const float*)d_in[8];
    const float* fc1_w  = (const float*)d_in[9];
    const float* fc1_b  = (const float*)d_in[10];
    const float* fc2_w  = (const float*)d_in[11];
    const float* fc2_b  = (const float*)d_in[12];
    const float* attn_a = (const float*)d_in[13];
    const float* attn_b = (const float*)d_in[14];
    const float* attn_c = (const float*)d_in[15];
    const float* gelu_a = (const float*)d_in[16];
    const float* gelu_b = (const float*)d_in[17];
    const float* gelu_c = (const float*)d_in[18];

    float *qkvbuf, *x1;
    __nv_bfloat16 *h_hi, *h_lo, *at_hi, *at_lo, *u_hi, *u_lo;
    __nv_bfloat16 *wqh, *wql, *wph, *wpl, *w1h, *w1l, *w2h, *w2l;
    cudaGetSymbolAddress((void**)&qkvbuf, g_qkv);
    cudaGetSymbolAddress((void**)&x1,     g_x1);
    cudaGetSymbolAddress((void**)&h_hi,   g_h_hi);
    cudaGetSymbolAddress((void**)&h_lo,   g_h_lo);
    cudaGetSymbolAddress((void**)&at_hi,  g_at_hi);
    cudaGetSymbolAddress((void**)&at_lo,  g_at_lo);
    cudaGetSymbolAddress((void**)&u_hi,   g_u_hi);
    cudaGetSymbolAddress((void**)&u_lo,   g_u_lo);
    cudaGetSymbolAddress((void**)&wqh,    g_wqkv_h);
    cudaGetSymbolAddress((void**)&wql,    g_wqkv_l);
    cudaGetSymbolAddress((void**)&wph,    g_wprj_h);
    cudaGetSymbolAddress((void**)&wpl,    g_wprj_l);
    cudaGetSymbolAddress((void**)&w1h,    g_wfc1_h);
    cudaGetSymbolAddress((void**)&w1l,    g_wfc1_l);
    cudaGetSymbolAddress((void**)&w2h,    g_wfc2_h);
    cudaGetSymbolAddress((void**)&w2l,    g_wfc2_l);

    cudaFuncSetAttribute(attn_kernel, cudaFuncAttributeMaxDynamicSharedMemorySize,
                         ATTN_SMEM_BYTES);
    cudaFuncSetAttribute(tc_gemm<0>, cudaFuncAttributeMaxDynamicSharedMemorySize,
                         GEMM_SMEM_BYTES);
    cudaFuncSetAttribute(tc_gemm<1>, cudaFuncAttributeMaxDynamicSharedMemorySize,
                         GEMM_SMEM_BYTES);
    cudaFuncSetAttribute(tc_gemm<2>, cudaFuncAttributeMaxDynamicSharedMemorySize,
                         GEMM_SMEM_BYTES);

    // 0) split + transpose weights -> [N,K] bf16 hi/lo
    wconv_kernel<<<dim3(QKV_N / 32, DIM / 32),   dim3(32, 8)>>>(qkv_w,  wqh, wql, DIM, QKV_N);
    wconv_kernel<<<dim3(DIM / 32, DIM / 32),     dim3(32, 8)>>>(proj_w, wph, wpl, DIM, DIM);
    wconv_kernel<<<dim3(HIDDEN / 32, DIM / 32),  dim3(32, 8)>>>(fc1_w,  w1h, w1l, DIM, HIDDEN);
    wconv_kernel<<<dim3(DIM / 32, HIDDEN / 32),  dim3(32, 8)>>>(fc2_w,  w2h, w2l, HIDDEN, DIM);

    // 1) LN1 -> hi/lo
    ln_kernel<<<MTOK, 256>>>(x, ln1_g, ln1_b, h_hi, h_lo);

    // 2) QKV GEMM (fp32 out)
    tc_gemm<0><<<dim3(QKV_N / 128, MTOK / 128), 256, GEMM_SMEM_BYTES>>>(
        h_hi, h_lo, wqh, wql, qkv_b, nullptr, qkvbuf, nullptr, nullptr,
        QKV_N, DIM, nullptr, nullptr, nullptr);

    // 3) fused attention -> hi/lo
    attn_kernel<<<dim3(SEQ / 64, BATCH * HEADS), 256, ATTN_SMEM_BYTES>>>(
        qkvbuf, at_hi, at_lo, attn_a, attn_b, attn_c);

    // 4) proj GEMM + residual(x) -> x1 (fp32)
    tc_gemm<1><<<dim3(DIM / 128, MTOK / 128), 256, GEMM_SMEM_BYTES>>>(
        at_hi, at_lo, wph, wpl, proj_b, x, x1, nullptr, nullptr,
        DIM, DIM, nullptr, nullptr, nullptr);

    // 5) LN2 -> hi/lo
    ln_kernel<<<MTOK, 256>>>(x1, ln2_g, ln2_b, h_hi, h_lo);

    // 6) FC1 + poly-GELU -> u hi/lo
    tc_gemm<2><<<dim3(HIDDEN / 128, MTOK / 128), 256, GEMM_SMEM_BYTES>>>(
        h_hi, h_lo, w1h, w1l, fc1_b, nullptr, nullptr, u_hi, u_lo,
        HIDDEN, DIM, gelu_a, gelu_b, gelu_c);

    // 7) FC2 + residual(x1) -> out (fp32)
    tc_gemm<1><<<dim3(DIM / 128, MTOK / 128), 256, GEMM_SMEM_BYTES>>>(
        u_hi, u_lo, w2h, w2l, fc2_b, x1, (float*)d_out, nullptr, nullptr,
        DIM, HIDDEN, nullptr, nullptr, nullptr);
}

// round 8
// speedup vs baseline: 3.3430x; 2.0156x over previous
#include <cuda_runtime.h>
#include <cuda_bf16.h>
#include <cstdint>
#include <cstddef>

// ---------------- problem constants ----------------
#define BATCH   4
#define SEQ     2048
#define DIM     768
#define HEADS   12
#define HEAD_D  64
#define HIDDEN  3072
#define MTOK    (BATCH * SEQ)        // 8192 tokens
#define QKV_N   (3 * DIM)            // 2304
#define SCALE_ATT 0.125f             // 64^-0.5
#define LN_EPS  1e-5f

// ---------------- scratch (alloc-free: __device__ globals) ----------------
__device__ float g_x1  [(size_t)MTOK * DIM];     // residual after attn branch

__device__ __align__(16) __nv_bfloat16 g_qkv_bf[(size_t)MTOK * QKV_N]; // q/k/v bf16
__device__ __align__(16) __nv_bfloat16 g_h_hi [(size_t)MTOK * DIM];
__device__ __align__(16) __nv_bfloat16 g_h_lo [(size_t)MTOK * DIM];
__device__ __align__(16) __nv_bfloat16 g_at_hi[(size_t)MTOK * DIM];
__device__ __align__(16) __nv_bfloat16 g_at_lo[(size_t)MTOK * DIM];
__device__ __align__(16) __nv_bfloat16 g_u_hi [(size_t)MTOK * HIDDEN];
__device__ __align__(16) __nv_bfloat16 g_u_lo [(size_t)MTOK * HIDDEN];

// transposed + hi/lo-split weights: stored [N, K] bf16
__device__ __align__(16) __nv_bfloat16 g_wqkv_h[(size_t)QKV_N * DIM];
__device__ __align__(16) __nv_bfloat16 g_wqkv_l[(size_t)QKV_N * DIM];
__device__ __align__(16) __nv_bfloat16 g_wprj_h[(size_t)DIM * DIM];
__device__ __align__(16) __nv_bfloat16 g_wprj_l[(size_t)DIM * DIM];
__device__ __align__(16) __nv_bfloat16 g_wfc1_h[(size_t)HIDDEN * DIM];
__device__ __align__(16) __nv_bfloat16 g_wfc1_l[(size_t)HIDDEN * DIM];
__device__ __align__(16) __nv_bfloat16 g_wfc2_h[(size_t)DIM * HIDDEN];
__device__ __align__(16) __nv_bfloat16 g_wfc2_l[(size_t)DIM * HIDDEN];

// =====================================================================
// PTX helpers (sm_80-class: mma.sync / ldmatrix / cp.async — OK on sm_103)
// =====================================================================
__device__ __forceinline__ uint32_t smem_u32(const void* p) {
    uint32_t a;
    asm("{ .reg .u64 t; cvta.to.shared.u64 t, %1; cvt.u32.u64 %0, t; }"
        : "=r"(a) : "l"(p));
    return a;
}

#define LDSM_X4(r, addr)                                                        \
    asm volatile("ldmatrix.sync.aligned.m8n8.x4.shared.b16 {%0,%1,%2,%3}, [%4];"\
        : "=r"((r)[0]), "=r"((r)[1]), "=r"((r)[2]), "=r"((r)[3]) : "r"(addr))

#define LDSM_X4_T(r, addr)                                                      \
    asm volatile("ldmatrix.sync.aligned.m8n8.x4.trans.shared.b16 {%0,%1,%2,%3}, [%4];"\
        : "=r"((r)[0]), "=r"((r)[1]), "=r"((r)[2]), "=r"((r)[3]) : "r"(addr))

#define MMA_BF16(d, a, b0, b1)                                                  \
    asm volatile("mma.sync.aligned.m16n8k16.row.col.f32.bf16.bf16.f32 "         \
        "{%0,%1,%2,%3}, {%4,%5,%6,%7}, {%8,%9}, {%0,%1,%2,%3};"                 \
        : "+f"((d)[0]), "+f"((d)[1]), "+f"((d)[2]), "+f"((d)[3])                \
        : "r"((a)[0]), "r"((a)[1]), "r"((a)[2]), "r"((a)[3]), "r"(b0), "r"(b1))

__device__ __forceinline__ void cp16(uint32_t dst, const void* src) {
    asm volatile("cp.async.cg.shared.global [%0], [%1], 16;"
                 :: "r"(dst), "l"(src) : "memory");
}
#define CP_COMMIT() asm volatile("cp.async.commit_group;" ::: "memory")
#define CP_WAIT1()  asm volatile("cp.async.wait_group 1;" ::: "memory")
#define CP_WAIT0()  asm volatile("cp.async.wait_group 0;" ::: "memory")

__device__ __forceinline__ void split_bf16(float v, __nv_bfloat16& hi, __nv_bfloat16& lo) {
    hi = __float2bfloat16(v);
    lo = __float2bfloat16(v - __bfloat162float(hi));
}

__device__ __forceinline__ uint32_t pack_bf16(float x, float y) {
    __nv_bfloat162 t(__float2bfloat16(x), __float2bfloat16(y));
    return *(uint32_t*)&t;
}

// =====================================================================
// Weight convert: W[K,N] fp32 -> Wt_hi/Wt_lo[N,K] bf16 (tiled transpose)
// =====================================================================
__global__ __launch_bounds__(256) void wconv_kernel(
    const float* __restrict__ W, __nv_bfloat16* __restrict__ Th,
    __nv_bfloat16* __restrict__ Tl, int K, int N)
{
    __shared__ float t[32][33];
    const int n0 = blockIdx.x * 32, k0 = blockIdx.y * 32;
    const int tx = threadIdx.x, ty = threadIdx.y;
    #pragma unroll
    for (int j = 0; j < 4; j++)
        t[ty + 8 * j][tx] = W[(size_t)(k0 + ty + 8 * j) * N + n0 + tx];
    __syncthreads();
    #pragma unroll
    for (int j = 0; j < 4; j++) {
        const float v = t[tx][ty + 8 * j];
        __nv_bfloat16 hi, lo; split_bf16(v, hi, lo);
        const size_t idx = (size_t)(n0 + ty + 8 * j) * K + k0 + tx;
        Th[idx] = hi; Tl[idx] = lo;
    }
}

// =====================================================================
// LayerNorm -> bf16 hi/lo
// =====================================================================
__global__ __launch_bounds__(256) void ln_kernel(
    const float* __restrict__ x, const float* __restrict__ gamma,
    const float* __restrict__ beta,
    __nv_bfloat16* __restrict__ ohi, __nv_bfloat16* __restrict__ olo)
{
    const int row = blockIdx.x;
    const int tid = threadIdx.x;
    const float* xr = x + (size_t)row * DIM;

    float v0 = xr[tid], v1 = xr[tid + 256], v2 = xr[tid + 512];
    float s = v0 + v1 + v2;
    float q = v0 * v0 + v1 * v1 + v2 * v2;

    __shared__ float ws[8], wq[8];
    #pragma unroll
    for (int o = 16; o; o >>= 1) {
        s += __shfl_xor_sync(0xffffffffu, s, o);
        q += __shfl_xor_sync(0xffffffffu, q, o);
    }
    if ((tid & 31) == 0) { ws[tid >> 5] = s; wq[tid >> 5] = q; }
    __syncthreads();
    float ts = 0.f, tq = 0.f;
    #pragma unroll
    for (int i = 0; i < 8; i++) { ts += ws[i]; tq += wq[i]; }

    const float mean = ts * (1.0f / DIM);
    const float var  = tq * (1.0f / DIM) - mean * mean;
    const float rstd = rsqrtf(var + LN_EPS);

    const size_t rb = (size_t)row * DIM;
    #pragma unroll
    for (int j = 0; j < 3; j++) {
        const int c = tid + j * 256;
        const float v = (j == 0 ? v0 : (j == 1 ? v1 : v2));
        const float y = (v - mean) * rstd * gamma[c] + beta[c];
        __nv_bfloat16 hi, lo; split_bf16(y, hi, lo);
        ohi[rb + c] = hi; olo[rb + c] = lo;
    }
}

// =====================================================================
// Tensor-core split-bf16 GEMM via mma.sync.m16n8k16:
//   C[M,N] = (Ah+Al)[M,K] @ (Bh+Bl)[N,K]^T
// Block 128x128x32, 8 warps, 3-stage cp.async pipeline, 96KB smem.
// MODE 1: out = D + bias + res (fp32)
// MODE 2: u = D + bias; poly-GELU(u) -> bf16 hi/lo
// MODE 3: out = D + bias -> plain bf16 (for attention q/k/v)
// =====================================================================
#define STAGE_BYTES 32768
#define GEMM_SMEM_BYTES (3 * STAGE_BYTES)

template<int MODE>
__global__ __launch_bounds__(256) void tc_gemm(
    const __nv_bfloat16* __restrict__ Ah, const __nv_bfloat16* __restrict__ Al,
    const __nv_bfloat16* __restrict__ Bh, const __nv_bfloat16* __restrict__ Bl,
    const float* __restrict__ bias, const float* __restrict__ res,
    float* __restrict__ outf,
    __nv_bfloat16* __restrict__ ohi, __nv_bfloat16* __restrict__ olo,
    int N, int K,
    const float* __restrict__ pga, const float* __restrict__ pgb,
    const float* __restrict__ pgc)
{
    extern __shared__ char sm[];
    const uint32_t sbase = smem_u32(sm);
    const int tid = threadIdx.x;
    const int lane = tid & 31, wid = tid >> 5;
    const int wm = wid & 3, wn = wid >> 2;      // 4 x 2 warp grid
    const int m0 = blockIdx.y * 128, n0 = blockIdx.x * 128;
    const int nt = K >> 5;                       // K/32 stages

    const __nv_bfloat16* agsrc[4]; uint32_t asoff[4];
    const __nv_bfloat16* bgsrc[4]; uint32_t bsoff[4];
    #pragma unroll
    for (int i = 0; i < 4; i++) {
        const int id = tid + i * 256;
        const int row = id >> 3, c = id & 7;
        const int half = c >> 2, kc = c & 3;
        agsrc[i] = (half ? Al : Ah) + (size_t)(m0 + row) * K + kc * 8;
        asoff[i] = row * 128 + ((c ^ (row & 7)) << 4);
        bgsrc[i] = (half ? Bl : Bh) + (size_t)(n0 + row) * K + kc * 8;
        bsoff[i] = 16384 + row * 128 + ((c ^ (row & 7)) << 4);
    }

    #define LOAD_STAGE(kt, slot) do {                                          \
        const uint32_t sb_ = sbase + (uint32_t)(slot) * STAGE_BYTES;            \
        const size_t ko_ = (size_t)(kt) * 32;                                   \
        _Pragma("unroll")                                                       \
        for (int i_ = 0; i_ < 4; i_++) {                                        \
            cp16(sb_ + asoff[i_], agsrc[i_] + ko_);                             \
            cp16(sb_ + bsoff[i_], bgsrc[i_] + ko_);                             \
        }                                                                       \
    } while (0)

    LOAD_STAGE(0, 0); CP_COMMIT();
    LOAD_STAGE(1, 1); CP_COMMIT();

    uint32_t a_off[2][2][2];
    #pragma unroll
    for (int mi = 0; mi < 2; mi++) {
        const int row = wm * 32 + mi * 16 + (lane & 15);
        const int kbit = (lane >> 4) & 1;
        #pragma unroll
        for (int ks = 0; ks < 2; ks++) {
            const int chi = ks * 2 + kbit;
            a_off[mi][ks][0] = row * 128 + (((chi    ) ^ (row & 7)) << 4);
            a_off[mi][ks][1] = row * 128 + (((chi + 4) ^ (row & 7)) << 4);
        }
    }
    uint32_t b_off[4][2][2];
    #pragma unroll
    for (int nj = 0; nj < 4; nj++) {
        const int nrow = wn * 64 + nj * 16 + (lane & 7) + ((lane >> 4) << 3);
        const int kbit = (lane >> 3) & 1;
        #pragma unroll
        for (int ks = 0; ks < 2; ks++) {
            const int chi = ks * 2 + kbit;
            b_off[nj][ks][0] = 16384 + nrow * 128 + (((chi    ) ^ (nrow & 7)) << 4);
            b_off[nj][ks][1] = 16384 + nrow * 128 + (((chi + 4) ^ (nrow & 7)) << 4);
        }
    }

    float acc[2][8][4] = {};

    for (int kt = 0; kt < nt; kt++) {
        CP_WAIT1();
        __syncthreads();
        const uint32_t sb = sbase + (uint32_t)(kt % 3) * STAGE_BYTES;

        #pragma unroll
        for (int ks = 0; ks < 2; ks++) {
            uint32_t ah[2][4], al[2][4];
            LDSM_X4(ah[0], sb + a_off[0][ks][0]);
            LDSM_X4(al[0], sb + a_off[0][ks][1]);
            LDSM_X4(ah[1], sb + a_off[1][ks][0]);
            LDSM_X4(al[1], sb + a_off[1][ks][1]);
            #pragma unroll
            for (int nj = 0; nj < 4; nj++) {
                uint32_t bh[4], bl[4];
                LDSM_X4(bh, sb + b_off[nj][ks][0]);
                LDSM_X4(bl, sb + b_off[nj][ks][1]);
                #pragma unroll
                for (int mi = 0; mi < 2; mi++) {
                    MMA_BF16(acc[mi][nj * 2    ], ah[mi], bh[0], bh[1]);
                    MMA_BF16(acc[mi][nj * 2    ], al[mi], bh[0], bh[1]);
                    MMA_BF16(acc[mi][nj * 2    ], ah[mi], bl[0], bl[1]);
                    MMA_BF16(acc[mi][nj * 2 + 1], ah[mi], bh[2], bh[3]);
                    MMA_BF16(acc[mi][nj * 2 + 1], al[mi], bh[2], bh[3]);
                    MMA_BF16(acc[mi][nj * 2 + 1], ah[mi], bl[2], bl[3]);
                }
            }
        }
        __syncthreads();
        if (kt + 2 < nt) LOAD_STAGE(kt + 2, (kt + 2) % 3);
        CP_COMMIT();
    }

    float gaV = 0.f, gbV = 0.f, gcV = 0.f;
    if (MODE == 2) { gaV = *pga; gbV = *pgb; gcV = *pgc; }

    #pragma unroll
    for (int mi = 0; mi < 2; mi++) {
        const int ma = m0 + wm * 32 + mi * 16 + (lane >> 2);
        #pragma unroll
        for (int t = 0; t < 8; t++) {
            const int n = n0 + wn * 64 + t * 8 + ((lane & 3) << 1);
            const float b0 = bias[n], b1 = bias[n + 1];
            #pragma unroll
            for (int half = 0; half < 2; half++) {
                const int m = ma + half * 8;
                float v0 = acc[mi][t][half * 2]     + b0;
                float v1 = acc[mi][t][half * 2 + 1] + b1;
                const size_t idx = (size_t)m * N + n;
                if (MODE == 2) {
                    v0 = fmaf(fmaf(gaV, v0, gbV), v0, gcV);
                    v1 = fmaf(fmaf(gaV, v1, gbV), v1, gcV);
                    __nv_bfloat16 h0, l0, h1, l1;
                    split_bf16(v0, h0, l0); split_bf16(v1, h1, l1);
                    *(__nv_bfloat162*)(ohi + idx) = __nv_bfloat162(h0, h1);
                    *(__nv_bfloat162*)(olo + idx) = __nv_bfloat162(l0, l1);
                } else if (MODE == 3) {
                    *(__nv_bfloat162*)(ohi + idx) =
                        __nv_bfloat162(__float2bfloat16(v0), __float2bfloat16(v1));
                } else {
                    const float2 rv = *(const float2*)(res + idx);
                    *(float2*)(outf + idx) = make_float2(v0 + rv.x, v1 + rv.y);
                }
            }
        }
    }
    #undef LOAD_STAGE
}

// =====================================================================
// Tensor-core fused attention (flash-style, bf16 mma, fp32 accum):
//   S = QK^T*scale; P = max(a*S^2+b*S+c, 1e-6); O = (P V) / rowsum(P)
// Block: 128 threads (4 warps x 16 queries), 64-query x 64-key tiles.
// K/V tiles double-buffered via cp.async. P repacked reg->reg (C->A frag).
// =====================================================================
__global__ __launch_bounds__(128) void attn_tc_kernel(
    const __nv_bfloat16* __restrict__ qkv,
    __nv_bfloat16* __restrict__ ohi, __nv_bfloat16* __restrict__ olo,
    const float* __restrict__ pa_, const float* __restrict__ pb_,
    const float* __restrict__ pc_)
{
    __shared__ __align__(16) char smQ[8192];
    __shared__ __align__(16) char smK[2][8192];
    __shared__ __align__(16) char smV[2][8192];

    const int tid = threadIdx.x, lane = tid & 31, warp = tid >> 5;
    const int bh = blockIdx.y, b = bh / HEADS, h = bh % HEADS;
    const int q0 = blockIdx.x * 64;
    const size_t tok0 = (size_t)b * SEQ;

    const uint32_t sQ = smem_u32(smQ);
    const uint32_t sK[2] = { smem_u32(smK[0]), smem_u32(smK[1]) };
    const uint32_t sV[2] = { smem_u32(smV[0]), smem_u32(smV[1]) };

    const float pa = *pa_, pb = *pb_, pc = *pc_;

    // ---- per-thread cp.async mapping: row = tid>>1, 4 chunks of 16B ----
    const int ldrow = tid >> 1;
    const int ldc0  = (tid & 1) * 4;
    const __nv_bfloat16* qsrc = qkv + (tok0 + q0 + ldrow) * QKV_N + h * HEAD_D + ldc0 * 8;
    const __nv_bfloat16* ksrc = qkv + (tok0 + ldrow) * QKV_N + DIM + h * HEAD_D + ldc0 * 8;
    const __nv_bfloat16* vsrc = ksrc + DIM;
    uint32_t ldoff[4];
    #pragma unroll
    for (int j = 0; j < 4; j++)
        ldoff[j] = ldrow * 128 + (((ldc0 + j) ^ (ldrow & 7)) << 4);

    // Q + tile 0
    #pragma unroll
    for (int j = 0; j < 4; j++) cp16(sQ + ldoff[j], qsrc + j * 8);
    #pragma unroll
    for (int j = 0; j < 4; j++) {
        cp16(sK[0] + ldoff[j], ksrc + j * 8);
        cp16(sV[0] + ldoff[j], vsrc + j * 8);
    }
    CP_COMMIT();
    CP_WAIT0();
    __syncthreads();

    // ---- hoist Q fragments (all rows ≡ r mod 8 -> swizzle XOR r) ----
    const int g = lane >> 3, r = lane & 7;
    const int rowadd = (g & 1) * 8 + r;     // +8 for lane groups 1,3
    const int cadd = g >> 1;                // +1 chunk for groups 2,3
    uint32_t qreg[4][4];
    {
        const uint32_t qb = sQ + (warp * 16 + rowadd) * 128;
        #pragma unroll
        for (int s = 0; s < 4; s++)
            LDSM_X4(qreg[s], qb + (((2 * s + cadd) ^ r) << 4));
    }

    float acc_o[8][4] = {};
    float rsum[2] = {};
    const int NT = SEQ / 64;

    for (int t = 0; t < NT; t++) {
        if (t + 1 < NT) {
            const int nb = (t + 1) & 1;
            const size_t roff = (size_t)(t + 1) * 64 * QKV_N;
            #pragma unroll
            for (int j = 0; j < 4; j++) {
                cp16(sK[nb] + ldoff[j], ksrc + roff + j * 8);
                cp16(sV[nb] + ldoff[j], vsrc + roff + j * 8);
            }
            CP_COMMIT();
            CP_WAIT1();
        } else {
            CP_WAIT0();
        }
        __syncthreads();

        const uint32_t sk = sK[t & 1], sv = sV[t & 1];

        // ---- S = Q K^T ----
        float acc_s[8][4] = {};
        #pragma unroll
        for (int s = 0; s < 4; s++) {
            const uint32_t coff = ((2 * s + cadd) ^ r) << 4;
            #pragma unroll
            for (int p = 0; p < 4; p++) {
                uint32_t kb[4];
                LDSM_X4(kb, sk + (16 * p + rowadd) * 128 + coff);
                MMA_BF16(acc_s[2 * p    ], qreg[s], kb[0], kb[2]);
                MMA_BF16(acc_s[2 * p + 1], qreg[s], kb[1], kb[3]);
            }
        }

        // ---- poly activation + clamp + rowsum ----
        #pragma unroll
        for (int j = 0; j < 8; j++)
            #pragma unroll
            for (int e = 0; e < 4; e++) {
                const float sv_ = acc_s[j][e] * SCALE_ATT;
                float pv = fmaf(fmaf(pa, sv_, pb), sv_, pc);
                pv = fmaxf(pv, 1e-6f);
                acc_s[j][e] = pv;
                rsum[e >> 1] += pv;
            }

        // ---- O += P V (P: C-frag -> A-frag register repack) ----
        #pragma unroll
        for (int s = 0; s < 4; s++) {
            uint32_t pf[4];
            pf[0] = pack_bf16(acc_s[2 * s][0],     acc_s[2 * s][1]);
            pf[1] = pack_bf16(acc_s[2 * s][2],     acc_s[2 * s][3]);
            pf[2] = pack_bf16(acc_s[2 * s + 1][0], acc_s[2 * s + 1][1]);
            pf[3] = pack_bf16(acc_s[2 * s + 1][2], acc_s[2 * s + 1][3]);
            const uint32_t vrb = sv + (16 * s + rowadd) * 128;
            #pragma unroll
            for (int p = 0; p < 4; p++) {
                uint32_t vb[4];
                LDSM_X4_T(vb, vrb + (((2 * p + cadd) ^ r) << 4));
                MMA_BF16(acc_o[2 * p    ], pf, vb[0], vb[1]);
                MMA_BF16(acc_o[2 * p + 1], pf, vb[2], vb[3]);
            }
        }
        __syncthreads();
    }

    // ---- reduce rowsums across the quad (lanes sharing a row) ----
    #pragma unroll
    for (int off = 1; off < 4; off <<= 1) {
        rsum[0] += __shfl_xor_sync(0xffffffffu, rsum[0], off);
        rsum[1] += __shfl_xor_sync(0xffffffffu, rsum[1], off);
    }
    const float inv0 = 1.0f / (rsum[0] + 1e-8f);
    const float inv1 = 1.0f / (rsum[1] + 1e-8f);

    // ---- normalize + split-bf16 write to [B,N,C] ----
    const int row0 = q0 + warp * 16 + (lane >> 2);
    const int dcol = h * HEAD_D + 2 * (lane & 3);
    #pragma unroll
    for (int j = 0; j < 8; j++) {
        const size_t i0 = (tok0 + row0) * DIM + dcol + 8 * j;
        const size_t i1 = (tok0 + row0 + 8) * DIM + dcol + 8 * j;
        const float a0 = acc_o[j][0] * inv0, a1 = acc_o[j][1] * inv0;
        const float a2 = acc_o[j][2] * inv1, a3 = acc_o[j][3] * inv1;
        __nv_bfloat16 h0, l0, h1, l1, h2, l2, h3, l3;
        split_bf16(a0, h0, l0); split_bf16(a1, h1, l1);
        split_bf16(a2, h2, l2); split_bf16(a3, h3, l3);
        *(__nv_bfloat162*)(ohi + i0) = __nv_bfloat162(h0, h1);
        *(__nv_bfloat162*)(olo + i0) = __nv_bfloat162(l0, l1);
        *(__nv_bfloat162*)(ohi + i1) = __nv_bfloat162(h2, h3);
        *(__nv_bfloat162*)(olo + i1) = __nv_bfloat162(l2, l3);
    }
}

// =====================================================================
// Launch
// =====================================================================
extern "C" void kernel_launch(void* const* d_in, const int* in_sizes, int n_in,
                              void* d_out, int out_size)
{
    const float* x      = (const float*)d_in[0];
    const float* ln1_g  = (const float*)d_in[1];
    const float* ln1_b  = (const float*)d_in[2];
    const float* ln2_g  = (const float*)d_in[3];
    const float* ln2_b  = (const float*)d_in[4];
    const float* qkv_w  = (const float*)d_in[5];
    const float* qkv_b  = (const float*)d_in[6];
    const float* proj_w = (const float*)d_in[7];
    const float* proj_b = (const float*)d_in[8];
    const float* fc1_w  = (const float*)d_in[9];
    const float* fc1_b  = (const float*)d_in[10];
    const float* fc2_w  = (const float*)d_in[11];
    const float* fc2_b  = (const float*)d_in[12];
    const float* attn_a = (const float*)d_in[13];
    const float* attn_b = (const float*)d_in[14];
    const float* attn_c = (const float*)d_in[15];
    const float* gelu_a = (const float*)d_in[16];
    const float* gelu_b = (const float*)d_in[17];
    const float* gelu_c = (const float*)d_in[18];

    float *x1;
    __nv_bfloat16 *qkv_bf, *h_hi, *h_lo, *at_hi, *at_lo, *u_hi, *u_lo;
    __nv_bfloat16 *wqh, *wql, *wph, *wpl, *w1h, *w1l, *w2h, *w2l;
    cudaGetSymbolAddress((void**)&x1,     g_x1);
    cudaGetSymbolAddress((void**)&qkv_bf, g_qkv_bf);
    cudaGetSymbolAddress((void**)&h_hi,   g_h_hi);
    cudaGetSymbolAddress((void**)&h_lo,   g_h_lo);
    cudaGetSymbolAddress((void**)&at_hi,  g_at_hi);
    cudaGetSymbolAddress((void**)&at_lo,  g_at_lo);
    cudaGetSymbolAddress((void**)&u_hi,   g_u_hi);
    cudaGetSymbolAddress((void**)&u_lo,   g_u_lo);
    cudaGetSymbolAddress((void**)&wqh,    g_wqkv_h);
    cudaGetSymbolAddress((void**)&wql,    g_wqkv_l);
    cudaGetSymbolAddress((void**)&wph,    g_wprj_h);
    cudaGetSymbolAddress((void**)&wpl,    g_wprj_l);
    cudaGetSymbolAddress((void**)&w1h,    g_wfc1_h);
    cudaGetSymbolAddress((void**)&w1l,    g_wfc1_l);
    cudaGetSymbolAddress((void**)&w2h,    g_wfc2_h);
    cudaGetSymbolAddress((void**)&w2l,    g_wfc2_l);

    cudaFuncSetAttribute(tc_gemm<1>, cudaFuncAttributeMaxDynamicSharedMemorySize,
                         GEMM_SMEM_BYTES);
    cudaFuncSetAttribute(tc_gemm<2>, cudaFuncAttributeMaxDynamicSharedMemorySize,
                         GEMM_SMEM_BYTES);
    cudaFuncSetAttribute(tc_gemm<3>, cudaFuncAttributeMaxDynamicSharedMemorySize,
                         GEMM_SMEM_BYTES);

    // 0) split + transpose weights -> [N,K] bf16 hi/lo
    wconv_kernel<<<dim3(QKV_N / 32, DIM / 32),   dim3(32, 8)>>>(qkv_w,  wqh, wql, DIM, QKV_N);
    wconv_kernel<<<dim3(DIM / 32, DIM / 32),     dim3(32, 8)>>>(proj_w, wph, wpl, DIM, DIM);
    wconv_kernel<<<dim3(HIDDEN / 32, DIM / 32),  dim3(32, 8)>>>(fc1_w,  w1h, w1l, DIM, HIDDEN);
    wconv_kernel<<<dim3(DIM / 32, HIDDEN / 32),  dim3(32, 8)>>>(fc2_w,  w2h, w2l, HIDDEN, DIM);

    // 1) LN1 -> hi/lo
    ln_kernel<<<MTOK, 256>>>(x, ln1_g, ln1_b, h_hi, h_lo);

    // 2) QKV GEMM -> plain bf16 q/k/v
    tc_gemm<3><<<dim3(QKV_N / 128, MTOK / 128), 256, GEMM_SMEM_BYTES>>>(
        h_hi, h_lo, wqh, wql, qkv_b, nullptr, nullptr, qkv_bf, nullptr,
        QKV_N, DIM, nullptr, nullptr, nullptr);

    // 3) tensor-core fused attention -> hi/lo
    attn_tc_kernel<<<dim3(SEQ / 64, BATCH * HEADS), 128>>>(
        qkv_bf, at_hi, at_lo, attn_a, attn_b, attn_c);

    // 4) proj GEMM + residual(x) -> x1 (fp32)
    tc_gemm<1><<<dim3(DIM / 128, MTOK / 128), 256, GEMM_SMEM_BYTES>>>(
        at_hi, at_lo, wph, wpl, proj_b, x, x1, nullptr, nullptr,
        DIM, DIM, nullptr, nullptr, nullptr);

    // 5) LN2 -> hi/lo
    ln_kernel<<<MTOK, 256>>>(x1, ln2_g, ln2_b, h_hi, h_lo);

    // 6) FC1 + poly-GELU -> u hi/lo
    tc_gemm<2><<<dim3(HIDDEN / 128, MTOK / 128), 256, GEMM_SMEM_BYTES>>>(
        h_hi, h_lo, w1h, w1l, fc1_b, nullptr, nullptr, u_hi, u_lo,
        HIDDEN, DIM, gelu_a, gelu_b, gelu_c);

    // 7) FC2 + residual(x1) -> out (fp32)
    tc_gemm<1><<<dim3(DIM / 128, MTOK / 128), 256, GEMM_SMEM_BYTES>>>(
        u_hi, u_lo, w2h, w2l, fc2_b, x1, (float*)d_out, nullptr, nullptr,
        DIM, HIDDEN, nullptr, nullptr, nullptr);
}

// round 9
// speedup vs baseline: 4.2777x; 1.2796x over previous
#include <cuda_runtime.h>
#include <cuda_fp16.h>
#include <cstdint>
#include <cstddef>

// ---------------- problem constants ----------------
#define BATCH   4
#define SEQ     2048
#define DIM     768
#define HEADS   12
#define HEAD_D  64
#define HIDDEN  3072
#define MTOK    (BATCH * SEQ)        // 8192 tokens
#define QKV_N   (3 * DIM)            // 2304
#define SCALE_ATT 0.125f             // 64^-0.5
#define LN_EPS  1e-5f

// ---------------- scratch (alloc-free: __device__ globals) ----------------
__device__ float g_x1  [(size_t)MTOK * DIM];     // residual after attn branch

__device__ __align__(16) __half g_qkv  [(size_t)MTOK * QKV_N]; // q/k/v fp16
__device__ __align__(16) __half g_h_hi [(size_t)MTOK * DIM];
__device__ __align__(16) __half g_h_lo [(size_t)MTOK * DIM];
__device__ __align__(16) __half g_at_hi[(size_t)MTOK * DIM];
__device__ __align__(16) __half g_at_lo[(size_t)MTOK * DIM];
__device__ __align__(16) __half g_u_hi [(size_t)MTOK * HIDDEN];
__device__ __align__(16) __half g_u_lo [(size_t)MTOK * HIDDEN];

// transposed weights: stored [N, K] fp16 (plain)
__device__ __align__(16) __half g_wqkv[(size_t)QKV_N * DIM];
__device__ __align__(16) __half g_wprj[(size_t)DIM * DIM];
__device__ __align__(16) __half g_wfc1[(size_t)HIDDEN * DIM];
__device__ __align__(16) __half g_wfc2[(size_t)DIM * HIDDEN];

// =====================================================================
// PTX helpers (sm_80-class: mma.sync / ldmatrix / cp.async — OK on sm_103)
// =====================================================================
__device__ __forceinline__ uint32_t smem_u32(const void* p) {
    uint32_t a;
    asm("{ .reg .u64 t; cvta.to.shared.u64 t, %1; cvt.u32.u64 %0, t; }"
        : "=r"(a) : "l"(p));
    return a;
}

#define LDSM_X4(r, addr)                                                        \
    asm volatile("ldmatrix.sync.aligned.m8n8.x4.shared.b16 {%0,%1,%2,%3}, [%4];"\
        : "=r"((r)[0]), "=r"((r)[1]), "=r"((r)[2]), "=r"((r)[3]) : "r"(addr))

#define LDSM_X4_T(r, addr)                                                      \
    asm volatile("ldmatrix.sync.aligned.m8n8.x4.trans.shared.b16 {%0,%1,%2,%3}, [%4];"\
        : "=r"((r)[0]), "=r"((r)[1]), "=r"((r)[2]), "=r"((r)[3]) : "r"(addr))

#define MMA_F16(d, a, b0, b1)                                                   \
    asm volatile("mma.sync.aligned.m16n8k16.row.col.f32.f16.f16.f32 "           \
        "{%0,%1,%2,%3}, {%4,%5,%6,%7}, {%8,%9}, {%0,%1,%2,%3};"                 \
        : "+f"((d)[0]), "+f"((d)[1]), "+f"((d)[2]), "+f"((d)[3])                \
        : "r"((a)[0]), "r"((a)[1]), "r"((a)[2]), "r"((a)[3]), "r"(b0), "r"(b1))

__device__ __forceinline__ void cp16(uint32_t dst, const void* src) {
    asm volatile("cp.async.cg.shared.global [%0], [%1], 16;"
                 :: "r"(dst), "l"(src) : "memory");
}
#define CP_COMMIT() asm volatile("cp.async.commit_group;" ::: "memory")
#define CP_WAIT1()  asm volatile("cp.async.wait_group 1;" ::: "memory")
#define CP_WAIT0()  asm volatile("cp.async.wait_group 0;" ::: "memory")

__device__ __forceinline__ void split_f16(float v, __half& hi, __half& lo) {
    hi = __float2half_rn(v);
    lo = __float2half_rn(v - __half2float(hi));
}

__device__ __forceinline__ uint32_t pack_f16(float x, float y) {
    __half2 t = __halves2half2(__float2half_rn(x), __float2half_rn(y));
    return *(uint32_t*)&t;
}

__device__ __forceinline__ void store_h2(__half* p, __half a, __half b) {
    __half2 t = __halves2half2(a, b);
    *(__half2*)p = t;
}

// =====================================================================
// Weight convert: W[K,N] fp32 -> Wt[N,K] fp16 (tiled transpose)
// =====================================================================
__global__ __launch_bounds__(256) void wconv_kernel(
    const float* __restrict__ W, __half* __restrict__ T, int K, int N)
{
    __shared__ float t[32][33];
    const int n0 = blockIdx.x * 32, k0 = blockIdx.y * 32;
    const int tx = threadIdx.x, ty = threadIdx.y;
    #pragma unroll
    for (int j = 0; j < 4; j++)
        t[ty + 8 * j][tx] = W[(size_t)(k0 + ty + 8 * j) * N + n0 + tx];
    __syncthreads();
    #pragma unroll
    for (int j = 0; j < 4; j++)
        T[(size_t)(n0 + ty + 8 * j) * K + k0 + tx] = __float2half_rn(t[tx][ty + 8 * j]);
}

// =====================================================================
// LayerNorm -> fp16 hi/lo
// =====================================================================
__global__ __launch_bounds__(256) void ln_kernel(
    const float* __restrict__ x, const float* __restrict__ gamma,
    const float* __restrict__ beta,
    __half* __restrict__ ohi, __half* __restrict__ olo)
{
    const int row = blockIdx.x;
    const int tid = threadIdx.x;
    const float* xr = x + (size_t)row * DIM;

    float v0 = xr[tid], v1 = xr[tid + 256], v2 = xr[tid + 512];
    float s = v0 + v1 + v2;
    float q = v0 * v0 + v1 * v1 + v2 * v2;

    __shared__ float ws[8], wq[8];
    #pragma unroll
    for (int o = 16; o; o >>= 1) {
        s += __shfl_xor_sync(0xffffffffu, s, o);
        q += __shfl_xor_sync(0xffffffffu, q, o);
    }
    if ((tid & 31) == 0) { ws[tid >> 5] = s; wq[tid >> 5] = q; }
    __syncthreads();
    float ts = 0.f, tq = 0.f;
    #pragma unroll
    for (int i = 0; i < 8; i++) { ts += ws[i]; tq += wq[i]; }

    const float mean = ts * (1.0f / DIM);
    const float var  = tq * (1.0f / DIM) - mean * mean;
    const float rstd = rsqrtf(var + LN_EPS);

    const size_t rb = (size_t)row * DIM;
    #pragma unroll
    for (int j = 0; j < 3; j++) {
        const int c = tid + j * 256;
        const float v = (j == 0 ? v0 : (j == 1 ? v1 : v2));
        const float y = (v - mean) * rstd * gamma[c] + beta[c];
        __half hi, lo; split_f16(y, hi, lo);
        ohi[rb + c] = hi; olo[rb + c] = lo;
    }
}

// =====================================================================
// Tensor-core split-fp16 GEMM via mma.sync.m16n8k16:
//   C[M,N] = (Ah+Al)[M,K] @ B[N,K]^T   (2 MMAs: Ah*B + Al*B)
// Block 128x128x32, 8 warps, 3-stage cp.async pipeline, 96KB smem.
// MODE 1: out = D + bias + res (fp32)
// MODE 2: u = D + bias; poly-GELU(u) -> fp16 hi/lo
// MODE 3: out = D + bias -> plain fp16 (attention q/k/v)
// =====================================================================
#define STAGE_BYTES 32768
#define GEMM_SMEM_BYTES (3 * STAGE_BYTES)

template<int MODE>
__global__ __launch_bounds__(256) void tc_gemm(
    const __half* __restrict__ Ah, const __half* __restrict__ Al,
    const __half* __restrict__ B,
    const float* __restrict__ bias, const float* __restrict__ res,
    float* __restrict__ outf, __half* __restrict__ out16,
    __half* __restrict__ ohi, __half* __restrict__ olo,
    int N, int K,
    const float* __restrict__ pga, const float* __restrict__ pgb,
    const float* __restrict__ pgc)
{
    extern __shared__ char sm[];
    const uint32_t sbase = smem_u32(sm);
    const int tid = threadIdx.x;
    const int lane = tid & 31, wid = tid >> 5;
    const int wm = wid & 3, wn = wid >> 2;      // 4 x 2 warp grid
    const int m0 = blockIdx.y * 128, n0 = blockIdx.x * 128;
    const int nt = K >> 5;                       // K/32 stages

    // A: 4 chunk-slots per thread (hi chunks 0-3, lo chunks 4-7 of 128B row)
    const __nv_half* agsrc[4]; uint32_t asoff[4];
    #pragma unroll
    for (int i = 0; i < 4; i++) {
        const int id = tid + i * 256;
        const int row = id >> 3, c = id & 7;
        const int half = c >> 2, kc = c & 3;
        agsrc[i] = (const __nv_half*)((half ? Al : Ah) + (size_t)(m0 + row) * K + kc * 8);
        asoff[i] = row * 128 + ((c ^ (row & 7)) << 4);
    }
    // B: only hi chunks (c<4). c == tid&7 is fixed per thread.
    const bool bval = (tid & 7) < 4;
    const __half* bgsrc[4]; uint32_t bsoff[4];
    #pragma unroll
    for (int i = 0; i < 4; i++) {
        const int id = tid + i * 256;
        const int row = id >> 3, c = id & 7;
        bgsrc[i] = B + (size_t)(n0 + row) * K + (c & 3) * 8;
        bsoff[i] = 16384 + row * 128 + ((c ^ (row & 7)) << 4);
    }

    #define LOAD_STAGE(kt, slot) do {                                          \
        const uint32_t sb_ = sbase + (uint32_t)(slot) * STAGE_BYTES;            \
        const size_t ko_ = (size_t)(kt) * 32;                                   \
        _Pragma("unroll")                                                       \
        for (int i_ = 0; i_ < 4; i_++)                                          \
            cp16(sb_ + asoff[i_], agsrc[i_] + ko_);                             \
        if (bval) {                                                             \
            _Pragma("unroll")                                                   \
            for (int i_ = 0; i_ < 4; i_++)                                      \
                cp16(sb_ + bsoff[i_], bgsrc[i_] + ko_);                         \
        }                                                                       \
    } while (0)

    LOAD_STAGE(0, 0); CP_COMMIT();
    LOAD_STAGE(1, 1); CP_COMMIT();

    uint32_t a_off[2][2][2];   // [mi][ks][half]
    #pragma unroll
    for (int mi = 0; mi < 2; mi++) {
        const int row = wm * 32 + mi * 16 + (lane & 15);
        const int kbit = (lane >> 4) & 1;
        #pragma unroll
        for (int ks = 0; ks < 2; ks++) {
            const int chi = ks * 2 + kbit;
            a_off[mi][ks][0] = row * 128 + (((chi    ) ^ (row & 7)) << 4);
            a_off[mi][ks][1] = row * 128 + (((chi + 4) ^ (row & 7)) << 4);
        }
    }
    uint32_t b_off[4][2];      // [nj][ks] (hi only)
    #pragma unroll
    for (int nj = 0; nj < 4; nj++) {
        const int nrow = wn * 64 + nj * 16 + (lane & 7) + ((lane >> 4) << 3);
        const int kbit = (lane >> 3) & 1;
        #pragma unroll
        for (int ks = 0; ks < 2; ks++) {
            const int chi = ks * 2 + kbit;
            b_off[nj][ks] = 16384 + nrow * 128 + ((chi ^ (nrow & 7)) << 4);
        }
    }

    float acc[2][8][4] = {};

    for (int kt = 0; kt < nt; kt++) {
        CP_WAIT1();
        __syncthreads();
        const uint32_t sb = sbase + (uint32_t)(kt % 3) * STAGE_BYTES;

        #pragma unroll
        for (int ks = 0; ks < 2; ks++) {
            uint32_t ah[2][4], al[2][4];
            LDSM_X4(ah[0], sb + a_off[0][ks][0]);
            LDSM_X4(al[0], sb + a_off[0][ks][1]);
            LDSM_X4(ah[1], sb + a_off[1][ks][0]);
            LDSM_X4(al[1], sb + a_off[1][ks][1]);
            #pragma unroll
            for (int nj = 0; nj < 4; nj++) {
                uint32_t bh[4];
                LDSM_X4(bh, sb + b_off[nj][ks]);
                #pragma unroll
                for (int mi = 0; mi < 2; mi++) {
                    MMA_F16(acc[mi][nj * 2    ], ah[mi], bh[0], bh[1]);
                    MMA_F16(acc[mi][nj * 2    ], al[mi], bh[0], bh[1]);
                    MMA_F16(acc[mi][nj * 2 + 1], ah[mi], bh[2], bh[3]);
                    MMA_F16(acc[mi][nj * 2 + 1], al[mi], bh[2], bh[3]);
                }
            }
        }
        __syncthreads();
        if (kt + 2 < nt) LOAD_STAGE(kt + 2, (kt + 2) % 3);
        CP_COMMIT();
    }

    float gaV = 0.f, gbV = 0.f, gcV = 0.f;
    if (MODE == 2) { gaV = *pga; gbV = *pgb; gcV = *pgc; }

    #pragma unroll
    for (int mi = 0; mi < 2; mi++) {
        const int ma = m0 + wm * 32 + mi * 16 + (lane >> 2);
        #pragma unroll
        for (int t = 0; t < 8; t++) {
            const int n = n0 + wn * 64 + t * 8 + ((lane & 3) << 1);
            const float b0 = bias[n], b1 = bias[n + 1];
            #pragma unroll
            for (int half = 0; half < 2; half++) {
                const int m = ma + half * 8;
                float v0 = acc[mi][t][half * 2]     + b0;
                float v1 = acc[mi][t][half * 2 + 1] + b1;
                const size_t idx = (size_t)m * N + n;
                if (MODE == 2) {
                    v0 = fmaf(fmaf(gaV, v0, gbV), v0, gcV);
                    v1 = fmaf(fmaf(gaV, v1, gbV), v1, gcV);
                    __half h0, l0, h1, l1;
                    split_f16(v0, h0, l0); split_f16(v1, h1, l1);
                    store_h2(ohi + idx, h0, h1);
                    store_h2(olo + idx, l0, l1);
                } else if (MODE == 3) {
                    store_h2(out16 + idx, __float2half_rn(v0), __float2half_rn(v1));
                } else {
                    const float2 rv = *(const float2*)(res + idx);
                    *(float2*)(outf + idx) = make_float2(v0 + rv.x, v1 + rv.y);
                }
            }
        }
    }
    #undef LOAD_STAGE
}

// =====================================================================
// Tensor-core fused attention (flash-style, fp16 mma, fp32 accum):
//   S = QK^T*scale; P = max(a*S^2+b*S+c, 1e-6); O = (P V) / rowsum(P)
// Block: 128 threads (4 warps x 16 queries), 64-query x 64-key tiles.
// =====================================================================
__global__ __launch_bounds__(128) void attn_tc_kernel(
    const __half* __restrict__ qkv,
    __half* __restrict__ ohi, __half* __restrict__ olo,
    const float* __restrict__ pa_, const float* __restrict__ pb_,
    const float* __restrict__ pc_)
{
    __shared__ __align__(16) char smQ[8192];
    __shared__ __align__(16) char smK[2][8192];
    __shared__ __align__(16) char smV[2][8192];

    const int tid = threadIdx.x, lane = tid & 31, warp = tid >> 5;
    const int bh = blockIdx.y, b = bh / HEADS, h = bh % HEADS;
    const int q0 = blockIdx.x * 64;
    const size_t tok0 = (size_t)b * SEQ;

    const uint32_t sQ = smem_u32(smQ);
    const uint32_t sK[2] = { smem_u32(smK[0]), smem_u32(smK[1]) };
    const uint32_t sV[2] = { smem_u32(smV[0]), smem_u32(smV[1]) };

    const float pa = *pa_, pb = *pb_, pc = *pc_;

    const int ldrow = tid >> 1;
    const int ldc0  = (tid & 1) * 4;
    const __half* qsrc = qkv + (tok0 + q0 + ldrow) * QKV_N + h * HEAD_D + ldc0 * 8;
    const __half* ksrc = qkv + (tok0 + ldrow) * QKV_N + DIM + h * HEAD_D + ldc0 * 8;
    const __half* vsrc = ksrc + DIM;
    uint32_t ldoff[4];
    #pragma unroll
    for (int j = 0; j < 4; j++)
        ldoff[j] = ldrow * 128 + (((ldc0 + j) ^ (ldrow & 7)) << 4);

    #pragma unroll
    for (int j = 0; j < 4; j++) cp16(sQ + ldoff[j], qsrc + j * 8);
    #pragma unroll
    for (int j = 0; j < 4; j++) {
        cp16(sK[0] + ldoff[j], ksrc + j * 8);
        cp16(sV[0] + ldoff[j], vsrc + j * 8);
    }
    CP_COMMIT();
    CP_WAIT0();
    __syncthreads();

    const int g = lane >> 3, r = lane & 7;
    const int rowadd = (g & 1) * 8 + r;
    const int cadd = g >> 1;
    uint32_t qreg[4][4];
    {
        const uint32_t qb = sQ + (warp * 16 + rowadd) * 128;
        #pragma unroll
        for (int s = 0; s < 4; s++)
            LDSM_X4(qreg[s], qb + (((2 * s + cadd) ^ r) << 4));
    }

    float acc_o[8][4] = {};
    float rsum[2] = {};
    const int NT = SEQ / 64;

    for (int t = 0; t < NT; t++) {
        if (t + 1 < NT) {
            const int nb = (t + 1) & 1;
            const size_t roff = (size_t)(t + 1) * 64 * QKV_N;
            #pragma unroll
            for (int j = 0; j < 4; j++) {
                cp16(sK[nb] + ldoff[j], ksrc + roff + j * 8);
                cp16(sV[nb] + ldoff[j], vsrc + roff + j * 8);
            }
            CP_COMMIT();
            CP_WAIT1();
        } else {
            CP_WAIT0();
        }
        __syncthreads();

        const uint32_t sk = sK[t & 1], sv = sV[t & 1];

        float acc_s[8][4] = {};
        #pragma unroll
        for (int s = 0; s < 4; s++) {
            const uint32_t coff = ((2 * s + cadd) ^ r) << 4;
            #pragma unroll
            for (int p = 0; p < 4; p++) {
                uint32_t kb[4];
                LDSM_X4(kb, sk + (16 * p + rowadd) * 128 + coff);
                MMA_F16(acc_s[2 * p    ], qreg[s], kb[0], kb[2]);
                MMA_F16(acc_s[2 * p + 1], qreg[s], kb[1], kb[3]);
            }
        }

        #pragma unroll
        for (int j = 0; j < 8; j++)
            #pragma unroll
            for (int e = 0; e < 4; e++) {
                const float sv_ = acc_s[j][e] * SCALE_ATT;
                float pv = fmaf(fmaf(pa, sv_, pb), sv_, pc);
                pv = fmaxf(pv, 1e-6f);
                acc_s[j][e] = pv;
                rsum[e >> 1] += pv;
            }

        #pragma unroll
        for (int s = 0; s < 4; s++) {
            uint32_t pf[4];
            pf[0] = pack_f16(acc_s[2 * s][0],     acc_s[2 * s][1]);
            pf[1] = pack_f16(acc_s[2 * s][2],     acc_s[2 * s][3]);
            pf[2] = pack_f16(acc_s[2 * s + 1][0], acc_s[2 * s + 1][1]);
            pf[3] = pack_f16(acc_s[2 * s + 1][2], acc_s[2 * s + 1][3]);
            const uint32_t vrb = sv + (16 * s + rowadd) * 128;
            #pragma unroll
            for (int p = 0; p < 4; p++) {
                uint32_t vb[4];
                LDSM_X4_T(vb, vrb + (((2 * p + cadd) ^ r) << 4));
                MMA_F16(acc_o[2 * p    ], pf, vb[0], vb[1]);
                MMA_F16(acc_o[2 * p + 1], pf, vb[2], vb[3]);
            }
        }
        __syncthreads();
    }

    #pragma unroll
    for (int off = 1; off < 4; off <<= 1) {
        rsum[0] += __shfl_xor_sync(0xffffffffu, rsum[0], off);
        rsum[1] += __shfl_xor_sync(0xffffffffu, rsum[1], off);
    }
    const float inv0 = 1.0f / (rsum[0] + 1e-8f);
    const float inv1 = 1.0f / (rsum[1] + 1e-8f);

    const int row0 = q0 + warp * 16 + (lane >> 2);
    const int dcol = h * HEAD_D + 2 * (lane & 3);
    #pragma unroll
    for (int j = 0; j < 8; j++) {
        const size_t i0 = (tok0 + row0) * DIM + dcol + 8 * j;
        const size_t i1 = (tok0 + row0 + 8) * DIM + dcol + 8 * j;
        const float a0 = acc_o[j][0] * inv0, a1 = acc_o[j][1] * inv0;
        const float a2 = acc_o[j][2] * inv1, a3 = acc_o[j][3] * inv1;
        __half h0, l0, h1, l1, h2, l2, h3, l3;
        split_f16(a0, h0, l0); split_f16(a1, h1, l1);
        split_f16(a2, h2, l2); split_f16(a3, h3, l3);
        store_h2(ohi + i0, h0, h1);
        store_h2(olo + i0, l0, l1);
        store_h2(ohi + i1, h2, h3);
        store_h2(olo + i1, l2, l3);
    }
}

// =====================================================================
// Launch
// =====================================================================
extern "C" void kernel_launch(void* const* d_in, const int* in_sizes, int n_in,
                              void* d_out, int out_size)
{
    const float* x      = (const float*)d_in[0];
    const float* ln1_g  = (const float*)d_in[1];
    const float* ln1_b  = (const float*)d_in[2];
    const float* ln2_g  = (const float*)d_in[3];
    const float* ln2_b  = (const float*)d_in[4];
    const float* qkv_w  = (const float*)d_in[5];
    const float* qkv_b  = (const float*)d_in[6];
    const float* proj_w = (const float*)d_in[7];
    const float* proj_b = (const float*)d_in[8];
    const float* fc1_w  = (const float*)d_in[9];
    const float* fc1_b  = (const float*)d_in[10];
    const float* fc2_w  = (const float*)d_in[11];
    const float* fc2_b  = (const float*)d_in[12];
    const float* attn_a = (const float*)d_in[13];
    const float* attn_b = (const float*)d_in[14];
    const float* attn_c = (const float*)d_in[15];
    const float* gelu_a = (const float*)d_in[16];
    const float* gelu_b = (const float*)d_in[17];
    const float* gelu_c = (const float*)d_in[18];

    float *x1;
    __half *qkvh, *h_hi, *h_lo, *at_hi, *at_lo, *u_hi, *u_lo;
    __half *wq, *wp, *w1, *w2;
    cudaGetSymbolAddress((void**)&x1,    g_x1);
    cudaGetSymbolAddress((void**)&qkvh,  g_qkv);
    cudaGetSymbolAddress((void**)&h_hi,  g_h_hi);
    cudaGetSymbolAddress((void**)&h_lo,  g_h_lo);
    cudaGetSymbolAddress((void**)&at_hi, g_at_hi);
    cudaGetSymbolAddress((void**)&at_lo, g_at_lo);
    cudaGetSymbolAddress((void**)&u_hi,  g_u_hi);
    cudaGetSymbolAddress((void**)&u_lo,  g_u_lo);
    cudaGetSymbolAddress((void**)&wq,    g_wqkv);
    cudaGetSymbolAddress((void**)&wp,    g_wprj);
    cudaGetSymbolAddress((void**)&w1,    g_wfc1);
    cudaGetSymbolAddress((void**)&w2,    g_wfc2);

    cudaFuncSetAttribute(tc_gemm<1>, cudaFuncAttributeMaxDynamicSharedMemorySize,
                         GEMM_SMEM_BYTES);
    cudaFuncSetAttribute(tc_gemm<2>, cudaFuncAttributeMaxDynamicSharedMemorySize,
                         GEMM_SMEM_BYTES);
    cudaFuncSetAttribute(tc_gemm<3>, cudaFuncAttributeMaxDynamicSharedMemorySize,
                         GEMM_SMEM_BYTES);

    // 0) transpose + fp16-convert weights -> [N,K]
    wconv_kernel<<<dim3(QKV_N / 32, DIM / 32),   dim3(32, 8)>>>(qkv_w,  wq, DIM, QKV_N);
    wconv_kernel<<<dim3(DIM / 32, DIM / 32),     dim3(32, 8)>>>(proj_w, wp, DIM, DIM);
    wconv_kernel<<<dim3(HIDDEN / 32, DIM / 32),  dim3(32, 8)>>>(fc1_w,  w1, DIM, HIDDEN);
    wconv_kernel<<<dim3(DIM / 32, HIDDEN / 32),  dim3(32, 8)>>>(fc2_w,  w2, HIDDEN, DIM);

    // 1) LN1 -> fp16 hi/lo
    ln_kernel<<<MTOK, 256>>>(x, ln1_g, ln1_b, h_hi, h_lo);

    // 2) QKV GEMM -> plain fp16 q/k/v
    tc_gemm<3><<<dim3(QKV_N / 128, MTOK / 128), 256, GEMM_SMEM_BYTES>>>(
        h_hi, h_lo, wq, qkv_b, nullptr, nullptr, qkvh, nullptr, nullptr,
        QKV_N, DIM, nullptr, nullptr, nullptr);

    // 3) tensor-core fused attention -> fp16 hi/lo
    attn_tc_kernel<<<dim3(SEQ / 64, BATCH * HEADS), 128>>>(
        qkvh, at_hi, at_lo, attn_a, attn_b, attn_c);

    // 4) proj GEMM + residual(x) -> x1 (fp32)
    tc_gemm<1><<<dim3(DIM / 128, MTOK / 128), 256, GEMM_SMEM_BYTES>>>(
        at_hi, at_lo, wp, proj_b, x, x1, nullptr, nullptr, nullptr,
        DIM, DIM, nullptr, nullptr, nullptr);

    // 5) LN2 -> fp16 hi/lo
    ln_kernel<<<MTOK, 256>>>(x1, ln2_g, ln2_b, h_hi, h_lo);

    // 6) FC1 + poly-GELU -> u fp16 hi/lo
    tc_gemm<2><<<dim3(HIDDEN / 128, MTOK / 128), 256, GEMM_SMEM_BYTES>>>(
        h_hi, h_lo, w1, fc1_b, nullptr, nullptr, nullptr, u_hi, u_lo,
        HIDDEN, DIM, gelu_a, gelu_b, gelu_c);

    // 7) FC2 + residual(x1) -> out (fp32)
    tc_gemm<1><<<dim3(DIM / 128, MTOK / 128), 256, GEMM_SMEM_BYTES>>>(
        u_hi, u_lo, w2, fc2_b, x1, (float*)d_out, nullptr, nullptr, nullptr,
        DIM, HIDDEN, nullptr, nullptr, nullptr);
}

// round 10
// speedup vs baseline: 6.5512x; 1.5315x over previous
#include <cuda_runtime.h>
#include <cuda_fp16.h>
#include <cstdint>
#include <cstddef>

// ---------------- problem constants ----------------
#define BATCH   4
#define SEQ     2048
#define DIM     768
#define HEADS   12
#define HEAD_D  64
#define HIDDEN  3072
#define MTOK    (BATCH * SEQ)        // 8192 tokens
#define QKV_N   (3 * DIM)            // 2304
#define SCALE_ATT 0.125f             // 64^-0.5
#define LN_EPS  1e-5f

// ---------------- scratch (alloc-free: __device__ globals) ----------------
__device__ float g_x1 [(size_t)MTOK * DIM];       // residual after attn branch

__device__ __align__(16) __half g_qkv[(size_t)MTOK * QKV_N]; // q/k/v fp16
__device__ __align__(16) __half g_h  [(size_t)MTOK * DIM];   // LN out fp16
__device__ __align__(16) __half g_at [(size_t)MTOK * DIM];   // attention out fp16
__device__ __align__(16) __half g_u  [(size_t)MTOK * HIDDEN];// FC1/gelu out fp16

// transposed weights: stored [N, K] fp16
__device__ __align__(16) __half g_wqkv[(size_t)QKV_N * DIM];
__device__ __align__(16) __half g_wprj[(size_t)DIM * DIM];
__device__ __align__(16) __half g_wfc1[(size_t)HIDDEN * DIM];
__device__ __align__(16) __half g_wfc2[(size_t)DIM * HIDDEN];

// =====================================================================
// PTX helpers (sm_80-class: mma.sync / ldmatrix / cp.async — OK on sm_103)
// =====================================================================
__device__ __forceinline__ uint32_t smem_u32(const void* p) {
    uint32_t a;
    asm("{ .reg .u64 t; cvta.to.shared.u64 t, %1; cvt.u32.u64 %0, t; }"
        : "=r"(a) : "l"(p));
    return a;
}

#define LDSM_X4(r, addr)                                                        \
    asm volatile("ldmatrix.sync.aligned.m8n8.x4.shared.b16 {%0,%1,%2,%3}, [%4];"\
        : "=r"((r)[0]), "=r"((r)[1]), "=r"((r)[2]), "=r"((r)[3]) : "r"(addr))

#define LDSM_X4_T(r, addr)                                                      \
    asm volatile("ldmatrix.sync.aligned.m8n8.x4.trans.shared.b16 {%0,%1,%2,%3}, [%4];"\
        : "=r"((r)[0]), "=r"((r)[1]), "=r"((r)[2]), "=r"((r)[3]) : "r"(addr))

#define MMA_F16(d, a, b0, b1)                                                   \
    asm volatile("mma.sync.aligned.m16n8k16.row.col.f32.f16.f16.f32 "           \
        "{%0,%1,%2,%3}, {%4,%5,%6,%7}, {%8,%9}, {%0,%1,%2,%3};"                 \
        : "+f"((d)[0]), "+f"((d)[1]), "+f"((d)[2]), "+f"((d)[3])                \
        : "r"((a)[0]), "r"((a)[1]), "r"((a)[2]), "r"((a)[3]), "r"(b0), "r"(b1))

__device__ __forceinline__ void cp16(uint32_t dst, const void* src) {
    asm volatile("cp.async.cg.shared.global [%0], [%1], 16;"
                 :: "r"(dst), "l"(src) : "memory");
}
#define CP_COMMIT() asm volatile("cp.async.commit_group;" ::: "memory")
#define CP_WAIT1()  asm volatile("cp.async.wait_group 1;" ::: "memory")
#define CP_WAIT0()  asm volatile("cp.async.wait_group 0;" ::: "memory")

__device__ __forceinline__ uint32_t pack_f16(float x, float y) {
    __half2 t = __halves2half2(__float2half_rn(x), __float2half_rn(y));
    return *(uint32_t*)&t;
}

__device__ __forceinline__ void store_h2(__half* p, float a, float b) {
    __half2 t = __halves2half2(__float2half_rn(a), __float2half_rn(b));
    *(__half2*)p = t;
}

// =====================================================================
// Weight convert: W[K,N] fp32 -> Wt[N,K] fp16 (tiled transpose)
// =====================================================================
__global__ __launch_bounds__(256) void wconv_kernel(
    const float* __restrict__ W, __half* __restrict__ T, int K, int N)
{
    __shared__ float t[32][33];
    const int n0 = blockIdx.x * 32, k0 = blockIdx.y * 32;
    const int tx = threadIdx.x, ty = threadIdx.y;
    #pragma unroll
    for (int j = 0; j < 4; j++)
        t[ty + 8 * j][tx] = W[(size_t)(k0 + ty + 8 * j) * N + n0 + tx];
    __syncthreads();
    #pragma unroll
    for (int j = 0; j < 4; j++)
        T[(size_t)(n0 + ty + 8 * j) * K + k0 + tx] = __float2half_rn(t[tx][ty + 8 * j]);
}

// =====================================================================
// LayerNorm -> fp16
// =====================================================================
__global__ __launch_bounds__(256) void ln_kernel(
    const float* __restrict__ x, const float* __restrict__ gamma,
    const float* __restrict__ beta, __half* __restrict__ out)
{
    const int row = blockIdx.x;
    const int tid = threadIdx.x;
    const float* xr = x + (size_t)row * DIM;

    float v0 = xr[tid], v1 = xr[tid + 256], v2 = xr[tid + 512];
    float s = v0 + v1 + v2;
    float q = v0 * v0 + v1 * v1 + v2 * v2;

    __shared__ float ws[8], wq[8];
    #pragma unroll
    for (int o = 16; o; o >>= 1) {
        s += __shfl_xor_sync(0xffffffffu, s, o);
        q += __shfl_xor_sync(0xffffffffu, q, o);
    }
    if ((tid & 31) == 0) { ws[tid >> 5] = s; wq[tid >> 5] = q; }
    __syncthreads();
    float ts = 0.f, tq = 0.f;
    #pragma unroll
    for (int i = 0; i < 8; i++) { ts += ws[i]; tq += wq[i]; }

    const float mean = ts * (1.0f / DIM);
    const float var  = tq * (1.0f / DIM) - mean * mean;
    const float rstd = rsqrtf(var + LN_EPS);

    const size_t rb = (size_t)row * DIM;
    #pragma unroll
    for (int j = 0; j < 3; j++) {
        const int c = tid + j * 256;
        const float v = (j == 0 ? v0 : (j == 1 ? v1 : v2));
        out[rb + c] = __float2half_rn((v - mean) * rstd * gamma[c] + beta[c]);
    }
}

// =====================================================================
// fp16 tensor-core GEMM via mma.sync.m16n8k16:
//   C[M,N] = A[M,K] @ B[N,K]^T  (fp32 accumulate)
// Block 128x128x64, 8 warps, 3-stage cp.async pipeline, 96KB smem.
// Stage: A 16KB ([128 rows][128B], chunk^(row&7) swizzle) + B 16KB.
// MODE 1: out = D + bias + res (fp32)
// MODE 2: u = D + bias; poly-GELU(u) -> fp16
// MODE 3: out = D + bias -> fp16 (attention q/k/v)
// =====================================================================
#define STAGE_BYTES 32768
#define GEMM_SMEM_BYTES (3 * STAGE_BYTES)

template<int MODE>
__global__ __launch_bounds__(256) void tc_gemm(
    const __half* __restrict__ A, const __half* __restrict__ B,
    const float* __restrict__ bias, const float* __restrict__ res,
    float* __restrict__ outf, __half* __restrict__ out16,
    int N, int K,
    const float* __restrict__ pga, const float* __restrict__ pgb,
    const float* __restrict__ pgc)
{
    extern __shared__ char sm[];
    const uint32_t sbase = smem_u32(sm);
    const int tid = threadIdx.x;
    const int lane = tid & 31, wid = tid >> 5;
    const int wm = wid & 3, wn = wid >> 2;      // 4 x 2 warp grid
    const int m0 = blockIdx.y * 128, n0 = blockIdx.x * 128;
    const int nt = K >> 6;                       // K/64 stages

    // per-thread loads: 4 A chunks + 4 B chunks of 16B per stage
    const __half* agsrc[4]; uint32_t asoff[4];
    const __half* bgsrc[4]; uint32_t bsoff[4];
    #pragma unroll
    for (int i = 0; i < 4; i++) {
        const int id = tid + i * 256;            // 0..1023
        const int row = id >> 3, c = id & 7;     // 128 rows x 8 chunks
        agsrc[i] = A + (size_t)(m0 + row) * K + c * 8;
        asoff[i] = row * 128 + ((c ^ (row & 7)) << 4);
        bgsrc[i] = B + (size_t)(n0 + row) * K + c * 8;
        bsoff[i] = 16384 + row * 128 + ((c ^ (row & 7)) << 4);
    }

    #define LOAD_STAGE(kt, slot) do {                                          \
        const uint32_t sb_ = sbase + (uint32_t)(slot) * STAGE_BYTES;            \
        const size_t ko_ = (size_t)(kt) * 64;                                   \
        _Pragma("unroll")                                                       \
        for (int i_ = 0; i_ < 4; i_++) {                                        \
            cp16(sb_ + asoff[i_], agsrc[i_] + ko_);                             \
            cp16(sb_ + bsoff[i_], bgsrc[i_] + ko_);                             \
        }                                                                       \
    } while (0)

    LOAD_STAGE(0, 0); CP_COMMIT();
    LOAD_STAGE(1, 1); CP_COMMIT();

    // ldmatrix offsets within a stage (4 k-steps of 16)
    uint32_t a_off[2][4];
    #pragma unroll
    for (int mi = 0; mi < 2; mi++) {
        const int row = wm * 32 + mi * 16 + (lane & 15);
        const int kbit = (lane >> 4) & 1;
        #pragma unroll
        for (int ks = 0; ks < 4; ks++) {
            const int chi = ks * 2 + kbit;
            a_off[mi][ks] = row * 128 + ((chi ^ (row & 7)) << 4);
        }
    }
    uint32_t b_off[4][4];
    #pragma unroll
    for (int nj = 0; nj < 4; nj++) {
        const int nrow = wn * 64 + nj * 16 + (lane & 7) + ((lane >> 4) << 3);
        const int kbit = (lane >> 3) & 1;
        #pragma unroll
        for (int ks = 0; ks < 4; ks++) {
            const int chi = ks * 2 + kbit;
            b_off[nj][ks] = 16384 + nrow * 128 + ((chi ^ (nrow & 7)) << 4);
        }
    }

    float acc[2][8][4] = {};

    for (int kt = 0; kt < nt; kt++) {
        CP_WAIT1();
        __syncthreads();
        const uint32_t sb = sbase + (uint32_t)(kt % 3) * STAGE_BYTES;

        #pragma unroll
        for (int ks = 0; ks < 4; ks++) {
            uint32_t ar[2][4];
            LDSM_X4(ar[0], sb + a_off[0][ks]);
            LDSM_X4(ar[1], sb + a_off[1][ks]);
            #pragma unroll
            for (int nj = 0; nj < 4; nj++) {
                uint32_t br[4];
                LDSM_X4(br, sb + b_off[nj][ks]);
                #pragma unroll
                for (int mi = 0; mi < 2; mi++) {
                    MMA_F16(acc[mi][nj * 2    ], ar[mi], br[0], br[1]);
                    MMA_F16(acc[mi][nj * 2 + 1], ar[mi], br[2], br[3]);
                }
            }
        }
        __syncthreads();
        if (kt + 2 < nt) LOAD_STAGE(kt + 2, (kt + 2) % 3);
        CP_COMMIT();
    }

    float gaV = 0.f, gbV = 0.f, gcV = 0.f;
    if (MODE == 2) { gaV = *pga; gbV = *pgb; gcV = *pgc; }

    #pragma unroll
    for (int mi = 0; mi < 2; mi++) {
        const int ma = m0 + wm * 32 + mi * 16 + (lane >> 2);
        #pragma unroll
        for (int t = 0; t < 8; t++) {
            const int n = n0 + wn * 64 + t * 8 + ((lane & 3) << 1);
            const float b0 = bias[n], b1 = bias[n + 1];
            #pragma unroll
            for (int half = 0; half < 2; half++) {
                const int m = ma + half * 8;
                float v0 = acc[mi][t][half * 2]     + b0;
                float v1 = acc[mi][t][half * 2 + 1] + b1;
                const size_t idx = (size_t)m * N + n;
                if (MODE == 2) {
                    v0 = fmaf(fmaf(gaV, v0, gbV), v0, gcV);
                    v1 = fmaf(fmaf(gaV, v1, gbV), v1, gcV);
                    store_h2(out16 + idx, v0, v1);
                } else if (MODE == 3) {
                    store_h2(out16 + idx, v0, v1);
                } else {
                    const float2 rv = *(const float2*)(res + idx);
                    *(float2*)(outf + idx) = make_float2(v0 + rv.x, v1 + rv.y);
                }
            }
        }
    }
    #undef LOAD_STAGE
}

// =====================================================================
// Tensor-core fused attention (flash-style, fp16 mma, fp32 accum):
//   S = QK^T*scale; P = max(a*S^2+b*S+c, 1e-6); O = (P V) / rowsum(P)
// Block: 128 threads (4 warps x 16 queries), 64-query x 64-key tiles.
// =====================================================================
__global__ __launch_bounds__(128) void attn_tc_kernel(
    const __half* __restrict__ qkv, __half* __restrict__ out,
    const float* __restrict__ pa_, const float* __restrict__ pb_,
    const float* __restrict__ pc_)
{
    __shared__ __align__(16) char smQ[8192];
    __shared__ __align__(16) char smK[2][8192];
    __shared__ __align__(16) char smV[2][8192];

    const int tid = threadIdx.x, lane = tid & 31, warp = tid >> 5;
    const int bh = blockIdx.y, b = bh / HEADS, h = bh % HEADS;
    const int q0 = blockIdx.x * 64;
    const size_t tok0 = (size_t)b * SEQ;

    const uint32_t sQ = smem_u32(smQ);
    const uint32_t sK[2] = { smem_u32(smK[0]), smem_u32(smK[1]) };
    const uint32_t sV[2] = { smem_u32(smV[0]), smem_u32(smV[1]) };

    const float pa = *pa_, pb = *pb_, pc = *pc_;

    const int ldrow = tid >> 1;
    const int ldc0  = (tid & 1) * 4;
    const __half* qsrc = qkv + (tok0 + q0 + ldrow) * QKV_N + h * HEAD_D + ldc0 * 8;
    const __half* ksrc = qkv + (tok0 + ldrow) * QKV_N + DIM + h * HEAD_D + ldc0 * 8;
    const __half* vsrc = ksrc + DIM;
    uint32_t ldoff[4];
    #pragma unroll
    for (int j = 0; j < 4; j++)
        ldoff[j] = ldrow * 128 + (((ldc0 + j) ^ (ldrow & 7)) << 4);

    #pragma unroll
    for (int j = 0; j < 4; j++) cp16(sQ + ldoff[j], qsrc + j * 8);
    #pragma unroll
    for (int j = 0; j < 4; j++) {
        cp16(sK[0] + ldoff[j], ksrc + j * 8);
        cp16(sV[0] + ldoff[j], vsrc + j * 8);
    }
    CP_COMMIT();
    CP_WAIT0();
    __syncthreads();

    const int g = lane >> 3, r = lane & 7;
    const int rowadd = (g & 1) * 8 + r;
    const int cadd = g >> 1;
    uint32_t qreg[4][4];
    {
        const uint32_t qb = sQ + (warp * 16 + rowadd) * 128;
        #pragma unroll
        for (int s = 0; s < 4; s++)
            LDSM_X4(qreg[s], qb + (((2 * s + cadd) ^ r) << 4));
    }

    float acc_o[8][4] = {};
    float rsum[2] = {};
    const int NT = SEQ / 64;

    for (int t = 0; t < NT; t++) {
        if (t + 1 < NT) {
            const int nb = (t + 1) & 1;
            const size_t roff = (size_t)(t + 1) * 64 * QKV_N;
            #pragma unroll
            for (int j = 0; j < 4; j++) {
                cp16(sK[nb] + ldoff[j], ksrc + roff + j * 8);
                cp16(sV[nb] + ldoff[j], vsrc + roff + j * 8);
            }
            CP_COMMIT();
            CP_WAIT1();
        } else {
            CP_WAIT0();
        }
        __syncthreads();

        const uint32_t sk = sK[t & 1], sv = sV[t & 1];

        float acc_s[8][4] = {};
        #pragma unroll
        for (int s = 0; s < 4; s++) {
            const uint32_t coff = ((2 * s + cadd) ^ r) << 4;
            #pragma unroll
            for (int p = 0; p < 4; p++) {
                uint32_t kb[4];
                LDSM_X4(kb, sk + (16 * p + rowadd) * 128 + coff);
                MMA_F16(acc_s[2 * p    ], qreg[s], kb[0], kb[2]);
                MMA_F16(acc_s[2 * p + 1], qreg[s], kb[1], kb[3]);
            }
        }

        #pragma unroll
        for (int j = 0; j < 8; j++)
            #pragma unroll
            for (int e = 0; e < 4; e++) {
                const float sv_ = acc_s[j][e] * SCALE_ATT;
                float pv = fmaf(fmaf(pa, sv_, pb), sv_, pc);
                pv = fmaxf(pv, 1e-6f);
                acc_s[j][e] = pv;
                rsum[e >> 1] += pv;
            }

        #pragma unroll
        for (int s = 0; s < 4; s++) {
            uint32_t pf[4];
            pf[0] = pack_f16(acc_s[2 * s][0],     acc_s[2 * s][1]);
            pf[1] = pack_f16(acc_s[2 * s][2],     acc_s[2 * s][3]);
            pf[2] = pack_f16(acc_s[2 * s + 1][0], acc_s[2 * s + 1][1]);
            pf[3] = pack_f16(acc_s[2 * s + 1][2], acc_s[2 * s + 1][3]);
            const uint32_t vrb = sv + (16 * s + rowadd) * 128;
            #pragma unroll
            for (int p = 0; p < 4; p++) {
                uint32_t vb[4];
                LDSM_X4_T(vb, vrb + (((2 * p + cadd) ^ r) << 4));
                MMA_F16(acc_o[2 * p    ], pf, vb[0], vb[1]);
                MMA_F16(acc_o[2 * p + 1], pf, vb[2], vb[3]);
            }
        }
        __syncthreads();
    }

    #pragma unroll
    for (int off = 1; off < 4; off <<= 1) {
        rsum[0] += __shfl_xor_sync(0xffffffffu, rsum[0], off);
        rsum[1] += __shfl_xor_sync(0xffffffffu, rsum[1], off);
    }
    const float inv0 = 1.0f / (rsum[0] + 1e-8f);
    const float inv1 = 1.0f / (rsum[1] + 1e-8f);

    const int row0 = q0 + warp * 16 + (lane >> 2);
    const int dcol = h * HEAD_D + 2 * (lane & 3);
    #pragma unroll
    for (int j = 0; j < 8; j++) {
        const size_t i0 = (tok0 + row0) * DIM + dcol + 8 * j;
        const size_t i1 = (tok0 + row0 + 8) * DIM + dcol + 8 * j;
        store_h2(out + i0, acc_o[j][0] * inv0, acc_o[j][1] * inv0);
        store_h2(out + i1, acc_o[j][2] * inv1, acc_o[j][3] * inv1);
    }
}

// =====================================================================
// Launch
// =====================================================================
extern "C" void kernel_launch(void* const* d_in, const int* in_sizes, int n_in,
                              void* d_out, int out_size)
{
    const float* x      = (const float*)d_in[0];
    const float* ln1_g  = (const float*)d_in[1];
    const float* ln1_b  = (const float*)d_in[2];
    const float* ln2_g  = (const float*)d_in[3];
    const float* ln2_b  = (const float*)d_in[4];
    const float* qkv_w  = (const float*)d_in[5];
    const float* qkv_b  = (const float*)d_in[6];
    const float* proj_w = (const float*)d_in[7];
    const float* proj_b = (const float*)d_in[8];
    const float* fc1_w  = (const float*)d_in[9];
    const float* fc1_b  = (const float*)d_in[10];
    const float* fc2_w  = (const float*)d_in[11];
    const float* fc2_b  = (const float*)d_in[12];
    const float* attn_a = (const float*)d_in[13];
    const float* attn_b = (const float*)d_in[14];
    const float* attn_c = (const float*)d_in[15];
    const float* gelu_a = (const float*)d_in[16];
    const float* gelu_b = (const float*)d_in[17];
    const float* gelu_c = (const float*)d_in[18];

    float *x1;
    __half *qkvh, *hbuf, *atbuf, *ubuf, *wq, *wp, *w1, *w2;
    cudaGetSymbolAddress((void**)&x1,    g_x1);
    cudaGetSymbolAddress((void**)&qkvh,  g_qkv);
    cudaGetSymbolAddress((void**)&hbuf,  g_h);
    cudaGetSymbolAddress((void**)&atbuf, g_at);
    cudaGetSymbolAddress((void**)&ubuf,  g_u);
    cudaGetSymbolAddress((void**)&wq,    g_wqkv);
    cudaGetSymbolAddress((void**)&wp,    g_wprj);
    cudaGetSymbolAddress((void**)&w1,    g_wfc1);
    cudaGetSymbolAddress((void**)&w2,    g_wfc2);

    cudaFuncSetAttribute(tc_gemm<1>, cudaFuncAttributeMaxDynamicSharedMemorySize,
                         GEMM_SMEM_BYTES);
    cudaFuncSetAttribute(tc_gemm<2>, cudaFuncAttributeMaxDynamicSharedMemorySize,
                         GEMM_SMEM_BYTES);
    cudaFuncSetAttribute(tc_gemm<3>, cudaFuncAttributeMaxDynamicSharedMemorySize,
                         GEMM_SMEM_BYTES);

    // 0) transpose + fp16-convert weights -> [N,K]
    wconv_kernel<<<dim3(QKV_N / 32, DIM / 32),   dim3(32, 8)>>>(qkv_w,  wq, DIM, QKV_N);
    wconv_kernel<<<dim3(DIM / 32, DIM / 32),     dim3(32, 8)>>>(proj_w, wp, DIM, DIM);
    wconv_kernel<<<dim3(HIDDEN / 32, DIM / 32),  dim3(32, 8)>>>(fc1_w,  w1, DIM, HIDDEN);
    wconv_kernel<<<dim3(DIM / 32, HIDDEN / 32),  dim3(32, 8)>>>(fc2_w,  w2, HIDDEN, DIM);

    // 1) LN1 -> fp16
    ln_kernel<<<MTOK, 256>>>(x, ln1_g, ln1_b, hbuf);

    // 2) QKV GEMM -> fp16 q/k/v
    tc_gemm<3><<<dim3(QKV_N / 128, MTOK / 128), 256, GEMM_SMEM_BYTES>>>(
        hbuf, wq, qkv_b, nullptr, nullptr, qkvh,
        QKV_N, DIM, nullptr, nullptr, nullptr);

    // 3) tensor-core fused attention -> fp16
    attn_tc_kernel<<<dim3(SEQ / 64, BATCH * HEADS), 128>>>(
        qkvh, atbuf, attn_a, attn_b, attn_c);

    // 4) proj GEMM + residual(x) -> x1 (fp32)
    tc_gemm<1><<<dim3(DIM / 128, MTOK / 128), 256, GEMM_SMEM_BYTES>>>(
        atbuf, wp, proj_b, x, x1, nullptr,
        DIM, DIM, nullptr, nullptr, nullptr);

    // 5) LN2 -> fp16
    ln_kernel<<<MTOK, 256>>>(x1, ln2_g, ln2_b, hbuf);

    // 6) FC1 + poly-GELU -> u fp16
    tc_gemm<2><<<dim3(HIDDEN / 128, MTOK / 128), 256, GEMM_SMEM_BYTES>>>(
        hbuf, w1, fc1_b, nullptr, nullptr, ubuf,
        HIDDEN, DIM, gelu_a, gelu_b, gelu_c);

    // 7) FC2 + residual(x1) -> out (fp32)
    tc_gemm<1><<<dim3(DIM / 128, MTOK / 128), 256, GEMM_SMEM_BYTES>>>(
        ubuf, w2, fc2_b, x1, (float*)d_out, nullptr,
        DIM, HIDDEN, nullptr, nullptr, nullptr);
}

// round 11
// speedup vs baseline: 6.7844x; 1.0356x over previous
#include <cuda_runtime.h>
#include <cuda_fp16.h>
#include <cstdint>
#include <cstddef>

// ---------------- problem constants ----------------
#define BATCH   4
#define SEQ     2048
#define DIM     768
#define HEADS   12
#define HEAD_D  64
#define HIDDEN  3072
#define MTOK    (BATCH * SEQ)        // 8192 tokens
#define QKV_N   (3 * DIM)            // 2304
#define SCALE_ATT 0.125f             // 64^-0.5
#define LN_EPS  1e-5f

// ---------------- scratch (alloc-free: __device__ globals) ----------------
__device__ float g_x1 [(size_t)MTOK * DIM];       // residual after attn branch

__device__ __align__(16) __half g_qkv[(size_t)MTOK * QKV_N]; // q/k/v fp16
__device__ __align__(16) __half g_h  [(size_t)MTOK * DIM];   // LN out fp16
__device__ __align__(16) __half g_at [(size_t)MTOK * DIM];   // attention out fp16
__device__ __align__(16) __half g_u  [(size_t)MTOK * HIDDEN];// FC1/gelu out fp16

// transposed weights: stored [N, K] fp16
__device__ __align__(16) __half g_wqkv[(size_t)QKV_N * DIM];
__device__ __align__(16) __half g_wprj[(size_t)DIM * DIM];
__device__ __align__(16) __half g_wfc1[(size_t)HIDDEN * DIM];
__device__ __align__(16) __half g_wfc2[(size_t)DIM * HIDDEN];

// =====================================================================
// PTX helpers (sm_80-class: mma.sync / ldmatrix / cp.async — OK on sm_103)
// =====================================================================
__device__ __forceinline__ uint32_t smem_u32(const void* p) {
    uint32_t a;
    asm("{ .reg .u64 t; cvta.to.shared.u64 t, %1; cvt.u32.u64 %0, t; }"
        : "=r"(a) : "l"(p));
    return a;
}

#define LDSM_X4(r, addr)                                                        \
    asm volatile("ldmatrix.sync.aligned.m8n8.x4.shared.b16 {%0,%1,%2,%3}, [%4];"\
        : "=r"((r)[0]), "=r"((r)[1]), "=r"((r)[2]), "=r"((r)[3]) : "r"(addr))

#define LDSM_X4_T(r, addr)                                                      \
    asm volatile("ldmatrix.sync.aligned.m8n8.x4.trans.shared.b16 {%0,%1,%2,%3}, [%4];"\
        : "=r"((r)[0]), "=r"((r)[1]), "=r"((r)[2]), "=r"((r)[3]) : "r"(addr))

#define MMA_F16(d, a, b0, b1)                                                   \
    asm volatile("mma.sync.aligned.m16n8k16.row.col.f32.f16.f16.f32 "           \
        "{%0,%1,%2,%3}, {%4,%5,%6,%7}, {%8,%9}, {%0,%1,%2,%3};"                 \
        : "+f"((d)[0]), "+f"((d)[1]), "+f"((d)[2]), "+f"((d)[3])                \
        : "r"((a)[0]), "r"((a)[1]), "r"((a)[2]), "r"((a)[3]), "r"(b0), "r"(b1))

__device__ __forceinline__ void cp16(uint32_t dst, const void* src) {
    asm volatile("cp.async.cg.shared.global [%0], [%1], 16;"
                 :: "r"(dst), "l"(src) : "memory");
}
#define CP_COMMIT() asm volatile("cp.async.commit_group;" ::: "memory")
#define CP_WAIT1()  asm volatile("cp.async.wait_group 1;" ::: "memory")
#define CP_WAIT0()  asm volatile("cp.async.wait_group 0;" ::: "memory")

__device__ __forceinline__ uint32_t pack_f16(float x, float y) {
    __half2 t = __halves2half2(__float2half_rn(x), __float2half_rn(y));
    return *(uint32_t*)&t;
}

__device__ __forceinline__ void store_h2(__half* p, float a, float b) {
    __half2 t = __halves2half2(__float2half_rn(a), __float2half_rn(b));
    *(__half2*)p = t;
}

// =====================================================================
// Weight convert: W[K,N] fp32 -> Wt[N,K] fp16 (tiled transpose)
// =====================================================================
__global__ __launch_bounds__(256) void wconv_kernel(
    const float* __restrict__ W, __half* __restrict__ T, int K, int N)
{
    __shared__ float t[32][33];
    const int n0 = blockIdx.x * 32, k0 = blockIdx.y * 32;
    const int tx = threadIdx.x, ty = threadIdx.y;
    #pragma unroll
    for (int j = 0; j < 4; j++)
        t[ty + 8 * j][tx] = W[(size_t)(k0 + ty + 8 * j) * N + n0 + tx];
    __syncthreads();
    #pragma unroll
    for (int j = 0; j < 4; j++)
        T[(size_t)(n0 + ty + 8 * j) * K + k0 + tx] = __float2half_rn(t[tx][ty + 8 * j]);
}

// =====================================================================
// LayerNorm -> fp16
// =====================================================================
__global__ __launch_bounds__(256) void ln_kernel(
    const float* __restrict__ x, const float* __restrict__ gamma,
    const float* __restrict__ beta, __half* __restrict__ out)
{
    const int row = blockIdx.x;
    const int tid = threadIdx.x;
    const float* xr = x + (size_t)row * DIM;

    float v0 = xr[tid], v1 = xr[tid + 256], v2 = xr[tid + 512];
    float s = v0 + v1 + v2;
    float q = v0 * v0 + v1 * v1 + v2 * v2;

    __shared__ float ws[8], wq[8];
    #pragma unroll
    for (int o = 16; o; o >>= 1) {
        s += __shfl_xor_sync(0xffffffffu, s, o);
        q += __shfl_xor_sync(0xffffffffu, q, o);
    }
    if ((tid & 31) == 0) { ws[tid >> 5] = s; wq[tid >> 5] = q; }
    __syncthreads();
    float ts = 0.f, tq = 0.f;
    #pragma unroll
    for (int i = 0; i < 8; i++) { ts += ws[i]; tq += wq[i]; }

    const float mean = ts * (1.0f / DIM);
    const float var  = tq * (1.0f / DIM) - mean * mean;
    const float rstd = rsqrtf(var + LN_EPS);

    const size_t rb = (size_t)row * DIM;
    #pragma unroll
    for (int j = 0; j < 3; j++) {
        const int c = tid + j * 256;
        const float v = (j == 0 ? v0 : (j == 1 ? v1 : v2));
        out[rb + c] = __float2half_rn((v - mean) * rstd * gamma[c] + beta[c]);
    }
}

// =====================================================================
// fp16 tensor-core GEMM via mma.sync.m16n8k16:
//   C[M,N] = A[M,K] @ B[N,K]^T  (fp32 accumulate)
// Block 128x128x64, 8 warps, 3-stage cp.async pipeline, 96KB smem.
// MODE 1: out = D + bias + res (fp32)
// MODE 2: u = D + bias; poly-GELU(u) -> fp16
// MODE 3: out = D + bias -> fp16 (attention q/k/v)
// =====================================================================
#define STAGE_BYTES 32768
#define GEMM_SMEM_BYTES (3 * STAGE_BYTES)

template<int MODE>
__global__ __launch_bounds__(256) void tc_gemm(
    const __half* __restrict__ A, const __half* __restrict__ B,
    const float* __restrict__ bias, const float* __restrict__ res,
    float* __restrict__ outf, __half* __restrict__ out16,
    int N, int K,
    const float* __restrict__ pga, const float* __restrict__ pgb,
    const float* __restrict__ pgc)
{
    extern __shared__ char sm[];
    const uint32_t sbase = smem_u32(sm);
    const int tid = threadIdx.x;
    const int lane = tid & 31, wid = tid >> 5;
    const int wm = wid & 3, wn = wid >> 2;      // 4 x 2 warp grid
    const int m0 = blockIdx.y * 128, n0 = blockIdx.x * 128;
    const int nt = K >> 6;                       // K/64 stages

    const __half* agsrc[4]; uint32_t asoff[4];
    const __half* bgsrc[4]; uint32_t bsoff[4];
    #pragma unroll
    for (int i = 0; i < 4; i++) {
        const int id = tid + i * 256;            // 0..1023
        const int row = id >> 3, c = id & 7;     // 128 rows x 8 chunks
        agsrc[i] = A + (size_t)(m0 + row) * K + c * 8;
        asoff[i] = row * 128 + ((c ^ (row & 7)) << 4);
        bgsrc[i] = B + (size_t)(n0 + row) * K + c * 8;
        bsoff[i] = 16384 + row * 128 + ((c ^ (row & 7)) << 4);
    }

    #define LOAD_STAGE(kt, slot) do {                                          \
        const uint32_t sb_ = sbase + (uint32_t)(slot) * STAGE_BYTES;            \
        const size_t ko_ = (size_t)(kt) * 64;                                   \
        _Pragma("unroll")                                                       \
        for (int i_ = 0; i_ < 4; i_++) {                                        \
            cp16(sb_ + asoff[i_], agsrc[i_] + ko_);                             \
            cp16(sb_ + bsoff[i_], bgsrc[i_] + ko_);                             \
        }                                                                       \
    } while (0)

    LOAD_STAGE(0, 0); CP_COMMIT();
    LOAD_STAGE(1, 1); CP_COMMIT();

    uint32_t a_off[2][4];
    #pragma unroll
    for (int mi = 0; mi < 2; mi++) {
        const int row = wm * 32 + mi * 16 + (lane & 15);
        const int kbit = (lane >> 4) & 1;
        #pragma unroll
        for (int ks = 0; ks < 4; ks++) {
            const int chi = ks * 2 + kbit;
            a_off[mi][ks] = row * 128 + ((chi ^ (row & 7)) << 4);
        }
    }
    uint32_t b_off[4][4];
    #pragma unroll
    for (int nj = 0; nj < 4; nj++) {
        const int nrow = wn * 64 + nj * 16 + (lane & 7) + ((lane >> 4) << 3);
        const int kbit = (lane >> 3) & 1;
        #pragma unroll
        for (int ks = 0; ks < 4; ks++) {
            const int chi = ks * 2 + kbit;
            b_off[nj][ks] = 16384 + nrow * 128 + ((chi ^ (nrow & 7)) << 4);
        }
    }

    float acc[2][8][4] = {};

    for (int kt = 0; kt < nt; kt++) {
        CP_WAIT1();
        __syncthreads();
        const uint32_t sb = sbase + (uint32_t)(kt % 3) * STAGE_BYTES;

        #pragma unroll
        for (int ks = 0; ks < 4; ks++) {
            uint32_t ar[2][4];
            LDSM_X4(ar[0], sb + a_off[0][ks]);
            LDSM_X4(ar[1], sb + a_off[1][ks]);
            #pragma unroll
            for (int nj = 0; nj < 4; nj++) {
                uint32_t br[4];
                LDSM_X4(br, sb + b_off[nj][ks]);
                #pragma unroll
                for (int mi = 0; mi < 2; mi++) {
                    MMA_F16(acc[mi][nj * 2    ], ar[mi], br[0], br[1]);
                    MMA_F16(acc[mi][nj * 2 + 1], ar[mi], br[2], br[3]);
                }
            }
        }
        __syncthreads();
        if (kt + 2 < nt) LOAD_STAGE(kt + 2, (kt + 2) % 3);
        CP_COMMIT();
    }

    float gaV = 0.f, gbV = 0.f, gcV = 0.f;
    if (MODE == 2) { gaV = *pga; gbV = *pgb; gcV = *pgc; }

    #pragma unroll
    for (int mi = 0; mi < 2; mi++) {
        const int ma = m0 + wm * 32 + mi * 16 + (lane >> 2);
        #pragma unroll
        for (int t = 0; t < 8; t++) {
            const int n = n0 + wn * 64 + t * 8 + ((lane & 3) << 1);
            const float b0 = bias[n], b1 = bias[n + 1];
            #pragma unroll
            for (int half = 0; half < 2; half++) {
                const int m = ma + half * 8;
                float v0 = acc[mi][t][half * 2]     + b0;
                float v1 = acc[mi][t][half * 2 + 1] + b1;
                const size_t idx = (size_t)m * N + n;
                if (MODE == 2) {
                    v0 = fmaf(fmaf(gaV, v0, gbV), v0, gcV);
                    v1 = fmaf(fmaf(gaV, v1, gbV), v1, gcV);
                    store_h2(out16 + idx, v0, v1);
                } else if (MODE == 3) {
                    store_h2(out16 + idx, v0, v1);
                } else {
                    const float2 rv = *(const float2*)(res + idx);
                    *(float2*)(outf + idx) = make_float2(v0 + rv.x, v1 + rv.y);
                }
            }
        }
    }
    #undef LOAD_STAGE
}

// =====================================================================
// Tensor-core fused attention (flash-style, fp16 mma, fp32 accum):
//   S = QK^T*scale; P = max(a*S^2+b*S+c, 1e-6); O = (P V) / rowsum(P)
// Block: 256 threads (8 warps x 16 queries = 128-query tile),
// 64-key tiles double-buffered via cp.async. K/V ldsm amortized over 2x
// more queries than the 64-query version.
// =====================================================================
__global__ __launch_bounds__(256) void attn_tc_kernel(
    const __half* __restrict__ qkv, __half* __restrict__ out,
    const float* __restrict__ pa_, const float* __restrict__ pb_,
    const float* __restrict__ pc_)
{
    __shared__ __align__(16) char smQ[16384];      // 128 rows x 128B
    __shared__ __align__(16) char smK[2][8192];    // 64 rows x 128B
    __shared__ __align__(16) char smV[2][8192];

    const int tid = threadIdx.x, lane = tid & 31, warp = tid >> 5;
    const int bh = blockIdx.y, b = bh / HEADS, h = bh % HEADS;
    const int q0 = blockIdx.x * 128;
    const size_t tok0 = (size_t)b * SEQ;

    const uint32_t sQ = smem_u32(smQ);
    const uint32_t sK[2] = { smem_u32(smK[0]), smem_u32(smK[1]) };
    const uint32_t sV[2] = { smem_u32(smV[0]), smem_u32(smV[1]) };

    const float pa = *pa_, pb = *pb_, pc = *pc_;

    // Q loads: 128 rows x 8 chunks = 1024 chunks / 256 thr = 4 each
    const int qrow = tid >> 1;
    const int qc0  = (tid & 1) * 4;
    const __half* qsrc = qkv + (tok0 + q0 + qrow) * QKV_N + h * HEAD_D + qc0 * 8;
    #pragma unroll
    for (int j = 0; j < 4; j++)
        cp16(sQ + qrow * 128 + (((qc0 + j) ^ (qrow & 7)) << 4), qsrc + j * 8);

    // K/V loads: 64 rows x 8 chunks = 512 chunks / 256 thr = 2 each
    const int krow = tid >> 2;
    const int kc0  = (tid & 3) * 2;
    const __half* ksrc = qkv + (tok0 + krow) * QKV_N + DIM + h * HEAD_D + kc0 * 8;
    const __half* vsrc = ksrc + DIM;
    uint32_t kvoff[2];
    #pragma unroll
    for (int j = 0; j < 2; j++)
        kvoff[j] = krow * 128 + (((kc0 + j) ^ (krow & 7)) << 4);

    #pragma unroll
    for (int j = 0; j < 2; j++) {
        cp16(sK[0] + kvoff[j], ksrc + j * 8);
        cp16(sV[0] + kvoff[j], vsrc + j * 8);
    }
    CP_COMMIT();
    CP_WAIT0();
    __syncthreads();

    // ---- hoist Q fragments ----
    const int g = lane >> 3, r = lane & 7;
    const int rowadd = (g & 1) * 8 + r;
    const int cadd = g >> 1;
    uint32_t qreg[4][4];
    {
        const uint32_t qb = sQ + (warp * 16 + rowadd) * 128;
        #pragma unroll
        for (int s = 0; s < 4; s++)
            LDSM_X4(qreg[s], qb + (((2 * s + cadd) ^ r) << 4));
    }

    float acc_o[8][4] = {};
    float rsum[2] = {};
    const int NT = SEQ / 64;

    for (int t = 0; t < NT; t++) {
        if (t + 1 < NT) {
            const int nb = (t + 1) & 1;
            const size_t roff = (size_t)(t + 1) * 64 * QKV_N;
            #pragma unroll
            for (int j = 0; j < 2; j++) {
                cp16(sK[nb] + kvoff[j], ksrc + roff + j * 8);
                cp16(sV[nb] + kvoff[j], vsrc + roff + j * 8);
            }
            CP_COMMIT();
            CP_WAIT1();
        } else {
            CP_WAIT0();
        }
        __syncthreads();

        const uint32_t sk = sK[t & 1], sv = sV[t & 1];

        // ---- S = Q K^T ----
        float acc_s[8][4] = {};
        #pragma unroll
        for (int s = 0; s < 4; s++) {
            const uint32_t coff = ((2 * s + cadd) ^ r) << 4;
            #pragma unroll
            for (int p = 0; p < 4; p++) {
                uint32_t kb[4];
                LDSM_X4(kb, sk + (16 * p + rowadd) * 128 + coff);
                MMA_F16(acc_s[2 * p    ], qreg[s], kb[0], kb[2]);
                MMA_F16(acc_s[2 * p + 1], qreg[s], kb[1], kb[3]);
            }
        }

        // ---- poly activation + clamp + rowsum ----
        #pragma unroll
        for (int j = 0; j < 8; j++)
            #pragma unroll
            for (int e = 0; e < 4; e++) {
                const float sv_ = acc_s[j][e] * SCALE_ATT;
                float pv = fmaf(fmaf(pa, sv_, pb), sv_, pc);
                pv = fmaxf(pv, 1e-6f);
                acc_s[j][e] = pv;
                rsum[e >> 1] += pv;
            }

        // ---- O += P V ----
        #pragma unroll
        for (int s = 0; s < 4; s++) {
            uint32_t pf[4];
            pf[0] = pack_f16(acc_s[2 * s][0],     acc_s[2 * s][1]);
            pf[1] = pack_f16(acc_s[2 * s][2],     acc_s[2 * s][3]);
            pf[2] = pack_f16(acc_s[2 * s + 1][0], acc_s[2 * s + 1][1]);
            pf[3] = pack_f16(acc_s[2 * s + 1][2], acc_s[2 * s + 1][3]);
            const uint32_t vrb = sv + (16 * s + rowadd) * 128;
            #pragma unroll
            for (int p = 0; p < 4; p++) {
                uint32_t vb[4];
                LDSM_X4_T(vb, vrb + (((2 * p + cadd) ^ r) << 4));
                MMA_F16(acc_o[2 * p    ], pf, vb[0], vb[1]);
                MMA_F16(acc_o[2 * p + 1], pf, vb[2], vb[3]);
            }
        }
        __syncthreads();
    }

    #pragma unroll
    for (int off = 1; off < 4; off <<= 1) {
        rsum[0] += __shfl_xor_sync(0xffffffffu, rsum[0], off);
        rsum[1] += __shfl_xor_sync(0xffffffffu, rsum[1], off);
    }
    const float inv0 = 1.0f / (rsum[0] + 1e-8f);
    const float inv1 = 1.0f / (rsum[1] + 1e-8f);

    const int row0 = q0 + warp * 16 + (lane >> 2);
    const int dcol = h * HEAD_D + 2 * (lane & 3);
    #pragma unroll
    for (int j = 0; j < 8; j++) {
        const size_t i0 = (tok0 + row0) * DIM + dcol + 8 * j;
        const size_t i1 = (tok0 + row0 + 8) * DIM + dcol + 8 * j;
        store_h2(out + i0, acc_o[j][0] * inv0, acc_o[j][1] * inv0);
        store_h2(out + i1, acc_o[j][2] * inv1, acc_o[j][3] * inv1);
    }
}

// =====================================================================
// Launch
// =====================================================================
extern "C" void kernel_launch(void* const* d_in, const int* in_sizes, int n_in,
                              void* d_out, int out_size)
{
    const float* x      = (const float*)d_in[0];
    const float* ln1_g  = (const float*)d_in[1];
    const float* ln1_b  = (const float*)d_in[2];
    const float* ln2_g  = (const float*)d_in[3];
    const float* ln2_b  = (const float*)d_in[4];
    const float* qkv_w  = (const float*)d_in[5];
    const float* qkv_b  = (const float*)d_in[6];
    const float* proj_w = (const float*)d_in[7];
    const float* proj_b = (const float*)d_in[8];
    const float* fc1_w  = (const float*)d_in[9];
    const float* fc1_b  = (const float*)d_in[10];
    const float* fc2_w  = (const float*)d_in[11];
    const float* fc2_b  = (const float*)d_in[12];
    const float* attn_a = (const float*)d_in[13];
    const float* attn_b = (const float*)d_in[14];
    const float* attn_c = (const float*)d_in[15];
    const float* gelu_a = (const float*)d_in[16];
    const float* gelu_b = (const float*)d_in[17];
    const float* gelu_c = (const float*)d_in[18];

    float *x1;
    __half *qkvh, *hbuf, *atbuf, *ubuf, *wq, *wp, *w1, *w2;
    cudaGetSymbolAddress((void**)&x1,    g_x1);
    cudaGetSymbolAddress((void**)&qkvh,  g_qkv);
    cudaGetSymbolAddress((void**)&hbuf,  g_h);
    cudaGetSymbolAddress((void**)&atbuf, g_at);
    cudaGetSymbolAddress((void**)&ubuf,  g_u);
    cudaGetSymbolAddress((void**)&wq,    g_wqkv);
    cudaGetSymbolAddress((void**)&wp,    g_wprj);
    cudaGetSymbolAddress((void**)&w1,    g_wfc1);
    cudaGetSymbolAddress((void**)&w2,    g_wfc2);

    cudaFuncSetAttribute(tc_gemm<1>, cudaFuncAttributeMaxDynamicSharedMemorySize,
                         GEMM_SMEM_BYTES);
    cudaFuncSetAttribute(tc_gemm<2>, cudaFuncAttributeMaxDynamicSharedMemorySize,
                         GEMM_SMEM_BYTES);
    cudaFuncSetAttribute(tc_gemm<3>, cudaFuncAttributeMaxDynamicSharedMemorySize,
                         GEMM_SMEM_BYTES);

    // 0) transpose + fp16-convert weights -> [N,K]
    wconv_kernel<<<dim3(QKV_N / 32, DIM / 32),   dim3(32, 8)>>>(qkv_w,  wq, DIM, QKV_N);
    wconv_kernel<<<dim3(DIM / 32, DIM / 32),     dim3(32, 8)>>>(proj_w, wp, DIM, DIM);
    wconv_kernel<<<dim3(HIDDEN / 32, DIM / 32),  dim3(32, 8)>>>(fc1_w,  w1, DIM, HIDDEN);
    wconv_kernel<<<dim3(DIM / 32, HIDDEN / 32),  dim3(32, 8)>>>(fc2_w,  w2, HIDDEN, DIM);

    // 1) LN1 -> fp16
    ln_kernel<<<MTOK, 256>>>(x, ln1_g, ln1_b, hbuf);

    // 2) QKV GEMM -> fp16 q/k/v
    tc_gemm<3><<<dim3(QKV_N / 128, MTOK / 128), 256, GEMM_SMEM_BYTES>>>(
        hbuf, wq, qkv_b, nullptr, nullptr, qkvh,
        QKV_N, DIM, nullptr, nullptr, nullptr);

    // 3) tensor-core fused attention (128-query tiles) -> fp16
    attn_tc_kernel<<<dim3(SEQ / 128, BATCH * HEADS), 256>>>(
        qkvh, atbuf, attn_a, attn_b, attn_c);

    // 4) proj GEMM + residual(x) -> x1 (fp32)
    tc_gemm<1><<<dim3(DIM / 128, MTOK / 128), 256, GEMM_SMEM_BYTES>>>(
        atbuf, wp, proj_b, x, x1, nullptr,
        DIM, DIM, nullptr, nullptr, nullptr);

    // 5) LN2 -> fp16
    ln_kernel<<<MTOK, 256>>>(x1, ln2_g, ln2_b, hbuf);

    // 6) FC1 + poly-GELU -> u fp16
    tc_gemm<2><<<dim3(HIDDEN / 128, MTOK / 128), 256, GEMM_SMEM_BYTES>>>(
        hbuf, w1, fc1_b, nullptr, nullptr, ubuf,
        HIDDEN, DIM, gelu_a, gelu_b, gelu_c);

    // 7) FC2 + residual(x1) -> out (fp32)
    tc_gemm<1><<<dim3(DIM / 128, MTOK / 128), 256, GEMM_SMEM_BYTES>>>(
        ubuf, w2, fc2_b, x1, (float*)d_out, nullptr,
        DIM, HIDDEN, nullptr, nullptr, nullptr);
}

// round 12
// speedup vs baseline: 7.0049x; 1.0325x over previous
#include <cuda_runtime.h>
#include <cuda_fp16.h>
#include <cstdint>
#include <cstddef>

// ---------------- problem constants ----------------
#define BATCH   4
#define SEQ     2048
#define DIM     768
#define HEADS   12
#define HEAD_D  64
#define HIDDEN  3072
#define MTOK    (BATCH * SEQ)        // 8192 tokens
#define QKV_N   (3 * DIM)            // 2304
#define SCALE_ATT 0.125f             // 64^-0.5
#define LN_EPS  1e-5f

// ---------------- scratch (alloc-free: __device__ globals) ----------------
__device__ float g_x1 [(size_t)MTOK * DIM];       // residual after attn branch

__device__ __align__(16) __half g_qkv[(size_t)MTOK * QKV_N]; // q/k/v fp16
__device__ __align__(16) __half g_h  [(size_t)MTOK * DIM];   // LN out fp16
__device__ __align__(16) __half g_at [(size_t)MTOK * DIM];   // attention out fp16
__device__ __align__(16) __half g_u  [(size_t)MTOK * HIDDEN];// FC1/gelu out fp16

// transposed weights: stored [N, K] fp16
__device__ __align__(16) __half g_wqkv[(size_t)QKV_N * DIM];
__device__ __align__(16) __half g_wprj[(size_t)DIM * DIM];
__device__ __align__(16) __half g_wfc1[(size_t)HIDDEN * DIM];
__device__ __align__(16) __half g_wfc2[(size_t)DIM * HIDDEN];

// =====================================================================
// PTX helpers (sm_80-class: mma.sync / ldmatrix / cp.async — OK on sm_103)
// =====================================================================
__device__ __forceinline__ uint32_t smem_u32(const void* p) {
    uint32_t a;
    asm("{ .reg .u64 t; cvta.to.shared.u64 t, %1; cvt.u32.u64 %0, t; }"
        : "=r"(a) : "l"(p));
    return a;
}

#define LDSM_X4(r, addr)                                                        \
    asm volatile("ldmatrix.sync.aligned.m8n8.x4.shared.b16 {%0,%1,%2,%3}, [%4];"\
        : "=r"((r)[0]), "=r"((r)[1]), "=r"((r)[2]), "=r"((r)[3]) : "r"(addr))

#define LDSM_X4_T(r, addr)                                                      \
    asm volatile("ldmatrix.sync.aligned.m8n8.x4.trans.shared.b16 {%0,%1,%2,%3}, [%4];"\
        : "=r"((r)[0]), "=r"((r)[1]), "=r"((r)[2]), "=r"((r)[3]) : "r"(addr))

#define MMA_F16(d, a, b0, b1)                                                   \
    asm volatile("mma.sync.aligned.m16n8k16.row.col.f32.f16.f16.f32 "           \
        "{%0,%1,%2,%3}, {%4,%5,%6,%7}, {%8,%9}, {%0,%1,%2,%3};"                 \
        : "+f"((d)[0]), "+f"((d)[1]), "+f"((d)[2]), "+f"((d)[3])                \
        : "r"((a)[0]), "r"((a)[1]), "r"((a)[2]), "r"((a)[3]), "r"(b0), "r"(b1))

__device__ __forceinline__ void cp16(uint32_t dst, const void* src) {
    asm volatile("cp.async.cg.shared.global [%0], [%1], 16;"
                 :: "r"(dst), "l"(src) : "memory");
}
#define CP_COMMIT() asm volatile("cp.async.commit_group;" ::: "memory")
#define CP_WAIT1()  asm volatile("cp.async.wait_group 1;" ::: "memory")
#define CP_WAIT0()  asm volatile("cp.async.wait_group 0;" ::: "memory")

__device__ __forceinline__ uint32_t pack_f16(float x, float y) {
    __half2 t = __halves2half2(__float2half_rn(x), __float2half_rn(y));
    return *(uint32_t*)&t;
}

__device__ __forceinline__ void store_h2(__half* p, float a, float b) {
    __half2 t = __halves2half2(__float2half_rn(a), __float2half_rn(b));
    *(__half2*)p = t;
}

// =====================================================================
// Weight convert: W[K,N] fp32 -> Wt[N,K] fp16 (tiled transpose)
// =====================================================================
__global__ __launch_bounds__(256) void wconv_kernel(
    const float* __restrict__ W, __half* __restrict__ T, int K, int N)
{
    __shared__ float t[32][33];
    const int n0 = blockIdx.x * 32, k0 = blockIdx.y * 32;
    const int tx = threadIdx.x, ty = threadIdx.y;
    #pragma unroll
    for (int j = 0; j < 4; j++)
        t[ty + 8 * j][tx] = W[(size_t)(k0 + ty + 8 * j) * N + n0 + tx];
    __syncthreads();
    #pragma unroll
    for (int j = 0; j < 4; j++)
        T[(size_t)(n0 + ty + 8 * j) * K + k0 + tx] = __float2half_rn(t[tx][ty + 8 * j]);
}

// =====================================================================
// LayerNorm -> fp16
// =====================================================================
__global__ __launch_bounds__(256) void ln_kernel(
    const float* __restrict__ x, const float* __restrict__ gamma,
    const float* __restrict__ beta, __half* __restrict__ out)
{
    const int row = blockIdx.x;
    const int tid = threadIdx.x;
    const float* xr = x + (size_t)row * DIM;

    float v0 = xr[tid], v1 = xr[tid + 256], v2 = xr[tid + 512];
    float s = v0 + v1 + v2;
    float q = v0 * v0 + v1 * v1 + v2 * v2;

    __shared__ float ws[8], wq[8];
    #pragma unroll
    for (int o = 16; o; o >>= 1) {
        s += __shfl_xor_sync(0xffffffffu, s, o);
        q += __shfl_xor_sync(0xffffffffu, q, o);
    }
    if ((tid & 31) == 0) { ws[tid >> 5] = s; wq[tid >> 5] = q; }
    __syncthreads();
    float ts = 0.f, tq = 0.f;
    #pragma unroll
    for (int i = 0; i < 8; i++) { ts += ws[i]; tq += wq[i]; }

    const float mean = ts * (1.0f / DIM);
    const float var  = tq * (1.0f / DIM) - mean * mean;
    const float rstd = rsqrtf(var + LN_EPS);

    const size_t rb = (size_t)row * DIM;
    #pragma unroll
    for (int j = 0; j < 3; j++) {
        const int c = tid + j * 256;
        const float v = (j == 0 ? v0 : (j == 1 ? v1 : v2));
        out[rb + c] = __float2half_rn((v - mean) * rstd * gamma[c] + beta[c]);
    }
}

// =====================================================================
// fp16 tensor-core GEMM via mma.sync.m16n8k16:
//   C[M,N] = A[M,K] @ B[N,K]^T  (fp32 accumulate)
// Block tile 128 x (32*NJ) x 64, 8 warps (4x2), 3-stage cp.async pipeline.
//   NJ=4 -> 128x128 tile (stage 32KB, 96KB smem)
//   NJ=2 -> 128x64  tile (stage 24KB, 72KB smem)  [wave-quantization fix
//           for N=768 GEMMs: proj/FC2 get 768 CTAs vs 384]
// MODE 1: out = D + bias + res (fp32)
// MODE 2: u = D + bias; poly-GELU(u) -> fp16
// MODE 3: out = D + bias -> fp16 (attention q/k/v)
// =====================================================================
#define GEMM_SMEM(NJ) (3 * (16384 + 4096 * (NJ)))

template<int MODE, int NJ>
__global__ __launch_bounds__(256) void tc_gemm(
    const __half* __restrict__ A, const __half* __restrict__ B,
    const float* __restrict__ bias, const float* __restrict__ res,
    float* __restrict__ outf, __half* __restrict__ out16,
    int N, int K,
    const float* __restrict__ pga, const float* __restrict__ pgb,
    const float* __restrict__ pgc)
{
    constexpr int BN = 32 * NJ;                       // N tile
    constexpr int STAGE = 16384 + 4096 * NJ;          // bytes per stage
    extern __shared__ char sm[];
    const uint32_t sbase = smem_u32(sm);
    const int tid = threadIdx.x;
    const int lane = tid & 31, wid = tid >> 5;
    const int wm = wid & 3, wn = wid >> 2;            // 4 x 2 warp grid
    const int m0 = blockIdx.y * 128, n0 = blockIdx.x * BN;
    const int nt = K >> 6;                            // K/64 stages

    // A loads: 128 rows x 8 chunks / 256 thr = 4 per thread
    const __half* agsrc[4]; uint32_t asoff[4];
    #pragma unroll
    for (int i = 0; i < 4; i++) {
        const int id = tid + i * 256;
        const int row = id >> 3, c = id & 7;
        agsrc[i] = A + (size_t)(m0 + row) * K + c * 8;
        asoff[i] = row * 128 + ((c ^ (row & 7)) << 4);
    }
    // B loads: BN rows x 8 chunks / 256 thr = NJ per thread
    const __half* bgsrc[NJ]; uint32_t bsoff[NJ];
    #pragma unroll
    for (int i = 0; i < NJ; i++) {
        const int id = tid + i * 256;
        const int row = id >> 3, c = id & 7;
        bgsrc[i] = B + (size_t)(n0 + row) * K + c * 8;
        bsoff[i] = 16384 + row * 128 + ((c ^ (row & 7)) << 4);
    }

    #define LOAD_STAGE(kt, slot) do {                                          \
        const uint32_t sb_ = sbase + (uint32_t)(slot) * STAGE;                  \
        const size_t ko_ = (size_t)(kt) * 64;                                   \
        _Pragma("unroll")                                                       \
        for (int i_ = 0; i_ < 4; i_++)                                          \
            cp16(sb_ + asoff[i_], agsrc[i_] + ko_);                             \
        _Pragma("unroll")                                                       \
        for (int i_ = 0; i_ < NJ; i_++)                                         \
            cp16(sb_ + bsoff[i_], bgsrc[i_] + ko_);                             \
    } while (0)

    LOAD_STAGE(0, 0); CP_COMMIT();
    LOAD_STAGE(1, 1); CP_COMMIT();

    uint32_t a_off[2][4];
    #pragma unroll
    for (int mi = 0; mi < 2; mi++) {
        const int row = wm * 32 + mi * 16 + (lane & 15);
        const int kbit = (lane >> 4) & 1;
        #pragma unroll
        for (int ks = 0; ks < 4; ks++) {
            const int chi = ks * 2 + kbit;
            a_off[mi][ks] = row * 128 + ((chi ^ (row & 7)) << 4);
        }
    }
    uint32_t b_off[NJ][4];
    #pragma unroll
    for (int nj = 0; nj < NJ; nj++) {
        const int nrow = wn * (16 * NJ) + nj * 16 + (lane & 7) + ((lane >> 4) << 3);
        const int kbit = (lane >> 3) & 1;
        #pragma unroll
        for (int ks = 0; ks < 4; ks++) {
            const int chi = ks * 2 + kbit;
            b_off[nj][ks] = 16384 + nrow * 128 + ((chi ^ (nrow & 7)) << 4);
        }
    }

    float acc[2][2 * NJ][4] = {};

    for (int kt = 0; kt < nt; kt++) {
        CP_WAIT1();
        __syncthreads();
        const uint32_t sb = sbase + (uint32_t)(kt % 3) * STAGE;

        #pragma unroll
        for (int ks = 0; ks < 4; ks++) {
            uint32_t ar[2][4];
            LDSM_X4(ar[0], sb + a_off[0][ks]);
            LDSM_X4(ar[1], sb + a_off[1][ks]);
            #pragma unroll
            for (int nj = 0; nj < NJ; nj++) {
                uint32_t br[4];
                LDSM_X4(br, sb + b_off[nj][ks]);
                #pragma unroll
                for (int mi = 0; mi < 2; mi++) {
                    MMA_F16(acc[mi][nj * 2    ], ar[mi], br[0], br[1]);
                    MMA_F16(acc[mi][nj * 2 + 1], ar[mi], br[2], br[3]);
                }
            }
        }
        __syncthreads();
        if (kt + 2 < nt) LOAD_STAGE(kt + 2, (kt + 2) % 3);
        CP_COMMIT();
    }

    float gaV = 0.f, gbV = 0.f, gcV = 0.f;
    if (MODE == 2) { gaV = *pga; gbV = *pgb; gcV = *pgc; }

    #pragma unroll
    for (int mi = 0; mi < 2; mi++) {
        const int ma = m0 + wm * 32 + mi * 16 + (lane >> 2);
        #pragma unroll
        for (int t = 0; t < 2 * NJ; t++) {
            const int n = n0 + wn * (16 * NJ) + t * 8 + ((lane & 3) << 1);
            const float b0 = bias[n], b1 = bias[n + 1];
            #pragma unroll
            for (int half = 0; half < 2; half++) {
                const int m = ma + half * 8;
                float v0 = acc[mi][t][half * 2]     + b0;
                float v1 = acc[mi][t][half * 2 + 1] + b1;
                const size_t idx = (size_t)m * N + n;
                if (MODE == 2) {
                    v0 = fmaf(fmaf(gaV, v0, gbV), v0, gcV);
                    v1 = fmaf(fmaf(gaV, v1, gbV), v1, gcV);
                    store_h2(out16 + idx, v0, v1);
                } else if (MODE == 3) {
                    store_h2(out16 + idx, v0, v1);
                } else {
                    const float2 rv = *(const float2*)(res + idx);
                    *(float2*)(outf + idx) = make_float2(v0 + rv.x, v1 + rv.y);
                }
            }
        }
    }
    #undef LOAD_STAGE
}

// =====================================================================
// Tensor-core fused attention (flash-style, fp16 mma, fp32 accum):
//   S = QK^T*scale; P = max(a*S^2+b*S+c, 1e-6); O = (P V) / rowsum(P)
// Block: 256 threads (8 warps x 16 queries = 128-query tile),
// 64-key tiles double-buffered via cp.async.
// =====================================================================
__global__ __launch_bounds__(256) void attn_tc_kernel(
    const __half* __restrict__ qkv, __half* __restrict__ out,
    const float* __restrict__ pa_, const float* __restrict__ pb_,
    const float* __restrict__ pc_)
{
    __shared__ __align__(16) char smQ[16384];      // 128 rows x 128B
    __shared__ __align__(16) char smK[2][8192];    // 64 rows x 128B
    __shared__ __align__(16) char smV[2][8192];

    const int tid = threadIdx.x, lane = tid & 31, warp = tid >> 5;
    const int bh = blockIdx.y, b = bh / HEADS, h = bh % HEADS;
    const int q0 = blockIdx.x * 128;
    const size_t tok0 = (size_t)b * SEQ;

    const uint32_t sQ = smem_u32(smQ);
    const uint32_t sK[2] = { smem_u32(smK[0]), smem_u32(smK[1]) };
    const uint32_t sV[2] = { smem_u32(smV[0]), smem_u32(smV[1]) };

    const float pa = *pa_, pb = *pb_, pc = *pc_;

    const int qrow = tid >> 1;
    const int qc0  = (tid & 1) * 4;
    const __half* qsrc = qkv + (tok0 + q0 + qrow) * QKV_N + h * HEAD_D + qc0 * 8;
    #pragma unroll
    for (int j = 0; j < 4; j++)
        cp16(sQ + qrow * 128 + (((qc0 + j) ^ (qrow & 7)) << 4), qsrc + j * 8);

    const int krow = tid >> 2;
    const int kc0  = (tid & 3) * 2;
    const __half* ksrc = qkv + (tok0 + krow) * QKV_N + DIM + h * HEAD_D + kc0 * 8;
    const __half* vsrc = ksrc + DIM;
    uint32_t kvoff[2];
    #pragma unroll
    for (int j = 0; j < 2; j++)
        kvoff[j] = krow * 128 + (((kc0 + j) ^ (krow & 7)) << 4);

    #pragma unroll
    for (int j = 0; j < 2; j++) {
        cp16(sK[0] + kvoff[j], ksrc + j * 8);
        cp16(sV[0] + kvoff[j], vsrc + j * 8);
    }
    CP_COMMIT();
    CP_WAIT0();
    __syncthreads();

    const int g = lane >> 3, r = lane & 7;
    const int rowadd = (g & 1) * 8 + r;
    const int cadd = g >> 1;
    uint32_t qreg[4][4];
    {
        const uint32_t qb = sQ + (warp * 16 + rowadd) * 128;
        #pragma unroll
        for (int s = 0; s < 4; s++)
            LDSM_X4(qreg[s], qb + (((2 * s + cadd) ^ r) << 4));
    }

    float acc_o[8][4] = {};
    float rsum[2] = {};
    const int NT = SEQ / 64;

    for (int t = 0; t < NT; t++) {
        if (t + 1 < NT) {
            const int nb = (t + 1) & 1;
            const size_t roff = (size_t)(t + 1) * 64 * QKV_N;
            #pragma unroll
            for (int j = 0; j < 2; j++) {
                cp16(sK[nb] + kvoff[j], ksrc + roff + j * 8);
                cp16(sV[nb] + kvoff[j], vsrc + roff + j * 8);
            }
            CP_COMMIT();
            CP_WAIT1();
        } else {
            CP_WAIT0();
        }
        __syncthreads();

        const uint32_t sk = sK[t & 1], sv = sV[t & 1];

        float acc_s[8][4] = {};
        #pragma unroll
        for (int s = 0; s < 4; s++) {
            const uint32_t coff = ((2 * s + cadd) ^ r) << 4;
            #pragma unroll
            for (int p = 0; p < 4; p++) {
                uint32_t kb[4];
                LDSM_X4(kb, sk + (16 * p + rowadd) * 128 + coff);
                MMA_F16(acc_s[2 * p    ], qreg[s], kb[0], kb[2]);
                MMA_F16(acc_s[2 * p + 1], qreg[s], kb[1], kb[3]);
            }
        }

        #pragma unroll
        for (int j = 0; j < 8; j++)
            #pragma unroll
            for (int e = 0; e < 4; e++) {
                const float sv_ = acc_s[j][e] * SCALE_ATT;
                float pv = fmaf(fmaf(pa, sv_, pb), sv_, pc);
                pv = fmaxf(pv, 1e-6f);
                acc_s[j][e] = pv;
                rsum[e >> 1] += pv;
            }

        #pragma unroll
        for (int s = 0; s < 4; s++) {
            uint32_t pf[4];
            pf[0] = pack_f16(acc_s[2 * s][0],     acc_s[2 * s][1]);
            pf[1] = pack_f16(acc_s[2 * s][2],     acc_s[2 * s][3]);
            pf[2] = pack_f16(acc_s[2 * s + 1][0], acc_s[2 * s + 1][1]);
            pf[3] = pack_f16(acc_s[2 * s + 1][2], acc_s[2 * s + 1][3]);
            const uint32_t vrb = sv + (16 * s + rowadd) * 128;
            #pragma unroll
            for (int p = 0; p < 4; p++) {
                uint32_t vb[4];
                LDSM_X4_T(vb, vrb + (((2 * p + cadd) ^ r) << 4));
                MMA_F16(acc_o[2 * p    ], pf, vb[0], vb[1]);
                MMA_F16(acc_o[2 * p + 1], pf, vb[2], vb[3]);
            }
        }
        __syncthreads();
    }

    #pragma unroll
    for (int off = 1; off < 4; off <<= 1) {
        rsum[0] += __shfl_xor_sync(0xffffffffu, rsum[0], off);
        rsum[1] += __shfl_xor_sync(0xffffffffu, rsum[1], off);
    }
    const float inv0 = 1.0f / (rsum[0] + 1e-8f);
    const float inv1 = 1.0f / (rsum[1] + 1e-8f);

    const int row0 = q0 + warp * 16 + (lane >> 2);
    const int dcol = h * HEAD_D + 2 * (lane & 3);
    #pragma unroll
    for (int j = 0; j < 8; j++) {
        const size_t i0 = (tok0 + row0) * DIM + dcol + 8 * j;
        const size_t i1 = (tok0 + row0 + 8) * DIM + dcol + 8 * j;
        store_h2(out + i0, acc_o[j][0] * inv0, acc_o[j][1] * inv0);
        store_h2(out + i1, acc_o[j][2] * inv1, acc_o[j][3] * inv1);
    }
}

// =====================================================================
// Launch
// =====================================================================
extern "C" void kernel_launch(void* const* d_in, const int* in_sizes, int n_in,
                              void* d_out, int out_size)
{
    const float* x      = (const float*)d_in[0];
    const float* ln1_g  = (const float*)d_in[1];
    const float* ln1_b  = (const float*)d_in[2];
    const float* ln2_g  = (const float*)d_in[3];
    const float* ln2_b  = (const float*)d_in[4];
    const float* qkv_w  = (const float*)d_in[5];
    const float* qkv_b  = (const float*)d_in[6];
    const float* proj_w = (const float*)d_in[7];
    const float* proj_b = (const float*)d_in[8];
    const float* fc1_w  = (const float*)d_in[9];
    const float* fc1_b  = (const float*)d_in[10];
    const float* fc2_w  = (const float*)d_in[11];
    const float* fc2_b  = (const float*)d_in[12];
    const float* attn_a = (const float*)d_in[13];
    const float* attn_b = (const float*)d_in[14];
    const float* attn_c = (const float*)d_in[15];
    const float* gelu_a = (const float*)d_in[16];
    const float* gelu_b = (const float*)d_in[17];
    const float* gelu_c = (const float*)d_in[18];

    float *x1;
    __half *qkvh, *hbuf, *atbuf, *ubuf, *wq, *wp, *w1, *w2;
    cudaGetSymbolAddress((void**)&x1,    g_x1);
    cudaGetSymbolAddress((void**)&qkvh,  g_qkv);
    cudaGetSymbolAddress((void**)&hbuf,  g_h);
    cudaGetSymbolAddress((void**)&atbuf, g_at);
    cudaGetSymbolAddress((void**)&ubuf,  g_u);
    cudaGetSymbolAddress((void**)&wq,    g_wqkv);
    cudaGetSymbolAddress((void**)&wp,    g_wprj);
    cudaGetSymbolAddress((void**)&w1,    g_wfc1);
    cudaGetSymbolAddress((void**)&w2,    g_wfc2);

    cudaFuncSetAttribute(tc_gemm<1, 2>, cudaFuncAttributeMaxDynamicSharedMemorySize,
                         GEMM_SMEM(2));
    cudaFuncSetAttribute(tc_gemm<2, 4>, cudaFuncAttributeMaxDynamicSharedMemorySize,
                         GEMM_SMEM(4));
    cudaFuncSetAttribute(tc_gemm<3, 4>, cudaFuncAttributeMaxDynamicSharedMemorySize,
                         GEMM_SMEM(4));

    // 0) transpose + fp16-convert weights -> [N,K]
    wconv_kernel<<<dim3(QKV_N / 32, DIM / 32),   dim3(32, 8)>>>(qkv_w,  wq, DIM, QKV_N);
    wconv_kernel<<<dim3(DIM / 32, DIM / 32),     dim3(32, 8)>>>(proj_w, wp, DIM, DIM);
    wconv_kernel<<<dim3(HIDDEN / 32, DIM / 32),  dim3(32, 8)>>>(fc1_w,  w1, DIM, HIDDEN);
    wconv_kernel<<<dim3(DIM / 32, HIDDEN / 32),  dim3(32, 8)>>>(fc2_w,  w2, HIDDEN, DIM);

    // 1) LN1 -> fp16
    ln_kernel<<<MTOK, 256>>>(x, ln1_g, ln1_b, hbuf);

    // 2) QKV GEMM -> fp16 q/k/v   (128x128 tiles, 3.9 waves)
    tc_gemm<3, 4><<<dim3(QKV_N / 128, MTOK / 128), 256, GEMM_SMEM(4)>>>(
        hbuf, wq, qkv_b, nullptr, nullptr, qkvh,
        QKV_N, DIM, nullptr, nullptr, nullptr);

    // 3) tensor-core fused attention (128-query tiles) -> fp16
    attn_tc_kernel<<<dim3(SEQ / 128, BATCH * HEADS), 256>>>(
        qkvh, atbuf, attn_a, attn_b, attn_c);

    // 4) proj GEMM + residual(x) -> x1 (fp32)   (128x64 tiles: 768 CTAs)
    tc_gemm<1, 2><<<dim3(DIM / 64, MTOK / 128), 256, GEMM_SMEM(2)>>>(
        atbuf, wp, proj_b, x, x1, nullptr,
        DIM, DIM, nullptr, nullptr, nullptr);

    // 5) LN2 -> fp16
    ln_kernel<<<MTOK, 256>>>(x1, ln2_g, ln2_b, hbuf);

    // 6) FC1 + poly-GELU -> u fp16   (128x128 tiles, 5.2 waves)
    tc_gemm<2, 4><<<dim3(HIDDEN / 128, MTOK / 128), 256, GEMM_SMEM(4)>>>(
        hbuf, w1, fc1_b, nullptr, nullptr, ubuf,
        HIDDEN, DIM, gelu_a, gelu_b, gelu_c);

    // 7) FC2 + residual(x1) -> out (fp32)   (128x64 tiles: 768 CTAs)
    tc_gemm<1, 2><<<dim3(DIM / 64, MTOK / 128), 256, GEMM_SMEM(2)>>>(
        ubuf, w2, fc2_b, x1, (float*)d_out, nullptr,
        DIM, HIDDEN, nullptr, nullptr, nullptr);
}

// round 13
// speedup vs baseline: 7.6171x; 1.0874x over previous
#include <cuda_runtime.h>
#include <cuda_fp16.h>
#include <cstdint>
#include <cstddef>

// ---------------- problem constants ----------------
#define BATCH   4
#define SEQ     2048
#define DIM     768
#define HEADS   12
#define HEAD_D  64
#define HIDDEN  3072
#define MTOK    (BATCH * SEQ)        // 8192 tokens
#define QKV_N   (3 * DIM)            // 2304
#define SCALE_ATT 0.125f             // 64^-0.5
#define LN_EPS  1e-5f

// ---------------- scratch (alloc-free: __device__ globals) ----------------
__device__ float g_x1 [(size_t)MTOK * DIM];       // residual after attn branch

__device__ __align__(16) __half g_qkv[(size_t)MTOK * QKV_N]; // q/k/v fp16
__device__ __align__(16) __half g_h  [(size_t)MTOK * DIM];   // LN out fp16
__device__ __align__(16) __half g_at [(size_t)MTOK * DIM];   // attention out fp16
__device__ __align__(16) __half g_u  [(size_t)MTOK * HIDDEN];// FC1/gelu out fp16

// transposed weights: stored [N, K] fp16
__device__ __align__(16) __half g_wqkv[(size_t)QKV_N * DIM];
__device__ __align__(16) __half g_wprj[(size_t)DIM * DIM];
__device__ __align__(16) __half g_wfc1[(size_t)HIDDEN * DIM];
__device__ __align__(16) __half g_wfc2[(size_t)DIM * HIDDEN];

// =====================================================================
// PTX helpers (sm_80-class: mma.sync / ldmatrix / cp.async — OK on sm_103)
// =====================================================================
__device__ __forceinline__ uint32_t smem_u32(const void* p) {
    uint32_t a;
    asm("{ .reg .u64 t; cvta.to.shared.u64 t, %1; cvt.u32.u64 %0, t; }"
        : "=r"(a) : "l"(p));
    return a;
}

#define LDSM_X4(r, addr)                                                        \
    asm volatile("ldmatrix.sync.aligned.m8n8.x4.shared.b16 {%0,%1,%2,%3}, [%4];"\
        : "=r"((r)[0]), "=r"((r)[1]), "=r"((r)[2]), "=r"((r)[3]) : "r"(addr))

#define LDSM_X4_T(r, addr)                                                      \
    asm volatile("ldmatrix.sync.aligned.m8n8.x4.trans.shared.b16 {%0,%1,%2,%3}, [%4];"\
        : "=r"((r)[0]), "=r"((r)[1]), "=r"((r)[2]), "=r"((r)[3]) : "r"(addr))

#define MMA_F16(d, a, b0, b1)                                                   \
    asm volatile("mma.sync.aligned.m16n8k16.row.col.f32.f16.f16.f32 "           \
        "{%0,%1,%2,%3}, {%4,%5,%6,%7}, {%8,%9}, {%0,%1,%2,%3};"                 \
        : "+f"((d)[0]), "+f"((d)[1]), "+f"((d)[2]), "+f"((d)[3])                \
        : "r"((a)[0]), "r"((a)[1]), "r"((a)[2]), "r"((a)[3]), "r"(b0), "r"(b1))

__device__ __forceinline__ void cp16(uint32_t dst, const void* src) {
    asm volatile("cp.async.cg.shared.global [%0], [%1], 16;"
                 :: "r"(dst), "l"(src) : "memory");
}
#define CP_COMMIT() asm volatile("cp.async.commit_group;" ::: "memory")
#define CP_WAIT1()  asm volatile("cp.async.wait_group 1;" ::: "memory")
#define CP_WAIT0()  asm volatile("cp.async.wait_group 0;" ::: "memory")

__device__ __forceinline__ uint32_t pack_f16(float x, float y) {
    __half2 t = __halves2half2(__float2half_rn(x), __float2half_rn(y));
    return *(uint32_t*)&t;
}

__device__ __forceinline__ void store_h2(__half* p, float a, float b) {
    __half2 t = __halves2half2(__float2half_rn(a), __float2half_rn(b));
    *(__half2*)p = t;
}

// =====================================================================
// Weight convert: W[K,N] fp32 -> Wt[N,K] fp16 (tiled transpose)
// =====================================================================
__global__ __launch_bounds__(256) void wconv_kernel(
    const float* __restrict__ W, __half* __restrict__ T, int K, int N)
{
    __shared__ float t[32][33];
    const int n0 = blockIdx.x * 32, k0 = blockIdx.y * 32;
    const int tx = threadIdx.x, ty = threadIdx.y;
    #pragma unroll
    for (int j = 0; j < 4; j++)
        t[ty + 8 * j][tx] = W[(size_t)(k0 + ty + 8 * j) * N + n0 + tx];
    __syncthreads();
    #pragma unroll
    for (int j = 0; j < 4; j++)
        T[(size_t)(n0 + ty + 8 * j) * K + k0 + tx] = __float2half_rn(t[tx][ty + 8 * j]);
}

// =====================================================================
// LayerNorm -> fp16
// =====================================================================
__global__ __launch_bounds__(256) void ln_kernel(
    const float* __restrict__ x, const float* __restrict__ gamma,
    const float* __restrict__ beta, __half* __restrict__ out)
{
    const int row = blockIdx.x;
    const int tid = threadIdx.x;
    const float* xr = x + (size_t)row * DIM;

    float v0 = xr[tid], v1 = xr[tid + 256], v2 = xr[tid + 512];
    float s = v0 + v1 + v2;
    float q = v0 * v0 + v1 * v1 + v2 * v2;

    __shared__ float ws[8], wq[8];
    #pragma unroll
    for (int o = 16; o; o >>= 1) {
        s += __shfl_xor_sync(0xffffffffu, s, o);
        q += __shfl_xor_sync(0xffffffffu, q, o);
    }
    if ((tid & 31) == 0) { ws[tid >> 5] = s; wq[tid >> 5] = q; }
    __syncthreads();
    float ts = 0.f, tq = 0.f;
    #pragma unroll
    for (int i = 0; i < 8; i++) { ts += ws[i]; tq += wq[i]; }

    const float mean = ts * (1.0f / DIM);
    const float var  = tq * (1.0f / DIM) - mean * mean;
    const float rstd = rsqrtf(var + LN_EPS);

    const size_t rb = (size_t)row * DIM;
    #pragma unroll
    for (int j = 0; j < 3; j++) {
        const int c = tid + j * 256;
        const float v = (j == 0 ? v0 : (j == 1 ? v1 : v2));
        out[rb + c] = __float2half_rn((v - mean) * rstd * gamma[c] + beta[c]);
    }
}

// =====================================================================
// fp16 tensor-core GEMM via mma.sync.m16n8k16:
//   C[M,N] = A[M,K] @ B[N,K]^T  (fp32 accumulate)
// Block tile 128 x (32*NJ) x 64, 8 warps (4x2), 3-stage cp.async pipeline.
//   NJ=4 -> 128x128 tile (stage 32KB, 96KB smem)
//   NJ=2 -> 128x64  tile (stage 24KB, 72KB smem)
// __launch_bounds__(256, 2): cap regs at 128 -> guaranteed 2 CTAs/SM.
// MODE 1: out = D + bias + res (fp32)
// MODE 2: u = D + bias; poly-GELU(u) -> fp16
// MODE 3: out = D + bias -> fp16 (attention q/k/v)
// =====================================================================
#define GEMM_SMEM(NJ) (3 * (16384 + 4096 * (NJ)))

template<int MODE, int NJ>
__global__ __launch_bounds__(256, 2) void tc_gemm(
    const __half* __restrict__ A, const __half* __restrict__ B,
    const float* __restrict__ bias, const float* __restrict__ res,
    float* __restrict__ outf, __half* __restrict__ out16,
    int N, int K,
    const float* __restrict__ pga, const float* __restrict__ pgb,
    const float* __restrict__ pgc)
{
    constexpr int BN = 32 * NJ;                       // N tile
    constexpr int STAGE = 16384 + 4096 * NJ;          // bytes per stage
    extern __shared__ char sm[];
    const uint32_t sbase = smem_u32(sm);
    const int tid = threadIdx.x;
    const int lane = tid & 31, wid = tid >> 5;
    const int wm = wid & 3, wn = wid >> 2;            // 4 x 2 warp grid
    const int m0 = blockIdx.y * 128, n0 = blockIdx.x * BN;
    const int nt = K >> 6;                            // K/64 stages

    // A loads: 128 rows x 8 chunks / 256 thr = 4 per thread
    const __half* agsrc[4]; uint32_t asoff[4];
    #pragma unroll
    for (int i = 0; i < 4; i++) {
        const int id = tid + i * 256;
        const int row = id >> 3, c = id & 7;
        agsrc[i] = A + (size_t)(m0 + row) * K + c * 8;
        asoff[i] = row * 128 + ((c ^ (row & 7)) << 4);
    }
    // B loads: BN rows x 8 chunks / 256 thr = NJ per thread
    const __half* bgsrc[NJ]; uint32_t bsoff[NJ];
    #pragma unroll
    for (int i = 0; i < NJ; i++) {
        const int id = tid + i * 256;
        const int row = id >> 3, c = id & 7;
        bgsrc[i] = B + (size_t)(n0 + row) * K + c * 8;
        bsoff[i] = 16384 + row * 128 + ((c ^ (row & 7)) << 4);
    }

    #define LOAD_STAGE(kt, slot) do {                                          \
        const uint32_t sb_ = sbase + (uint32_t)(slot) * STAGE;                  \
        const size_t ko_ = (size_t)(kt) * 64;                                   \
        _Pragma("unroll")                                                       \
        for (int i_ = 0; i_ < 4; i_++)                                          \
            cp16(sb_ + asoff[i_], agsrc[i_] + ko_);                             \
        _Pragma("unroll")                                                       \
        for (int i_ = 0; i_ < NJ; i_++)                                         \
            cp16(sb_ + bsoff[i_], bgsrc[i_] + ko_);                             \
    } while (0)

    LOAD_STAGE(0, 0); CP_COMMIT();
    LOAD_STAGE(1, 1); CP_COMMIT();

    uint32_t a_off[2][4];
    #pragma unroll
    for (int mi = 0; mi < 2; mi++) {
        const int row = wm * 32 + mi * 16 + (lane & 15);
        const int kbit = (lane >> 4) & 1;
        #pragma unroll
        for (int ks = 0; ks < 4; ks++) {
            const int chi = ks * 2 + kbit;
            a_off[mi][ks] = row * 128 + ((chi ^ (row & 7)) << 4);
        }
    }
    uint32_t b_off[NJ][4];
    #pragma unroll
    for (int nj = 0; nj < NJ; nj++) {
        const int nrow = wn * (16 * NJ) + nj * 16 + (lane & 7) + ((lane >> 4) << 3);
        const int kbit = (lane >> 3) & 1;
        #pragma unroll
        for (int ks = 0; ks < 4; ks++) {
            const int chi = ks * 2 + kbit;
            b_off[nj][ks] = 16384 + nrow * 128 + ((chi ^ (nrow & 7)) << 4);
        }
    }

    float acc[2][2 * NJ][4] = {};

    for (int kt = 0; kt < nt; kt++) {
        CP_WAIT1();
        __syncthreads();
        const uint32_t sb = sbase + (uint32_t)(kt % 3) * STAGE;

        #pragma unroll
        for (int ks = 0; ks < 4; ks++) {
            uint32_t ar[2][4];
            LDSM_X4(ar[0], sb + a_off[0][ks]);
            LDSM_X4(ar[1], sb + a_off[1][ks]);
            #pragma unroll
            for (int nj = 0; nj < NJ; nj++) {
                uint32_t br[4];
                LDSM_X4(br, sb + b_off[nj][ks]);
                #pragma unroll
                for (int mi = 0; mi < 2; mi++) {
                    MMA_F16(acc[mi][nj * 2    ], ar[mi], br[0], br[1]);
                    MMA_F16(acc[mi][nj * 2 + 1], ar[mi], br[2], br[3]);
                }
            }
        }
        __syncthreads();
        if (kt + 2 < nt) LOAD_STAGE(kt + 2, (kt + 2) % 3);
        CP_COMMIT();
    }

    float gaV = 0.f, gbV = 0.f, gcV = 0.f;
    if (MODE == 2) { gaV = *pga; gbV = *pgb; gcV = *pgc; }

    #pragma unroll
    for (int mi = 0; mi < 2; mi++) {
        const int ma = m0 + wm * 32 + mi * 16 + (lane >> 2);
        #pragma unroll
        for (int t = 0; t < 2 * NJ; t++) {
            const int n = n0 + wn * (16 * NJ) + t * 8 + ((lane & 3) << 1);
            const float b0 = bias[n], b1 = bias[n + 1];
            #pragma unroll
            for (int half = 0; half < 2; half++) {
                const int m = ma + half * 8;
                float v0 = acc[mi][t][half * 2]     + b0;
                float v1 = acc[mi][t][half * 2 + 1] + b1;
                const size_t idx = (size_t)m * N + n;
                if (MODE == 2) {
                    v0 = fmaf(fmaf(gaV, v0, gbV), v0, gcV);
                    v1 = fmaf(fmaf(gaV, v1, gbV), v1, gcV);
                    store_h2(out16 + idx, v0, v1);
                } else if (MODE == 3) {
                    store_h2(out16 + idx, v0, v1);
                } else {
                    const float2 rv = *(const float2*)(res + idx);
                    *(float2*)(outf + idx) = make_float2(v0 + rv.x, v1 + rv.y);
                }
            }
        }
    }
    #undef LOAD_STAGE
}

// =====================================================================
// Tensor-core fused attention (flash-style, fp16 mma, fp32 accum):
//   S = QK^T*scale; P = max(a*S^2+b*S+c, 1e-6); O = (P V) / rowsum(P)
// Block: 256 threads (8 warps x 16 queries = 128-query tile),
// 64-key tiles double-buffered via cp.async.
// __launch_bounds__(256, 2): guarantee 2 CTAs/SM.
// =====================================================================
__global__ __launch_bounds__(256, 2) void attn_tc_kernel(
    const __half* __restrict__ qkv, __half* __restrict__ out,
    const float* __restrict__ pa_, const float* __restrict__ pb_,
    const float* __restrict__ pc_)
{
    __shared__ __align__(16) char smQ[16384];      // 128 rows x 128B
    __shared__ __align__(16) char smK[2][8192];    // 64 rows x 128B
    __shared__ __align__(16) char smV[2][8192];

    const int tid = threadIdx.x, lane = tid & 31, warp = tid >> 5;
    const int bh = blockIdx.y, b = bh / HEADS, h = bh % HEADS;
    const int q0 = blockIdx.x * 128;
    const size_t tok0 = (size_t)b * SEQ;

    const uint32_t sQ = smem_u32(smQ);
    const uint32_t sK[2] = { smem_u32(smK[0]), smem_u32(smK[1]) };
    const uint32_t sV[2] = { smem_u32(smV[0]), smem_u32(smV[1]) };

    const float pa = *pa_, pb = *pb_, pc = *pc_;

    const int qrow = tid >> 1;
    const int qc0  = (tid & 1) * 4;
    const __half* qsrc = qkv + (tok0 + q0 + qrow) * QKV_N + h * HEAD_D + qc0 * 8;
    #pragma unroll
    for (int j = 0; j < 4; j++)
        cp16(sQ + qrow * 128 + (((qc0 + j) ^ (qrow & 7)) << 4), qsrc + j * 8);

    const int krow = tid >> 2;
    const int kc0  = (tid & 3) * 2;
    const __half* ksrc = qkv + (tok0 + krow) * QKV_N + DIM + h * HEAD_D + kc0 * 8;
    const __half* vsrc = ksrc + DIM;
    uint32_t kvoff[2];
    #pragma unroll
    for (int j = 0; j < 2; j++)
        kvoff[j] = krow * 128 + (((kc0 + j) ^ (krow & 7)) << 4);

    #pragma unroll
    for (int j = 0; j < 2; j++) {
        cp16(sK[0] + kvoff[j], ksrc + j * 8);
        cp16(sV[0] + kvoff[j], vsrc + j * 8);
    }
    CP_COMMIT();
    CP_WAIT0();
    __syncthreads();

    const int g = lane >> 3, r = lane & 7;
    const int rowadd = (g & 1) * 8 + r;
    const int cadd = g >> 1;
    uint32_t qreg[4][4];
    {
        const uint32_t qb = sQ + (warp * 16 + rowadd) * 128;
        #pragma unroll
        for (int s = 0; s < 4; s++)
            LDSM_X4(qreg[s], qb + (((2 * s + cadd) ^ r) << 4));
    }

    float acc_o[8][4] = {};
    float rsum[2] = {};
    const int NT = SEQ / 64;

    for (int t = 0; t < NT; t++) {
        if (t + 1 < NT) {
            const int nb = (t + 1) & 1;
            const size_t roff = (size_t)(t + 1) * 64 * QKV_N;
            #pragma unroll
            for (int j = 0; j < 2; j++) {
                cp16(sK[nb] + kvoff[j], ksrc + roff + j * 8);
                cp16(sV[nb] + kvoff[j], vsrc + roff + j * 8);
            }
            CP_COMMIT();
            CP_WAIT1();
        } else {
            CP_WAIT0();
        }
        __syncthreads();

        const uint32_t sk = sK[t & 1], sv = sV[t & 1];

        float acc_s[8][4] = {};
        #pragma unroll
        for (int s = 0; s < 4; s++) {
            const uint32_t coff = ((2 * s + cadd) ^ r) << 4;
            #pragma unroll
            for (int p = 0; p < 4; p++) {
                uint32_t kb[4];
                LDSM_X4(kb, sk + (16 * p + rowadd) * 128 + coff);
                MMA_F16(acc_s[2 * p    ], qreg[s], kb[0], kb[2]);
                MMA_F16(acc_s[2 * p + 1], qreg[s], kb[1], kb[3]);
            }
        }

        #pragma unroll
        for (int j = 0; j < 8; j++)
            #pragma unroll
            for (int e = 0; e < 4; e++) {
                const float sv_ = acc_s[j][e] * SCALE_ATT;
                float pv = fmaf(fmaf(pa, sv_, pb), sv_, pc);
                pv = fmaxf(pv, 1e-6f);
                acc_s[j][e] = pv;
                rsum[e >> 1] += pv;
            }

        #pragma unroll
        for (int s = 0; s < 4; s++) {
            uint32_t pf[4];
            pf[0] = pack_f16(acc_s[2 * s][0],     acc_s[2 * s][1]);
            pf[1] = pack_f16(acc_s[2 * s][2],     acc_s[2 * s][3]);
            pf[2] = pack_f16(acc_s[2 * s + 1][0], acc_s[2 * s + 1][1]);
            pf[3] = pack_f16(acc_s[2 * s + 1][2], acc_s[2 * s + 1][3]);
            const uint32_t vrb = sv + (16 * s + rowadd) * 128;
            #pragma unroll
            for (int p = 0; p < 4; p++) {
                uint32_t vb[4];
                LDSM_X4_T(vb, vrb + (((2 * p + cadd) ^ r) << 4));
                MMA_F16(acc_o[2 * p    ], pf, vb[0], vb[1]);
                MMA_F16(acc_o[2 * p + 1], pf, vb[2], vb[3]);
            }
        }
        __syncthreads();
    }

    #pragma unroll
    for (int off = 1; off < 4; off <<= 1) {
        rsum[0] += __shfl_xor_sync(0xffffffffu, rsum[0], off);
        rsum[1] += __shfl_xor_sync(0xffffffffu, rsum[1], off);
    }
    const float inv0 = 1.0f / (rsum[0] + 1e-8f);
    const float inv1 = 1.0f / (rsum[1] + 1e-8f);

    const int row0 = q0 + warp * 16 + (lane >> 2);
    const int dcol = h * HEAD_D + 2 * (lane & 3);
    #pragma unroll
    for (int j = 0; j < 8; j++) {
        const size_t i0 = (tok0 + row0) * DIM + dcol + 8 * j;
        const size_t i1 = (tok0 + row0 + 8) * DIM + dcol + 8 * j;
        store_h2(out + i0, acc_o[j][0] * inv0, acc_o[j][1] * inv0);
        store_h2(out + i1, acc_o[j][2] * inv1, acc_o[j][3] * inv1);
    }
}

// =====================================================================
// Launch
// =====================================================================
extern "C" void kernel_launch(void* const* d_in, const int* in_sizes, int n_in,
                              void* d_out, int out_size)
{
    const float* x      = (const float*)d_in[0];
    const float* ln1_g  = (const float*)d_in[1];
    const float* ln1_b  = (const float*)d_in[2];
    const float* ln2_g  = (const float*)d_in[3];
    const float* ln2_b  = (const float*)d_in[4];
    const float* qkv_w  = (const float*)d_in[5];
    const float* qkv_b  = (const float*)d_in[6];
    const float* proj_w = (const float*)d_in[7];
    const float* proj_b = (const float*)d_in[8];
    const float* fc1_w  = (const float*)d_in[9];
    const float* fc1_b  = (const float*)d_in[10];
    const float* fc2_w  = (const float*)d_in[11];
    const float* fc2_b  = (const float*)d_in[12];
    const float* attn_a = (const float*)d_in[13];
    const float* attn_b = (const float*)d_in[14];
    const float* attn_c = (const float*)d_in[15];
    const float* gelu_a = (const float*)d_in[16];
    const float* gelu_b = (const float*)d_in[17];
    const float* gelu_c = (const float*)d_in[18];

    float *x1;
    __half *qkvh, *hbuf, *atbuf, *ubuf, *wq, *wp, *w1, *w2;
    cudaGetSymbolAddress((void**)&x1,    g_x1);
    cudaGetSymbolAddress((void**)&qkvh,  g_qkv);
    cudaGetSymbolAddress((void**)&hbuf,  g_h);
    cudaGetSymbolAddress((void**)&atbuf, g_at);
    cudaGetSymbolAddress((void**)&ubuf,  g_u);
    cudaGetSymbolAddress((void**)&wq,    g_wqkv);
    cudaGetSymbolAddress((void**)&wp,    g_wprj);
    cudaGetSymbolAddress((void**)&w1,    g_wfc1);
    cudaGetSymbolAddress((void**)&w2,    g_wfc2);

    cudaFuncSetAttribute(tc_gemm<1, 2>, cudaFuncAttributeMaxDynamicSharedMemorySize,
                         GEMM_SMEM(2));
    cudaFuncSetAttribute(tc_gemm<2, 4>, cudaFuncAttributeMaxDynamicSharedMemorySize,
                         GEMM_SMEM(4));
    cudaFuncSetAttribute(tc_gemm<3, 4>, cudaFuncAttributeMaxDynamicSharedMemorySize,
                         GEMM_SMEM(4));

    // 0) transpose + fp16-convert weights -> [N,K]
    wconv_kernel<<<dim3(QKV_N / 32, DIM / 32),   dim3(32, 8)>>>(qkv_w,  wq, DIM, QKV_N);
    wconv_kernel<<<dim3(DIM / 32, DIM / 32),     dim3(32, 8)>>>(proj_w, wp, DIM, DIM);
    wconv_kernel<<<dim3(HIDDEN / 32, DIM / 32),  dim3(32, 8)>>>(fc1_w,  w1, DIM, HIDDEN);
    wconv_kernel<<<dim3(DIM / 32, HIDDEN / 32),  dim3(32, 8)>>>(fc2_w,  w2, HIDDEN, DIM);

    // 1) LN1 -> fp16
    ln_kernel<<<MTOK, 256>>>(x, ln1_g, ln1_b, hbuf);

    // 2) QKV GEMM -> fp16 q/k/v   (128x128 tiles)
    tc_gemm<3, 4><<<dim3(QKV_N / 128, MTOK / 128), 256, GEMM_SMEM(4)>>>(
        hbuf, wq, qkv_b, nullptr, nullptr, qkvh,
        QKV_N, DIM, nullptr, nullptr, nullptr);

    // 3) tensor-core fused attention (128-query tiles) -> fp16
    attn_tc_kernel<<<dim3(SEQ / 128, BATCH * HEADS), 256>>>(
        qkvh, atbuf, attn_a, attn_b, attn_c);

    // 4) proj GEMM + residual(x) -> x1 (fp32)   (128x64 tiles)
    tc_gemm<1, 2><<<dim3(DIM / 64, MTOK / 128), 256, GEMM_SMEM(2)>>>(
        atbuf, wp, proj_b, x, x1, nullptr,
        DIM, DIM, nullptr, nullptr, nullptr);

    // 5) LN2 -> fp16
    ln_kernel<<<MTOK, 256>>>(x1, ln2_g, ln2_b, hbuf);

    // 6) FC1 + poly-GELU -> u fp16   (128x128 tiles)
    tc_gemm<2, 4><<<dim3(HIDDEN / 128, MTOK / 128), 256, GEMM_SMEM(4)>>>(
        hbuf, w1, fc1_b, nullptr, nullptr, ubuf,
        HIDDEN, DIM, gelu_a, gelu_b, gelu_c);

    // 7) FC2 + residual(x1) -> out (fp32)   (128x64 tiles)
    tc_gemm<1, 2><<<dim3(DIM / 64, MTOK / 128), 256, GEMM_SMEM(2)>>>(
        ubuf, w2, fc2_b, x1, (float*)d_out, nullptr,
        DIM, HIDDEN, nullptr, nullptr, nullptr);
}

// round 14
// speedup vs baseline: 8.0493x; 1.0568x over previous
#include <cuda_runtime.h>
#include <cuda_fp16.h>
#include <cstdint>
#include <cstddef>

// ---------------- problem constants ----------------
#define BATCH   4
#define SEQ     2048
#define DIM     768
#define HEADS   12
#define HEAD_D  64
#define HIDDEN  3072
#define MTOK    (BATCH * SEQ)        // 8192 tokens
#define QKV_N   (3 * DIM)            // 2304
#define SCALE_ATT 0.125f             // 64^-0.5
#define LN_EPS  1e-5f

// ---------------- scratch (alloc-free: __device__ globals) ----------------
__device__ float g_x1 [(size_t)MTOK * DIM];       // residual after attn branch

__device__ __align__(16) __half g_qkv[(size_t)MTOK * QKV_N]; // q/k/v fp16
__device__ __align__(16) __half g_h  [(size_t)MTOK * DIM];   // LN out fp16
__device__ __align__(16) __half g_at [(size_t)MTOK * DIM];   // attention out fp16
__device__ __align__(16) __half g_u  [(size_t)MTOK * HIDDEN];// FC1/gelu out fp16

// transposed weights: stored [N, K] fp16
__device__ __align__(16) __half g_wqkv[(size_t)QKV_N * DIM];
__device__ __align__(16) __half g_wprj[(size_t)DIM * DIM];
__device__ __align__(16) __half g_wfc1[(size_t)HIDDEN * DIM];
__device__ __align__(16) __half g_wfc2[(size_t)DIM * HIDDEN];

// =====================================================================
// PTX helpers (sm_80-class: mma.sync / ldmatrix / cp.async — OK on sm_103)
// =====================================================================
__device__ __forceinline__ uint32_t smem_u32(const void* p) {
    uint32_t a;
    asm("{ .reg .u64 t; cvta.to.shared.u64 t, %1; cvt.u32.u64 %0, t; }"
        : "=r"(a) : "l"(p));
    return a;
}

#define LDSM_X4(r, addr)                                                        \
    asm volatile("ldmatrix.sync.aligned.m8n8.x4.shared.b16 {%0,%1,%2,%3}, [%4];"\
        : "=r"((r)[0]), "=r"((r)[1]), "=r"((r)[2]), "=r"((r)[3]) : "r"(addr))

#define LDSM_X4_T(r, addr)                                                      \
    asm volatile("ldmatrix.sync.aligned.m8n8.x4.trans.shared.b16 {%0,%1,%2,%3}, [%4];"\
        : "=r"((r)[0]), "=r"((r)[1]), "=r"((r)[2]), "=r"((r)[3]) : "r"(addr))

#define MMA_F16(d, a, b0, b1)                                                   \
    asm volatile("mma.sync.aligned.m16n8k16.row.col.f32.f16.f16.f32 "           \
        "{%0,%1,%2,%3}, {%4,%5,%6,%7}, {%8,%9}, {%0,%1,%2,%3};"                 \
        : "+f"((d)[0]), "+f"((d)[1]), "+f"((d)[2]), "+f"((d)[3])                \
        : "r"((a)[0]), "r"((a)[1]), "r"((a)[2]), "r"((a)[3]), "r"(b0), "r"(b1))

__device__ __forceinline__ void cp16(uint32_t dst, const void* src) {
    asm volatile("cp.async.cg.shared.global [%0], [%1], 16;"
                 :: "r"(dst), "l"(src) : "memory");
}
#define CP_COMMIT() asm volatile("cp.async.commit_group;" ::: "memory")
#define CP_WAIT1()  asm volatile("cp.async.wait_group 1;" ::: "memory")
#define CP_WAIT0()  asm volatile("cp.async.wait_group 0;" ::: "memory")

__device__ __forceinline__ uint32_t pack_f16(float x, float y) {
    __half2 t = __halves2half2(__float2half_rn(x), __float2half_rn(y));
    return *(uint32_t*)&t;
}

__device__ __forceinline__ void store_h2(__half* p, float a, float b) {
    __half2 t = __halves2half2(__float2half_rn(a), __float2half_rn(b));
    *(__half2*)p = t;
}

// =====================================================================
// Combined weight convert: all four W[K,N] fp32 -> Wt[N,K] fp16
// 32x32 tiled transpose; jobs packed into one grid (range dispatch).
//   qkv : K=768,  N=2304 : nx=72, 1728 blocks  [0,    1728)
//   proj: K=768,  N=768  : nx=24,  576 blocks  [1728, 2304)
//   fc1 : K=768,  N=3072 : nx=96, 2304 blocks  [2304, 4608)
//   fc2 : K=3072, N=768  : nx=24, 2304 blocks  [4608, 6912)
// =====================================================================
#define WCONV_BLOCKS 6912

__global__ __launch_bounds__(256) void wconv_all_kernel(
    const float* __restrict__ qkv_w, __half* __restrict__ wq,
    const float* __restrict__ proj_w, __half* __restrict__ wp,
    const float* __restrict__ fc1_w, __half* __restrict__ w1,
    const float* __restrict__ fc2_w, __half* __restrict__ w2)
{
    int bid = blockIdx.x;
    const float* W; __half* T; int K, N, nx;
    if (bid < 1728)      { W = qkv_w;  T = wq; K = DIM;    N = QKV_N;  nx = 72; }
    else if (bid < 2304) { bid -= 1728; W = proj_w; T = wp; K = DIM;   N = DIM;    nx = 24; }
    else if (bid < 4608) { bid -= 2304; W = fc1_w;  T = w1; K = DIM;   N = HIDDEN; nx = 96; }
    else                 { bid -= 4608; W = fc2_w;  T = w2; K = HIDDEN; N = DIM;   nx = 24; }
    const int n0 = (bid % nx) * 32, k0 = (bid / nx) * 32;

    __shared__ float t[32][33];
    const int tx = threadIdx.x, ty = threadIdx.y;
    #pragma unroll
    for (int j = 0; j < 4; j++)
        t[ty + 8 * j][tx] = W[(size_t)(k0 + ty + 8 * j) * N + n0 + tx];
    __syncthreads();
    #pragma unroll
    for (int j = 0; j < 4; j++)
        T[(size_t)(n0 + ty + 8 * j) * K + k0 + tx] = __float2half_rn(t[tx][ty + 8 * j]);
}

// =====================================================================
// LayerNorm -> fp16
// =====================================================================
__global__ __launch_bounds__(256) void ln_kernel(
    const float* __restrict__ x, const float* __restrict__ gamma,
    const float* __restrict__ beta, __half* __restrict__ out)
{
    const int row = blockIdx.x;
    const int tid = threadIdx.x;
    const float* xr = x + (size_t)row * DIM;

    float v0 = xr[tid], v1 = xr[tid + 256], v2 = xr[tid + 512];
    float s = v0 + v1 + v2;
    float q = v0 * v0 + v1 * v1 + v2 * v2;

    __shared__ float ws[8], wq[8];
    #pragma unroll
    for (int o = 16; o; o >>= 1) {
        s += __shfl_xor_sync(0xffffffffu, s, o);
        q += __shfl_xor_sync(0xffffffffu, q, o);
    }
    if ((tid & 31) == 0) { ws[tid >> 5] = s; wq[tid >> 5] = q; }
    __syncthreads();
    float ts = 0.f, tq = 0.f;
    #pragma unroll
    for (int i = 0; i < 8; i++) { ts += ws[i]; tq += wq[i]; }

    const float mean = ts * (1.0f / DIM);
    const float var  = tq * (1.0f / DIM) - mean * mean;
    const float rstd = rsqrtf(var + LN_EPS);

    const size_t rb = (size_t)row * DIM;
    #pragma unroll
    for (int j = 0; j < 3; j++) {
        const int c = tid + j * 256;
        const float v = (j == 0 ? v0 : (j == 1 ? v1 : v2));
        out[rb + c] = __float2half_rn((v - mean) * rstd * gamma[c] + beta[c]);
    }
}

// =====================================================================
// fp16 tensor-core GEMM via mma.sync.m16n8k16:
//   C[M,N] = A[M,K] @ B[N,K]^T  (fp32 accumulate)
// Block tile 128 x (32*NJ) x 64, 8 warps (4x2), 3-stage cp.async pipeline.
// Single barrier per k-tile (mid-loop barrier proven redundant: slot
// (kt+2)%3 was last read in iteration kt-1, sealed by kt's top barrier).
// __launch_bounds__(256, 2): 2 CTAs/SM.
// MODE 1: out = D + bias + res (fp32)
// MODE 2: u = D + bias; poly-GELU(u) -> fp16
// MODE 3: out = D + bias -> fp16 (attention q/k/v)
// =====================================================================
#define GEMM_SMEM(NJ) (3 * (16384 + 4096 * (NJ)))

template<int MODE, int NJ>
__global__ __launch_bounds__(256, 2) void tc_gemm(
    const __half* __restrict__ A, const __half* __restrict__ B,
    const float* __restrict__ bias, const float* __restrict__ res,
    float* __restrict__ outf, __half* __restrict__ out16,
    int N, int K,
    const float* __restrict__ pga, const float* __restrict__ pgb,
    const float* __restrict__ pgc)
{
    constexpr int BN = 32 * NJ;                       // N tile
    constexpr int STAGE = 16384 + 4096 * NJ;          // bytes per stage
    extern __shared__ char sm[];
    const uint32_t sbase = smem_u32(sm);
    const int tid = threadIdx.x;
    const int lane = tid & 31, wid = tid >> 5;
    const int wm = wid & 3, wn = wid >> 2;            // 4 x 2 warp grid
    const int m0 = blockIdx.y * 128, n0 = blockIdx.x * BN;
    const int nt = K >> 6;                            // K/64 stages

    const __half* agsrc[4]; uint32_t asoff[4];
    #pragma unroll
    for (int i = 0; i < 4; i++) {
        const int id = tid + i * 256;
        const int row = id >> 3, c = id & 7;
        agsrc[i] = A + (size_t)(m0 + row) * K + c * 8;
        asoff[i] = row * 128 + ((c ^ (row & 7)) << 4);
    }
    const __half* bgsrc[NJ]; uint32_t bsoff[NJ];
    #pragma unroll
    for (int i = 0; i < NJ; i++) {
        const int id = tid + i * 256;
        const int row = id >> 3, c = id & 7;
        bgsrc[i] = B + (size_t)(n0 + row) * K + c * 8;
        bsoff[i] = 16384 + row * 128 + ((c ^ (row & 7)) << 4);
    }

    #define LOAD_STAGE(kt, slot) do {                                          \
        const uint32_t sb_ = sbase + (uint32_t)(slot) * STAGE;                  \
        const size_t ko_ = (size_t)(kt) * 64;                                   \
        _Pragma("unroll")                                                       \
        for (int i_ = 0; i_ < 4; i_++)                                          \
            cp16(sb_ + asoff[i_], agsrc[i_] + ko_);                             \
        _Pragma("unroll")                                                       \
        for (int i_ = 0; i_ < NJ; i_++)                                         \
            cp16(sb_ + bsoff[i_], bgsrc[i_] + ko_);                             \
    } while (0)

    LOAD_STAGE(0, 0); CP_COMMIT();
    LOAD_STAGE(1, 1); CP_COMMIT();

    uint32_t a_off[2][4];
    #pragma unroll
    for (int mi = 0; mi < 2; mi++) {
        const int row = wm * 32 + mi * 16 + (lane & 15);
        const int kbit = (lane >> 4) & 1;
        #pragma unroll
        for (int ks = 0; ks < 4; ks++) {
            const int chi = ks * 2 + kbit;
            a_off[mi][ks] = row * 128 + ((chi ^ (row & 7)) << 4);
        }
    }
    uint32_t b_off[NJ][4];
    #pragma unroll
    for (int nj = 0; nj < NJ; nj++) {
        const int nrow = wn * (16 * NJ) + nj * 16 + (lane & 7) + ((lane >> 4) << 3);
        const int kbit = (lane >> 3) & 1;
        #pragma unroll
        for (int ks = 0; ks < 4; ks++) {
            const int chi = ks * 2 + kbit;
            b_off[nj][ks] = 16384 + nrow * 128 + ((chi ^ (nrow & 7)) << 4);
        }
    }

    float acc[2][2 * NJ][4] = {};

    for (int kt = 0; kt < nt; kt++) {
        CP_WAIT1();
        __syncthreads();
        const uint32_t sb = sbase + (uint32_t)(kt % 3) * STAGE;

        #pragma unroll
        for (int ks = 0; ks < 4; ks++) {
            uint32_t ar[2][4];
            LDSM_X4(ar[0], sb + a_off[0][ks]);
            LDSM_X4(ar[1], sb + a_off[1][ks]);
            #pragma unroll
            for (int nj = 0; nj < NJ; nj++) {
                uint32_t br[4];
                LDSM_X4(br, sb + b_off[nj][ks]);
                #pragma unroll
                for (int mi = 0; mi < 2; mi++) {
                    MMA_F16(acc[mi][nj * 2    ], ar[mi], br[0], br[1]);
                    MMA_F16(acc[mi][nj * 2 + 1], ar[mi], br[2], br[3]);
                }
            }
        }
        // no mid-loop barrier: slot (kt+2)%3 was last read in iteration
        // kt-1, and every warp passed this iteration's top barrier.
        if (kt + 2 < nt) LOAD_STAGE(kt + 2, (kt + 2) % 3);
        CP_COMMIT();
    }

    float gaV = 0.f, gbV = 0.f, gcV = 0.f;
    if (MODE == 2) { gaV = *pga; gbV = *pgb; gcV = *pgc; }

    #pragma unroll
    for (int mi = 0; mi < 2; mi++) {
        const int ma = m0 + wm * 32 + mi * 16 + (lane >> 2);
        #pragma unroll
        for (int t = 0; t < 2 * NJ; t++) {
            const int n = n0 + wn * (16 * NJ) + t * 8 + ((lane & 3) << 1);
            const float b0 = bias[n], b1 = bias[n + 1];
            #pragma unroll
            for (int half = 0; half < 2; half++) {
                const int m = ma + half * 8;
                float v0 = acc[mi][t][half * 2]     + b0;
                float v1 = acc[mi][t][half * 2 + 1] + b1;
                const size_t idx = (size_t)m * N + n;
                if (MODE == 2) {
                    v0 = fmaf(fmaf(gaV, v0, gbV), v0, gcV);
                    v1 = fmaf(fmaf(gaV, v1, gbV), v1, gcV);
                    store_h2(out16 + idx, v0, v1);
                } else if (MODE == 3) {
                    store_h2(out16 + idx, v0, v1);
                } else {
                    const float2 rv = *(const float2*)(res + idx);
                    *(float2*)(outf + idx) = make_float2(v0 + rv.x, v1 + rv.y);
                }
            }
        }
    }
    #undef LOAD_STAGE
}

// =====================================================================
// Tensor-core fused attention (flash-style, fp16 mma, fp32 accum):
//   S = QK^T; P = max(pa2*S^2 + pb2*S + pc, 1e-6)   [scale folded into
//   pa2 = a*SCALE^2, pb2 = b*SCALE];  O = (P V) / rowsum(P)
// Block: 256 threads (8 warps x 16 queries = 128-query tile),
// 64-key tiles double-buffered via cp.async. 2 CTAs/SM.
// =====================================================================
__global__ __launch_bounds__(256, 2) void attn_tc_kernel(
    const __half* __restrict__ qkv, __half* __restrict__ out,
    const float* __restrict__ pa_, const float* __restrict__ pb_,
    const float* __restrict__ pc_)
{
    __shared__ __align__(16) char smQ[16384];      // 128 rows x 128B
    __shared__ __align__(16) char smK[2][8192];    // 64 rows x 128B
    __shared__ __align__(16) char smV[2][8192];

    const int tid = threadIdx.x, lane = tid & 31, warp = tid >> 5;
    const int bh = blockIdx.y, b = bh / HEADS, h = bh % HEADS;
    const int q0 = blockIdx.x * 128;
    const size_t tok0 = (size_t)b * SEQ;

    const uint32_t sQ = smem_u32(smQ);
    const uint32_t sK[2] = { smem_u32(smK[0]), smem_u32(smK[1]) };
    const uint32_t sV[2] = { smem_u32(smV[0]), smem_u32(smV[1]) };

    const float pa2 = *pa_ * (SCALE_ATT * SCALE_ATT);
    const float pb2 = *pb_ * SCALE_ATT;
    const float pc  = *pc_;

    const int qrow = tid >> 1;
    const int qc0  = (tid & 1) * 4;
    const __half* qsrc = qkv + (tok0 + q0 + qrow) * QKV_N + h * HEAD_D + qc0 * 8;
    #pragma unroll
    for (int j = 0; j < 4; j++)
        cp16(sQ + qrow * 128 + (((qc0 + j) ^ (qrow & 7)) << 4), qsrc + j * 8);

    const int krow = tid >> 2;
    const int kc0  = (tid & 3) * 2;
    const __half* ksrc = qkv + (tok0 + krow) * QKV_N + DIM + h * HEAD_D + kc0 * 8;
    const __half* vsrc = ksrc + DIM;
    uint32_t kvoff[2];
    #pragma unroll
    for (int j = 0; j < 2; j++)
        kvoff[j] = krow * 128 + (((kc0 + j) ^ (krow & 7)) << 4);

    #pragma unroll
    for (int j = 0; j < 2; j++) {
        cp16(sK[0] + kvoff[j], ksrc + j * 8);
        cp16(sV[0] + kvoff[j], vsrc + j * 8);
    }
    CP_COMMIT();
    CP_WAIT0();
    __syncthreads();

    const int g = lane >> 3, r = lane & 7;
    const int rowadd = (g & 1) * 8 + r;
    const int cadd = g >> 1;
    uint32_t qreg[4][4];
    {
        const uint32_t qb = sQ + (warp * 16 + rowadd) * 128;
        #pragma unroll
        for (int s = 0; s < 4; s++)
            LDSM_X4(qreg[s], qb + (((2 * s + cadd) ^ r) << 4));
    }

    float acc_o[8][4] = {};
    float rsum[2] = {};
    const int NT = SEQ / 64;

    for (int t = 0; t < NT; t++) {
        if (t + 1 < NT) {
            const int nb = (t + 1) & 1;
            const size_t roff = (size_t)(t + 1) * 64 * QKV_N;
            #pragma unroll
            for (int j = 0; j < 2; j++) {
                cp16(sK[nb] + kvoff[j], ksrc + roff + j * 8);
                cp16(sV[nb] + kvoff[j], vsrc + roff + j * 8);
            }
            CP_COMMIT();
            CP_WAIT1();
        } else {
            CP_WAIT0();
        }
        __syncthreads();

        const uint32_t sk = sK[t & 1], sv = sV[t & 1];

        float acc_s[8][4] = {};
        #pragma unroll
        for (int s = 0; s < 4; s++) {
            const uint32_t coff = ((2 * s + cadd) ^ r) << 4;
            #pragma unroll
            for (int p = 0; p < 4; p++) {
                uint32_t kb[4];
                LDSM_X4(kb, sk + (16 * p + rowadd) * 128 + coff);
                MMA_F16(acc_s[2 * p    ], qreg[s], kb[0], kb[2]);
                MMA_F16(acc_s[2 * p + 1], qreg[s], kb[1], kb[3]);
            }
        }

        #pragma unroll
        for (int j = 0; j < 8; j++)
            #pragma unroll
            for (int e = 0; e < 4; e++) {
                const float sv_ = acc_s[j][e];
                float pv = fmaf(fmaf(pa2, sv_, pb2), sv_, pc);
                pv = fmaxf(pv, 1e-6f);
                acc_s[j][e] = pv;
                rsum[e >> 1] += pv;
            }

        #pragma unroll
        for (int s = 0; s < 4; s++) {
            uint32_t pf[4];
            pf[0] = pack_f16(acc_s[2 * s][0],     acc_s[2 * s][1]);
            pf[1] = pack_f16(acc_s[2 * s][2],     acc_s[2 * s][3]);
            pf[2] = pack_f16(acc_s[2 * s + 1][0], acc_s[2 * s + 1][1]);
            pf[3] = pack_f16(acc_s[2 * s + 1][2], acc_s[2 * s + 1][3]);
            const uint32_t vrb = sv + (16 * s + rowadd) * 128;
            #pragma unroll
            for (int p = 0; p < 4; p++) {
                uint32_t vb[4];
                LDSM_X4_T(vb, vrb + (((2 * p + cadd) ^ r) << 4));
                MMA_F16(acc_o[2 * p    ], pf, vb[0], vb[1]);
                MMA_F16(acc_o[2 * p + 1], pf, vb[2], vb[3]);
            }
        }
        __syncthreads();
    }

    #pragma unroll
    for (int off = 1; off < 4; off <<= 1) {
        rsum[0] += __shfl_xor_sync(0xffffffffu, rsum[0], off);
        rsum[1] += __shfl_xor_sync(0xffffffffu, rsum[1], off);
    }
    const float inv0 = 1.0f / (rsum[0] + 1e-8f);
    const float inv1 = 1.0f / (rsum[1] + 1e-8f);

    const int row0 = q0 + warp * 16 + (lane >> 2);
    const int dcol = h * HEAD_D + 2 * (lane & 3);
    #pragma unroll
    for (int j = 0; j < 8; j++) {
        const size_t i0 = (tok0 + row0) * DIM + dcol + 8 * j;
        const size_t i1 = (tok0 + row0 + 8) * DIM + dcol + 8 * j;
        store_h2(out + i0, acc_o[j][0] * inv0, acc_o[j][1] * inv0);
        store_h2(out + i1, acc_o[j][2] * inv1, acc_o[j][3] * inv1);
    }
}

// =====================================================================
// Launch
// =====================================================================
extern "C" void kernel_launch(void* const* d_in, const int* in_sizes, int n_in,
                              void* d_out, int out_size)
{
    const float* x      = (const float*)d_in[0];
    const float* ln1_g  = (const float*)d_in[1];
    const float* ln1_b  = (const float*)d_in[2];
    const float* ln2_g  = (const float*)d_in[3];
    const float* ln2_b  = (const float*)d_in[4];
    const float* qkv_w  = (const float*)d_in[5];
    const float* qkv_b  = (const float*)d_in[6];
    const float* proj_w = (const float*)d_in[7];
    const float* proj_b = (const float*)d_in[8];
    const float* fc1_w  = (const float*)d_in[9];
    const float* fc1_b  = (const float*)d_in[10];
    const float* fc2_w  = (const float*)d_in[11];
    const float* fc2_b  = (const float*)d_in[12];
    const float* attn_a = (const float*)d_in[13];
    const float* attn_b = (const float*)d_in[14];
    const float* attn_c = (const float*)d_in[15];
    const float* gelu_a = (const float*)d_in[16];
    const float* gelu_b = (const float*)d_in[17];
    const float* gelu_c = (const float*)d_in[18];

    float *x1;
    __half *qkvh, *hbuf, *atbuf, *ubuf, *wq, *wp, *w1, *w2;
    cudaGetSymbolAddress((void**)&x1,    g_x1);
    cudaGetSymbolAddress((void**)&qkvh,  g_qkv);
    cudaGetSymbolAddress((void**)&hbuf,  g_h);
    cudaGetSymbolAddress((void**)&atbuf, g_at);
    cudaGetSymbolAddress((void**)&ubuf,  g_u);
    cudaGetSymbolAddress((void**)&wq,    g_wqkv);
    cudaGetSymbolAddress((void**)&wp,    g_wprj);
    cudaGetSymbolAddress((void**)&w1,    g_wfc1);
    cudaGetSymbolAddress((void**)&w2,    g_wfc2);

    cudaFuncSetAttribute(tc_gemm<1, 2>, cudaFuncAttributeMaxDynamicSharedMemorySize,
                         GEMM_SMEM(2));
    cudaFuncSetAttribute(tc_gemm<2, 4>, cudaFuncAttributeMaxDynamicSharedMemorySize,
                         GEMM_SMEM(4));
    cudaFuncSetAttribute(tc_gemm<3, 4>, cudaFuncAttributeMaxDynamicSharedMemorySize,
                         GEMM_SMEM(4));

    // 0) all weight transposes + fp16 conversion in ONE launch
    wconv_all_kernel<<<WCONV_BLOCKS, dim3(32, 8)>>>(
        qkv_w, wq, proj_w, wp, fc1_w, w1, fc2_w, w2);

    // 1) LN1 -> fp16
    ln_kernel<<<MTOK, 256>>>(x, ln1_g, ln1_b, hbuf);

    // 2) QKV GEMM -> fp16 q/k/v   (128x128 tiles)
    tc_gemm<3, 4><<<dim3(QKV_N / 128, MTOK / 128), 256, GEMM_SMEM(4)>>>(
        hbuf, wq, qkv_b, nullptr, nullptr, qkvh,
        QKV_N, DIM, nullptr, nullptr, nullptr);

    // 3) tensor-core fused attention (128-query tiles) -> fp16
    attn_tc_kernel<<<dim3(SEQ / 128, BATCH * HEADS), 256>>>(
        qkvh, atbuf, attn_a, attn_b, attn_c);

    // 4) proj GEMM + residual(x) -> x1 (fp32)   (128x64 tiles)
    tc_gemm<1, 2><<<dim3(DIM / 64, MTOK / 128), 256, GEMM_SMEM(2)>>>(
        atbuf, wp, proj_b, x, x1, nullptr,
        DIM, DIM, nullptr, nullptr, nullptr);

    // 5) LN2 -> fp16
    ln_kernel<<<MTOK, 256>>>(x1, ln2_g, ln2_b, hbuf);

    // 6) FC1 + poly-GELU -> u fp16   (128x128 tiles)
    tc_gemm<2, 4><<<dim3(HIDDEN / 128, MTOK / 128), 256, GEMM_SMEM(4)>>>(
        hbuf, w1, fc1_b, nullptr, nullptr, ubuf,
        HIDDEN, DIM, gelu_a, gelu_b, gelu_c);

    // 7) FC2 + residual(x1) -> out (fp32)   (128x64 tiles)
    tc_gemm<1, 2><<<dim3(DIM / 64, MTOK / 128), 256, GEMM_SMEM(2)>>>(
        ubuf, w2, fc2_b, x1, (float*)d_out, nullptr,
        DIM, HIDDEN, nullptr, nullptr, nullptr);
}